// round 12
// baseline (speedup 1.0000x reference)
#include <cuda_runtime.h>
#include <cuda_bf16.h>
#include <math.h>
#include <stdint.h>

#define BB     4
#define SS     2048
#define DMODEL 1024
#define NH     16
#define HD     64
#define HDIM   1024
#define RK     8
#define TOK    (BB*SS)   // 8192

// ------------------- device scratch (static; allocation-free) -------------------
__device__ float g_beq[HDIM];
__device__ float g_bek[HDIM];
__device__ float g_bev[HDIM];
__device__ float g_V[(size_t)TOK*HDIM];
__device__ float g_colsum[(size_t)BB*NH*SS];
__device__ float g_KA[(size_t)TOK*RK];

__device__ __nv_bfloat16 g_qh[(size_t)TOK*DMODEL], g_ql[(size_t)TOK*DMODEL];
__device__ __nv_bfloat16 g_kh[(size_t)TOK*DMODEL], g_kl[(size_t)TOK*DMODEL];
__device__ __nv_bfloat16 g_vh[(size_t)TOK*DMODEL], g_vl[(size_t)TOK*DMODEL];
__device__ __nv_bfloat16 g_Qph[(size_t)TOK*HDIM], g_Qpl[(size_t)TOK*HDIM];
__device__ __nv_bfloat16 g_Kph[(size_t)TOK*HDIM], g_Kpl[(size_t)TOK*HDIM];
__device__ __nv_bfloat16 g_aoh[(size_t)TOK*HDIM], g_aol[(size_t)TOK*HDIM];
__device__ __nv_bfloat16 g_Vrth[(size_t)BB*NH*64*SS];
__device__ __nv_bfloat16 g_Vrtl[(size_t)BB*NH*64*SS];
__device__ __nv_bfloat16 g_wqh[DMODEL*HDIM], g_wql[DMODEL*HDIM];
__device__ __nv_bfloat16 g_wkh[DMODEL*HDIM], g_wkl[DMODEL*HDIM];
__device__ __nv_bfloat16 g_wvh[DMODEL*HDIM], g_wvl[DMODEL*HDIM];
__device__ __nv_bfloat16 g_woh[DMODEL*HDIM], g_wol[DMODEL*HDIM];

// ------------------- helpers ------------------------------------------------------
__device__ __forceinline__ uint32_t smem_u32(const void* p) {
    uint32_t a;
    asm("{ .reg .u64 t; cvta.to.shared.u64 t, %1; cvt.u32.u64 %0, t; }" : "=r"(a) : "l"(p));
    return a;
}
__device__ __forceinline__ void cpa16(uint32_t dst, const void* src) {
    asm volatile("cp.async.cg.shared.global [%0], [%1], 16;"
                 :: "r"(dst), "l"(__cvta_generic_to_global(src)));
}
#define CPA_COMMIT() asm volatile("cp.async.commit_group;")
#define CPA_WAIT2()  asm volatile("cp.async.wait_group 2;")
#define CPA_WAIT1()  asm volatile("cp.async.wait_group 1;")
#define CPA_WAIT0()  asm volatile("cp.async.wait_group 0;")

#define LDSM4(r, a) \
    asm volatile("ldmatrix.sync.aligned.m8n8.x4.shared.b16 {%0,%1,%2,%3}, [%4];" \
        : "=r"((r)[0]), "=r"((r)[1]), "=r"((r)[2]), "=r"((r)[3]) : "r"(a))

#define MMA16816(c, a, b0, b1) \
    asm volatile("mma.sync.aligned.m16n8k16.row.col.f32.bf16.bf16.f32 " \
        "{%0,%1,%2,%3}, {%4,%5,%6,%7}, {%8,%9}, {%0,%1,%2,%3};" \
        : "+f"((c)[0]), "+f"((c)[1]), "+f"((c)[2]), "+f"((c)[3]) \
        : "r"((a)[0]), "r"((a)[1]), "r"((a)[2]), "r"((a)[3]), "r"(b0), "r"(b1))

__device__ __forceinline__ uint32_t pack_bf2(float lo, float hi) {
    __nv_bfloat162 p = {__float2bfloat16(lo), __float2bfloat16(hi)};
    return *(uint32_t*)&p;
}

#define SWZ128(x) ((x) ^ (((x) >> 3) & 0x70))
// logical 64B rows packed 2-per-128B-physical-row, SW128 XOR swizzle.
__device__ __forceinline__ uint32_t swz_off(int row, int chunk) {
    uint32_t o = (uint32_t)((row >> 1) * 128 + (row & 1) * 64 + chunk * 16);
    return SWZ128(o);
}

// ------------------- fused prep kernels -------------------------------------------
struct ActArgs { const float* X[3]; __nv_bfloat16 *hi[3], *lo[3]; };
__global__ void actconv_kernel(ActArgs aa)
{
    int z = blockIdx.z;
    const float* X = aa.X[z];
    __nv_bfloat16* hi = aa.hi[z];
    __nv_bfloat16* lo = aa.lo[z];
    size_t i = ((size_t)blockIdx.x * 256 + threadIdx.x) * 4;
    float4 v = *(const float4*)&X[i];
    __nv_bfloat16 h0 = __float2bfloat16(v.x), h1 = __float2bfloat16(v.y);
    __nv_bfloat16 h2 = __float2bfloat16(v.z), h3 = __float2bfloat16(v.w);
    __nv_bfloat162 ph0 = {h0, h1}, ph1 = {h2, h3};
    __nv_bfloat162 pl0 = {__float2bfloat16(v.x - __bfloat162float(h0)),
                          __float2bfloat16(v.y - __bfloat162float(h1))};
    __nv_bfloat162 pl1 = {__float2bfloat16(v.z - __bfloat162float(h2)),
                          __float2bfloat16(v.w - __bfloat162float(h3))};
    *(__nv_bfloat162*)&hi[i]   = ph0;  *(__nv_bfloat162*)&hi[i+2] = ph1;
    *(__nv_bfloat162*)&lo[i]   = pl0;  *(__nv_bfloat162*)&lo[i+2] = pl1;
}

struct WprepArgs { const float *W[4], *A[4], *Bw[4]; __nv_bfloat16 *hi[4], *lo[4]; };
__global__ __launch_bounds__(256) void wprep_kernel(WprepArgs wa)
{
    __shared__ float t[32][33];
    int z = blockIdx.z;
    const float* W = wa.W[z];
    const float* A = wa.A[z];
    const float* Bw = wa.Bw[z];
    __nv_bfloat16* hi = wa.hi[z];
    __nv_bfloat16* lo = wa.lo[z];
    int kb = blockIdx.x * 32, nb = blockIdx.y * 32;
    int x = threadIdx.x & 31, y = threadIdx.x >> 5;
#pragma unroll
    for (int i = y; i < 32; i += 8) {
        int k = kb + i, n = nb + x;
        float v = W[(size_t)k*HDIM + n];
        if (A) {
#pragma unroll
            for (int r = 0; r < RK; r++) v += A[k*RK + r] * Bw[r*HDIM + n];
        }
        t[i][x] = v;
    }
    __syncthreads();
#pragma unroll
    for (int i = y; i < 32; i += 8) {
        int n = nb + i, k = kb + x;
        float v = t[x][i];
        __nv_bfloat16 h = __float2bfloat16(v);
        hi[(size_t)n*DMODEL + k] = h;
        lo[(size_t)n*DMODEL + k] = __float2bfloat16(v - __bfloat162float(h));
    }
}

struct BeffArgs { const float *Wb[3], *Ab[3], *Bw[3], *Bb[3]; float* out[3]; };
__global__ void beff_kernel(BeffArgs ba)
{
    int z = blockIdx.z;
    int j = blockIdx.x * 256 + threadIdx.x;
    float acc = ba.Wb[z][j] + ba.Bb[z][j];
    const float* Ab = ba.Ab[z];
    const float* Bw = ba.Bw[z];
#pragma unroll
    for (int r = 0; r < RK; r++) acc += Ab[r] * Bw[r*HDIM + j];
    ba.out[z][j] = acc;
}

__global__ void zero_kernel(float* p) { p[blockIdx.x * 256 + threadIdx.x] = 0.f; }

__global__ __launch_bounds__(256) void ka_kernel(const float* __restrict__ keys,
                                                 const float* __restrict__ Av,
                                                 float* __restrict__ KA)
{
    __shared__ float avT[RK][DMODEL];
    int tid = threadIdx.x;
#pragma unroll
    for (int f = tid; f < DMODEL*RK/4; f += 256) {
        int k = f >> 1, j = (f & 1) * 4;
        float4 v = ((const float4*)Av)[f];
        avT[j+0][k] = v.x; avT[j+1][k] = v.y;
        avT[j+2][k] = v.z; avT[j+3][k] = v.w;
    }
    __syncthreads();

    int warp = tid >> 5, lane = tid & 31;
    int row = blockIdx.x * 8 + warp;
    const float4* kr = (const float4*)(keys + (size_t)row * DMODEL);
    float acc[RK];
#pragma unroll
    for (int r = 0; r < RK; r++) acc[r] = 0.f;
#pragma unroll
    for (int i = 0; i < 8; i++) {
        int k4 = lane + i * 32;
        float4 kv = kr[k4];
        int k = 4 * k4;
#pragma unroll
        for (int r = 0; r < RK; r++) {
            float4 av = *(const float4*)&avT[r][k];
            acc[r] += kv.x*av.x + kv.y*av.y + kv.z*av.z + kv.w*av.w;
        }
    }
#pragma unroll
    for (int r = 0; r < RK; r++) {
#pragma unroll
        for (int off = 16; off > 0; off >>= 1)
            acc[r] += __shfl_down_sync(0xffffffffu, acc[r], off);
    }
    if (lane == 0) {
#pragma unroll
        for (int r = 0; r < RK; r++) KA[(size_t)row*RK + r] = acc[r];
    }
}

// ------------------- fused mma.sync split-bf16 GEMM -------------------------------
static constexpr int G_TILE  = 8192;
static constexpr int G_STAGE = 4 * G_TILE;
static constexpr int GEMM_SMEM = 3 * G_STAGE;    // 98304

struct GemmArgs {
    const __nv_bfloat16 *Ah[4], *Al[4], *Bh[4], *Bl[4];
    const float* bias[4];
    float* outF[4];
    __nv_bfloat16 *outH[4], *outL[4];
    const float *loraKA, *loraB;
};

// op==0: z = blockIdx.z (QKV fused, grid.z=3). op==3: O projection.
__global__ __launch_bounds__(256, 2)
void gemm_mma(GemmArgs ga, int op)
{
    extern __shared__ char smem[];
    const uint32_t sb = smem_u32(smem);
    const int z = (op == 0) ? blockIdx.z : op;
    const __nv_bfloat16* Ah = ga.Ah[z];
    const __nv_bfloat16* Al = ga.Al[z];
    const __nv_bfloat16* Bh = ga.Bh[z];
    const __nv_bfloat16* Bl = ga.Bl[z];
    const float* bias = ga.bias[z];
    float* outF = ga.outF[z];
    __nv_bfloat16* outH = ga.outH[z];
    __nv_bfloat16* outL = ga.outL[z];
    const float* loraKA = (z == 2) ? ga.loraKA : nullptr;
    const float* loraB  = ga.loraB;

    const int tid  = threadIdx.x;
    const int lane = tid & 31;
    const int warp = tid >> 5;
    const int wm = warp >> 2, wn = warp & 3;
    const int m0 = blockIdx.y * 128, n0 = blockIdx.x * 128;

    float acc[4][4][4];
#pragma unroll
    for (int i = 0; i < 4; i++)
#pragma unroll
        for (int j = 0; j < 4; j++)
#pragma unroll
            for (int k = 0; k < 4; k++) acc[i][j][k] = 0.f;

    auto load_stage = [&](int st, int chunk) {
        int k0 = chunk * 32;
        const __nv_bfloat16* tp[4] = {Ah, Al, Bh, Bl};
        uint32_t sbase = sb + st * G_STAGE;
#pragma unroll
        for (int i = 0; i < 8; i++) {
            const int t = i >> 1;
            int j = (i & 1) ? tid + 256 : tid;
            int row = j >> 2, sg = j & 3;
            int r0 = (t < 2) ? m0 : n0;
            cpa16(sbase + t * G_TILE + swz_off(row, sg),
                  tp[t] + (size_t)(r0 + row) * 1024 + k0 + sg * 8);
        }
    };

    auto compute_stage = [&](int st) {
        uint32_t ab = sb + st * G_STAGE;
#pragma unroll
        for (int kk = 0; kk < 2; kk++) {
            uint32_t ahr[4][4], alr[4][4], bh2[4][2], bl2[4][2];
            int arow = wm*64 + (lane & 15);
            int ac   = kk*2 + (lane >> 4);
            uint32_t abase = ab + swz_off(arow, ac);
#pragma unroll
            for (int mt = 0; mt < 4; mt++) {
                LDSM4(ahr[mt], abase + mt * 1024);
                LDSM4(alr[mt], abase + G_TILE + mt * 1024);
            }
            int brow = wn*32 + (lane & 7) + ((lane >> 4) << 3);
            int bc   = kk*2 + ((lane >> 3) & 1);
            uint32_t bbase = ab + 2*G_TILE + swz_off(brow, bc);
            {
                uint32_t t0[4], t1[4];
                LDSM4(t0, bbase);
                LDSM4(t1, bbase + 1024);
                bh2[0][0]=t0[0]; bh2[0][1]=t0[1]; bh2[1][0]=t0[2]; bh2[1][1]=t0[3];
                bh2[2][0]=t1[0]; bh2[2][1]=t1[1]; bh2[3][0]=t1[2]; bh2[3][1]=t1[3];
                LDSM4(t0, bbase + G_TILE);
                LDSM4(t1, bbase + G_TILE + 1024);
                bl2[0][0]=t0[0]; bl2[0][1]=t0[1]; bl2[1][0]=t0[2]; bl2[1][1]=t0[3];
                bl2[2][0]=t1[0]; bl2[2][1]=t1[1]; bl2[3][0]=t1[2]; bl2[3][1]=t1[3];
            }
#pragma unroll
            for (int mt = 0; mt < 4; mt++)
#pragma unroll
                for (int nt = 0; nt < 4; nt++) {
                    MMA16816(acc[mt][nt], ahr[mt], bh2[nt][0], bh2[nt][1]);
                    MMA16816(acc[mt][nt], ahr[mt], bl2[nt][0], bl2[nt][1]);
                    MMA16816(acc[mt][nt], alr[mt], bh2[nt][0], bh2[nt][1]);
                }
        }
    };

    load_stage(0, 0);
    CPA_COMMIT();
    load_stage(1, 1);
    CPA_COMMIT();

#pragma unroll 1
    for (int c = 0; c < 32; c++) {
        CPA_WAIT1();
        __syncthreads();
        if (c + 2 < 32) load_stage((c + 2) % 3, c + 2);
        CPA_COMMIT();
        compute_stage(c % 3);
    }

    int r_ = lane >> 2, c_ = (lane & 3) * 2;
#pragma unroll
    for (int mt = 0; mt < 4; mt++) {
        int row = m0 + wm*64 + mt*16 + r_;
        float ka0[RK], ka1[RK];
        if (loraKA) {
#pragma unroll
            for (int r = 0; r < RK; r++) {
                ka0[r] = loraKA[(size_t)row*RK + r];
                ka1[r] = loraKA[(size_t)(row+8)*RK + r];
            }
        }
#pragma unroll
        for (int nt = 0; nt < 4; nt++) {
            int col = n0 + wn*32 + nt*8 + c_;
            float b0 = bias[col], b1 = bias[col + 1];
            float v00 = acc[mt][nt][0] + b0, v01 = acc[mt][nt][1] + b1;
            float v10 = acc[mt][nt][2] + b0, v11 = acc[mt][nt][3] + b1;
            if (loraKA) {
#pragma unroll
                for (int r = 0; r < RK; r++) {
                    float w0 = loraB[r*HDIM + col], w1 = loraB[r*HDIM + col + 1];
                    v00 += ka0[r] * w0;  v01 += ka0[r] * w1;
                    v10 += ka1[r] * w0;  v11 += ka1[r] * w1;
                }
            }
            if (outF) {
                *(float2*)&outF[(size_t)row * 1024 + col] = {v00, v01};
                *(float2*)&outF[(size_t)(row + 8) * 1024 + col] = {v10, v11};
            } else {
                __nv_bfloat16 h00 = __float2bfloat16(v00), h01 = __float2bfloat16(v01);
                __nv_bfloat16 h10 = __float2bfloat16(v10), h11 = __float2bfloat16(v11);
                __nv_bfloat162 hp0 = {h00, h01}, hp1 = {h10, h11};
                __nv_bfloat162 lp0 = {__float2bfloat16(v00 - __bfloat162float(h00)),
                                      __float2bfloat16(v01 - __bfloat162float(h01))};
                __nv_bfloat162 lp1 = {__float2bfloat16(v10 - __bfloat162float(h10)),
                                      __float2bfloat16(v11 - __bfloat162float(h11))};
                *(__nv_bfloat162*)&outH[(size_t)row * 1024 + col] = hp0;
                *(__nv_bfloat162*)&outH[(size_t)(row + 8) * 1024 + col] = hp1;
                *(__nv_bfloat162*)&outL[(size_t)row * 1024 + col] = lp0;
                *(__nv_bfloat162*)&outL[(size_t)(row + 8) * 1024 + col] = lp1;
            }
        }
    }
}

// ------------------- pass 1 (slim): column sums of exp(QK^T) masked --------------
static constexpr int A1_PITCH = 144;
static constexpr int A1_TILE  = 128 * A1_PITCH;
static constexpr int A1_SMEM  = 4 * A1_TILE;

__global__ __launch_bounds__(256, 2) void attn1_mma()
{
    extern __shared__ char smem[];
    int idx = blockIdx.x;
    int qt = (int)((sqrtf(8.f*idx + 1.f) - 1.f) * 0.5f);
    if ((qt+1)*(qt+2)/2 <= idx) qt++;
    if (qt*(qt+1)/2 > idx) qt--;
    int kt = idx - qt*(qt+1)/2;
    int bh = blockIdx.y;
    const uint32_t sb = smem_u32(smem);
    int b = bh >> 4, h = bh & 15;
    int q0 = qt * 128, k0 = kt * 128;
    int tid = threadIdx.x, lane = tid & 31, warp = tid >> 5;
    int wm = warp >> 2, wn = warp & 3;

    {
        const __nv_bfloat16* tp[4] = {g_Qph, g_Qpl, g_Kph, g_Kpl};
#pragma unroll
        for (int t = 0; t < 4; t++) {
            int r0 = (t < 2) ? q0 : k0;
#pragma unroll
            for (int i = 0; i < 4; i++) {
                int ix = tid + i * 256;
                int row = ix >> 3, sg = ix & 7;
                cpa16(sb + t * A1_TILE + row * A1_PITCH + sg * 16,
                      tp[t] + (size_t)(b*SS + r0 + row) * 1024 + h*64 + sg * 8);
            }
        }
    }
    CPA_COMMIT(); CPA_WAIT0();
    __syncthreads();

    float acc[4][4][4];
#pragma unroll
    for (int i = 0; i < 4; i++)
#pragma unroll
        for (int j = 0; j < 4; j++)
#pragma unroll
            for (int k = 0; k < 4; k++) acc[i][j][k] = 0.f;

#pragma unroll
    for (int kk = 0; kk < 4; kk++) {
        uint32_t ahr[4][4], alr[4][4], bhf[4][2], blf[4][2];
        uint32_t aoff = (uint32_t)(wm*64 + (lane & 15)) * A1_PITCH
                      + (uint32_t)(kk*16 + (lane >> 4) * 8) * 2;
#pragma unroll
        for (int mt = 0; mt < 4; mt++) {
            LDSM4(ahr[mt], sb + aoff + mt * (16*A1_PITCH));
            LDSM4(alr[mt], sb + A1_TILE + aoff + mt * (16*A1_PITCH));
        }
        uint32_t boff = (uint32_t)(wn*32 + (lane & 7) + ((lane >> 4) << 3)) * A1_PITCH
                      + (uint32_t)(kk*16 + ((lane >> 3) & 1) * 8) * 2;
        {
            uint32_t t0[4], t1[4];
            LDSM4(t0, sb + 2*A1_TILE + boff);
            LDSM4(t1, sb + 2*A1_TILE + boff + 16*A1_PITCH);
            bhf[0][0]=t0[0]; bhf[0][1]=t0[1]; bhf[1][0]=t0[2]; bhf[1][1]=t0[3];
            bhf[2][0]=t1[0]; bhf[2][1]=t1[1]; bhf[3][0]=t1[2]; bhf[3][1]=t1[3];
            LDSM4(t0, sb + 3*A1_TILE + boff);
            LDSM4(t1, sb + 3*A1_TILE + boff + 16*A1_PITCH);
            blf[0][0]=t0[0]; blf[0][1]=t0[1]; blf[1][0]=t0[2]; blf[1][1]=t0[3];
            blf[2][0]=t1[0]; blf[2][1]=t1[1]; blf[3][0]=t1[2]; blf[3][1]=t1[3];
        }
#pragma unroll
        for (int mt = 0; mt < 4; mt++)
#pragma unroll
            for (int nt = 0; nt < 4; nt++) {
                MMA16816(acc[mt][nt], ahr[mt], bhf[nt][0], bhf[nt][1]);
                MMA16816(acc[mt][nt], ahr[mt], blf[nt][0], blf[nt][1]);
                MMA16816(acc[mt][nt], alr[mt], bhf[nt][0], bhf[nt][1]);
            }
    }

    __syncthreads();
    float* cs = (float*)smem;
    if (tid < 128) cs[tid] = 0.f;
    __syncthreads();

    const bool diag = (qt == kt);
    int r_ = lane >> 2, c_ = (lane & 3) * 2;
    float cs0[4] = {0,0,0,0}, cs1[4] = {0,0,0,0};
#pragma unroll
    for (int mt = 0; mt < 4; mt++) {
        int qb = q0 + wm*64 + mt*16;
#pragma unroll
        for (int nt = 0; nt < 4; nt++) {
            int k = k0 + wn*32 + nt*8 + c_;
            float e00 = __expf(acc[mt][nt][0]);
            float e01 = __expf(acc[mt][nt][1]);
            float e10 = __expf(acc[mt][nt][2]);
            float e11 = __expf(acc[mt][nt][3]);
            int qr0 = qb + r_, qr1 = qb + r_ + 8;
            if (diag) {
                if (qr0 < k)     e00 = 0.f;
                if (qr0 < k + 1) e01 = 0.f;
                if (qr1 < k)     e10 = 0.f;
                if (qr1 < k + 1) e11 = 0.f;
            }
            cs0[nt] += e00 + e10;
            cs1[nt] += e01 + e11;
        }
    }
#pragma unroll
    for (int nt = 0; nt < 4; nt++) {
        atomicAdd(&cs[wn*32 + nt*8 + c_],     cs0[nt]);
        atomicAdd(&cs[wn*32 + nt*8 + c_ + 1], cs1[nt]);
    }
    __syncthreads();
    if (tid < 128)
        atomicAdd(&g_colsum[(size_t)bh*SS + k0 + tid], cs[tid]);
}

// ------------------- Vrt prep: bf16 hi/lo ----------------------------------------
__global__ __launch_bounds__(256) void vrt_kernel()
{
    __shared__ float t[32][33];
    int kt = blockIdx.x, dt = blockIdx.y, bh = blockIdx.z;
    int b = bh >> 4, h = bh & 15;
    int k0 = kt * 32, d0 = dt * 32;
    int x = threadIdx.x & 31, y = threadIdx.x >> 5;
#pragma unroll
    for (int i = y; i < 32; i += 8) {
        int k = k0 + i;
        float r = 1.0f / (g_colsum[(size_t)bh*SS + k] * 8.0f);
        t[i][x] = g_V[(size_t)(b*SS + k) * HDIM + h*64 + d0 + x] * r;
    }
    __syncthreads();
#pragma unroll
    for (int i = y; i < 32; i += 8) {
        int d = d0 + i, k = k0 + x;
        float v = t[x][i];
        __nv_bfloat16 hh = __float2bfloat16(v);
        size_t idx = ((size_t)bh*64 + d) * SS + k;
        g_Vrth[idx] = hh;
        g_Vrtl[idx] = __float2bfloat16(v - __bfloat162float(hh));
    }
}

// ------------------- pass 2 (flash, wk-split): out = exp(QK^T) @ Vrt^T -----------
// 8 warps = wm(4: m32) x wk(2: k16 slice). Per-warp PV partials over its k slice;
// one cross-warp smem reduction at the end.
static constexpr int F2_QTILE = 16384;                        // 128 rows x 128B (per hi/lo)
static constexpr int F2_KTILE = 4096;                         // 32 k-rows x 128B
static constexpr int F2_VTILE = 4096;                         // 64 d-rows x 64B packed
static constexpr int F2_STAGE = 2*F2_KTILE + 2*F2_VTILE;      // 16384
static constexpr int F2_SMEM  = 2*F2_QTILE + 4*F2_STAGE;      // 98304

__global__ __launch_bounds__(256, 2) void attn2_mma()
{
    extern __shared__ char smem[];
    const uint32_t sb = smem_u32(smem);
    int qt = (int)gridDim.x - 1 - (int)blockIdx.x;   // LPT: heavy tiles first
    int bh = blockIdx.y;
    int b = bh >> 4, h = bh & 15;
    int q0 = qt * 128;
    int tid = threadIdx.x, lane = tid & 31, warp = tid >> 5;
    int wm = warp & 3, wk = warp >> 2;
    int nch = (qt + 1) * 4;

    const uint32_t qbh = sb;
    const uint32_t qbl = sb + F2_QTILE;
    const uint32_t stb = sb + 2*F2_QTILE;

    // resident Q tile (hi+lo), grouped with stage 0
#pragma unroll
    for (int i = 0; i < 4; i++) {
        int ix = tid + i * 256;
        int row = ix >> 3, sg = ix & 7;
        size_t gi = (size_t)(b*SS + q0 + row) * 1024 + h*64 + sg * 8;
        uint32_t off = SWZ128((uint32_t)(row * 128 + sg * 16));
        cpa16(qbh + off, &g_Qph[gi]);
        cpa16(qbl + off, &g_Qpl[gi]);
    }

    auto load_stage = [&](int st, int c) {
        int k0 = c * 32;
        uint32_t s = stb + st * F2_STAGE;
        {
            int row = tid >> 3, sg = tid & 7;
            size_t gi = (size_t)(b*SS + k0 + row) * 1024 + h*64 + sg * 8;
            uint32_t off = SWZ128((uint32_t)(row * 128 + sg * 16));
            cpa16(s + off, &g_Kph[gi]);
            cpa16(s + F2_KTILE + off, &g_Kpl[gi]);
        }
        {
            int row = tid >> 2, sg = tid & 3;
            size_t gi = ((size_t)bh*64 + row) * SS + k0 + sg * 8;
            uint32_t off = swz_off(row, sg);
            cpa16(s + 2*F2_KTILE + off, &g_Vrth[gi]);
            cpa16(s + 2*F2_KTILE + F2_VTILE + off, &g_Vrtl[gi]);
        }
    };

    load_stage(0, 0); CPA_COMMIT();
    load_stage(1, 1); CPA_COMMIT();
    load_stage(2, 2); CPA_COMMIT();

    float oacc[2][8][4];
#pragma unroll
    for (int i = 0; i < 2; i++)
#pragma unroll
        for (int j = 0; j < 8; j++)
#pragma unroll
            for (int k = 0; k < 4; k++) oacc[i][j][k] = 0.f;

    const int r_ = lane >> 2, t2 = (lane & 3) * 2;

#pragma unroll 1
    for (int c = 0; c < nch; c++) {
        CPA_WAIT2();
        __syncthreads();
        if (c + 3 < nch) load_stage((c + 3) & 3, c + 3);
        CPA_COMMIT();
        uint32_t s = stb + (c & 3) * F2_STAGE;
        int k0 = c * 32;

        // ---- S = Q @ K^T : per warp m32 x n16 (k-slice wk*16)
        float sacc[2][2][4];
#pragma unroll
        for (int i = 0; i < 2; i++)
#pragma unroll
            for (int j = 0; j < 2; j++)
#pragma unroll
                for (int k = 0; k < 4; k++) sacc[i][j][k] = 0.f;

#pragma unroll
        for (int kk = 0; kk < 4; kk++) {
            uint32_t aqh[2][4], aql[2][4];
#pragma unroll
            for (int mt = 0; mt < 2; mt++) {
                uint32_t arow = (uint32_t)(wm*32 + mt*16 + (lane & 15));
                uint32_t aoff = SWZ128(arow * 128 + (uint32_t)(kk*32 + (lane >> 4) * 16));
                LDSM4(aqh[mt], qbh + aoff);
                LDSM4(aql[mt], qbl + aoff);
            }
            uint32_t brow = (uint32_t)(wk*16 + (lane & 7) + ((lane >> 4) << 3));
            uint32_t bcol = (uint32_t)(kk*32 + ((lane >> 3) & 1) * 16);
            uint32_t kbh[4], kbl[4];
            LDSM4(kbh, s + SWZ128(brow * 128 + bcol));
            LDSM4(kbl, s + F2_KTILE + SWZ128(brow * 128 + bcol));
#pragma unroll
            for (int mt = 0; mt < 2; mt++)
#pragma unroll
                for (int nf = 0; nf < 2; nf++) {
                    MMA16816(sacc[mt][nf], aqh[mt], kbh[nf*2], kbh[nf*2+1]);
                    MMA16816(sacc[mt][nf], aqh[mt], kbl[nf*2], kbl[nf*2+1]);
                    MMA16816(sacc[mt][nf], aql[mt], kbh[nf*2], kbh[nf*2+1]);
                }
        }

        // ---- P = exp(S) masked -> bf16 hi/lo A-fragments (m16k16 per mt)
        uint32_t pah[2][4], pal[2][4];
#pragma unroll
        for (int mt = 0; mt < 2; mt++) {
            int qr = q0 + wm*32 + mt*16 + r_;
            const bool needmask = (k0 + wk*16 + 16 > q0 + wm*32 + mt*16);
#pragma unroll
            for (int nf = 0; nf < 2; nf++) {
                int kc = k0 + wk*16 + nf*8 + t2;
                float e0 = __expf(sacc[mt][nf][0]);
                float e1 = __expf(sacc[mt][nf][1]);
                float e2 = __expf(sacc[mt][nf][2]);
                float e3 = __expf(sacc[mt][nf][3]);
                if (needmask) {
                    if (kc     > qr)     e0 = 0.f;
                    if (kc + 1 > qr)     e1 = 0.f;
                    if (kc     > qr + 8) e2 = 0.f;
                    if (kc + 1 > qr + 8) e3 = 0.f;
                }
                float h0 = __bfloat162float(__float2bfloat16(e0));
                float h1 = __bfloat162float(__float2bfloat16(e1));
                float h2 = __bfloat162float(__float2bfloat16(e2));
                float h3 = __bfloat162float(__float2bfloat16(e3));
                pah[mt][nf*2+0] = pack_bf2(h0, h1);
                pah[mt][nf*2+1] = pack_bf2(h2, h3);
                pal[mt][nf*2+0] = pack_bf2(e0 - h0, e1 - h1);
                pal[mt][nf*2+1] = pack_bf2(e2 - h2, e3 - h3);
            }
        }

        // ---- oacc += P @ Vr^T (d64, warp k-slice 16)
        {
            uint32_t vb = s + 2*F2_KTILE;
            int brow = (lane & 7) + ((lane >> 4) << 3);
            int bc = wk*2 + ((lane >> 3) & 1);
#pragma unroll
            for (int g = 0; g < 4; g++) {
                uint32_t th[4], tl[4];
                LDSM4(th, vb + swz_off(brow + g*16, bc));
                LDSM4(tl, vb + F2_VTILE + swz_off(brow + g*16, bc));
#pragma unroll
                for (int mt = 0; mt < 2; mt++) {
                    MMA16816(oacc[mt][2*g],   pah[mt], th[0], th[1]);
                    MMA16816(oacc[mt][2*g],   pah[mt], tl[0], tl[1]);
                    MMA16816(oacc[mt][2*g],   pal[mt], th[0], th[1]);
                    MMA16816(oacc[mt][2*g+1], pah[mt], th[2], th[3]);
                    MMA16816(oacc[mt][2*g+1], pah[mt], tl[2], tl[3]);
                    MMA16816(oacc[mt][2*g+1], pal[mt], th[2], th[3]);
                }
            }
        }
    }

    // ---- cross-warp (wk) reduction via smem, then epilogue by wk==0 warps
    __syncthreads();
    float* red = (float*)(smem + 2*F2_QTILE);     // 128 x 66 floats = 33792 B
    if (wk == 1) {
#pragma unroll
        for (int mt = 0; mt < 2; mt++) {
            int row0 = wm*32 + mt*16 + r_;
#pragma unroll
            for (int nt = 0; nt < 8; nt++) {
                int d = nt*8 + t2;
                red[row0*66 + d]         = oacc[mt][nt][0];
                red[row0*66 + d + 1]     = oacc[mt][nt][1];
                red[(row0+8)*66 + d]     = oacc[mt][nt][2];
                red[(row0+8)*66 + d + 1] = oacc[mt][nt][3];
            }
        }
    }
    __syncthreads();
    if (wk == 0) {
#pragma unroll
        for (int mt = 0; mt < 2; mt++) {
            int row0 = wm*32 + mt*16 + r_;
#pragma unroll
            for (int nt = 0; nt < 8; nt++) {
                int d = nt*8 + t2;
                float v00 = oacc[mt][nt][0] + red[row0*66 + d];
                float v01 = oacc[mt][nt][1] + red[row0*66 + d + 1];
                float v10 = oacc[mt][nt][2] + red[(row0+8)*66 + d];
                float v11 = oacc[mt][nt][3] + red[(row0+8)*66 + d + 1];
                size_t i0 = (size_t)(b*SS + q0 + row0) * HDIM + h*64 + d;
                size_t i1 = (size_t)(b*SS + q0 + row0 + 8) * HDIM + h*64 + d;
                __nv_bfloat16 h00 = __float2bfloat16(v00), h01 = __float2bfloat16(v01);
                __nv_bfloat16 h10 = __float2bfloat16(v10), h11 = __float2bfloat16(v11);
                __nv_bfloat162 hp0 = {h00, h01}, hp1 = {h10, h11};
                __nv_bfloat162 lp0 = {__float2bfloat16(v00 - __bfloat162float(h00)),
                                      __float2bfloat16(v01 - __bfloat162float(h01))};
                __nv_bfloat162 lp1 = {__float2bfloat16(v10 - __bfloat162float(h10)),
                                      __float2bfloat16(v11 - __bfloat162float(h11))};
                *(__nv_bfloat162*)&g_aoh[i0] = hp0;  *(__nv_bfloat162*)&g_aol[i0] = lp0;
                *(__nv_bfloat162*)&g_aoh[i1] = hp1;  *(__nv_bfloat162*)&g_aol[i1] = lp1;
            }
        }
    }
}

// ------------------- launch ------------------------------------------------------
extern "C" void kernel_launch(void* const* d_in, const int* in_sizes, int n_in,
                              void* d_out, int out_size)
{
    const float* queries = (const float*)d_in[0];
    const float* keys    = (const float*)d_in[1];
    const float* values  = (const float*)d_in[2];
    const float* Wq_w = (const float*)d_in[3];  const float* Wq_b = (const float*)d_in[4];
    const float* Wk_w = (const float*)d_in[5];  const float* Wk_b = (const float*)d_in[6];
    const float* Wv_w = (const float*)d_in[7];  const float* Wv_b = (const float*)d_in[8];
    const float* Aq_w = (const float*)d_in[9];  const float* Aq_b = (const float*)d_in[10];
    const float* Bq_w = (const float*)d_in[11]; const float* Bq_b = (const float*)d_in[12];
    const float* Ak_w = (const float*)d_in[13]; const float* Ak_b = (const float*)d_in[14];
    const float* Bk_w = (const float*)d_in[15]; const float* Bk_b = (const float*)d_in[16];
    const float* Av_w = (const float*)d_in[17]; const float* Av_b = (const float*)d_in[18];
    const float* Bv_w = (const float*)d_in[19]; const float* Bv_b = (const float*)d_in[20];
    const float* Wo_w = (const float*)d_in[21]; const float* Wo_b = (const float*)d_in[22];
    float* out = (float*)d_out;

    cudaFuncSetAttribute(gemm_mma, cudaFuncAttributeMaxDynamicSharedMemorySize, GEMM_SMEM);
    cudaFuncSetAttribute(attn1_mma, cudaFuncAttributeMaxDynamicSharedMemorySize, A1_SMEM);
    cudaFuncSetAttribute(attn2_mma, cudaFuncAttributeMaxDynamicSharedMemorySize, F2_SMEM);

    void *pbeq, *pbek, *pbev, *pV, *pcs, *pKA;
    void *pqh, *pql, *pkh, *pkl, *pvh, *pvl, *paoh, *paol;
    void *pQph, *pQpl, *pKph, *pKpl;
    void *pwqh, *pwql, *pwkh, *pwkl, *pwvh, *pwvl, *pwoh, *pwol;
    cudaGetSymbolAddress(&pbeq, g_beq); cudaGetSymbolAddress(&pbek, g_bek);
    cudaGetSymbolAddress(&pbev, g_bev); cudaGetSymbolAddress(&pV, g_V);
    cudaGetSymbolAddress(&pcs, g_colsum); cudaGetSymbolAddress(&pKA, g_KA);
    cudaGetSymbolAddress(&pqh, g_qh); cudaGetSymbolAddress(&pql, g_ql);
    cudaGetSymbolAddress(&pkh, g_kh); cudaGetSymbolAddress(&pkl, g_kl);
    cudaGetSymbolAddress(&pvh, g_vh); cudaGetSymbolAddress(&pvl, g_vl);
    cudaGetSymbolAddress(&paoh, g_aoh); cudaGetSymbolAddress(&paol, g_aol);
    cudaGetSymbolAddress(&pQph, g_Qph); cudaGetSymbolAddress(&pQpl, g_Qpl);
    cudaGetSymbolAddress(&pKph, g_Kph); cudaGetSymbolAddress(&pKpl, g_Kpl);
    cudaGetSymbolAddress(&pwqh, g_wqh); cudaGetSymbolAddress(&pwql, g_wql);
    cudaGetSymbolAddress(&pwkh, g_wkh); cudaGetSymbolAddress(&pwkl, g_wkl);
    cudaGetSymbolAddress(&pwvh, g_wvh); cudaGetSymbolAddress(&pwvl, g_wvl);
    cudaGetSymbolAddress(&pwoh, g_woh); cudaGetSymbolAddress(&pwol, g_wol);

    ActArgs aa;
    aa.X[0] = queries; aa.X[1] = keys; aa.X[2] = values;
    aa.hi[0] = (__nv_bfloat16*)pqh; aa.hi[1] = (__nv_bfloat16*)pkh; aa.hi[2] = (__nv_bfloat16*)pvh;
    aa.lo[0] = (__nv_bfloat16*)pql; aa.lo[1] = (__nv_bfloat16*)pkl; aa.lo[2] = (__nv_bfloat16*)pvl;

    WprepArgs wa;
    wa.W[0] = Wq_w; wa.W[1] = Wk_w; wa.W[2] = Wv_w; wa.W[3] = Wo_w;
    wa.A[0] = Aq_w; wa.A[1] = Ak_w; wa.A[2] = nullptr; wa.A[3] = nullptr;
    wa.Bw[0] = Bq_w; wa.Bw[1] = Bk_w; wa.Bw[2] = nullptr; wa.Bw[3] = nullptr;
    wa.hi[0] = (__nv_bfloat16*)pwqh; wa.hi[1] = (__nv_bfloat16*)pwkh;
    wa.hi[2] = (__nv_bfloat16*)pwvh; wa.hi[3] = (__nv_bfloat16*)pwoh;
    wa.lo[0] = (__nv_bfloat16*)pwql; wa.lo[1] = (__nv_bfloat16*)pwkl;
    wa.lo[2] = (__nv_bfloat16*)pwvl; wa.lo[3] = (__nv_bfloat16*)pwol;

    BeffArgs ba;
    ba.Wb[0] = Wq_b; ba.Wb[1] = Wk_b; ba.Wb[2] = Wv_b;
    ba.Ab[0] = Aq_b; ba.Ab[1] = Ak_b; ba.Ab[2] = Av_b;
    ba.Bw[0] = Bq_w; ba.Bw[1] = Bk_w; ba.Bw[2] = Bv_w;
    ba.Bb[0] = Bq_b; ba.Bb[1] = Bk_b; ba.Bb[2] = Bv_b;
    ba.out[0] = (float*)pbeq; ba.out[1] = (float*)pbek; ba.out[2] = (float*)pbev;

    GemmArgs ga;
    ga.Ah[0] = (const __nv_bfloat16*)pqh;  ga.Al[0] = (const __nv_bfloat16*)pql;
    ga.Ah[1] = (const __nv_bfloat16*)pkh;  ga.Al[1] = (const __nv_bfloat16*)pkl;
    ga.Ah[2] = (const __nv_bfloat16*)pvh;  ga.Al[2] = (const __nv_bfloat16*)pvl;
    ga.Ah[3] = (const __nv_bfloat16*)paoh; ga.Al[3] = (const __nv_bfloat16*)paol;
    ga.Bh[0] = (const __nv_bfloat16*)pwqh; ga.Bl[0] = (const __nv_bfloat16*)pwql;
    ga.Bh[1] = (const __nv_bfloat16*)pwkh; ga.Bl[1] = (const __nv_bfloat16*)pwkl;
    ga.Bh[2] = (const __nv_bfloat16*)pwvh; ga.Bl[2] = (const __nv_bfloat16*)pwvl;
    ga.Bh[3] = (const __nv_bfloat16*)pwoh; ga.Bl[3] = (const __nv_bfloat16*)pwol;
    ga.bias[0] = (const float*)pbeq; ga.bias[1] = (const float*)pbek;
    ga.bias[2] = (const float*)pbev; ga.bias[3] = Wo_b;
    ga.outF[0] = nullptr; ga.outF[1] = nullptr; ga.outF[2] = (float*)pV; ga.outF[3] = out;
    ga.outH[0] = (__nv_bfloat16*)pQph; ga.outL[0] = (__nv_bfloat16*)pQpl;
    ga.outH[1] = (__nv_bfloat16*)pKph; ga.outL[1] = (__nv_bfloat16*)pKpl;
    ga.outH[2] = nullptr; ga.outL[2] = nullptr;
    ga.outH[3] = nullptr; ga.outL[3] = nullptr;
    ga.loraKA = (const float*)pKA; ga.loraB = Bv_w;

    actconv_kernel<<<dim3((TOK*DMODEL/4)/256, 1, 3), 256>>>(aa);          // 0
    wprep_kernel<<<dim3(DMODEL/32, HDIM/32, 4), 256>>>(wa);               // 1
    beff_kernel<<<dim3(HDIM/256, 1, 3), 256>>>(ba);                       // 2
    ka_kernel<<<TOK/8, 256>>>(keys, Av_w, (float*)pKA);                   // 3
    zero_kernel<<<(BB*NH*SS)/256, 256>>>((float*)pcs);                    // 4
    gemm_mma<<<dim3(HDIM/128, TOK/128, 3), 256, GEMM_SMEM>>>(ga, 0);      // 5: QKV fused
    attn1_mma<<<dim3(136, BB*NH), 256, A1_SMEM>>>();                      // 6
    vrt_kernel<<<dim3(SS/32, 2, BB*NH), 256>>>();                         // 7
    attn2_mma<<<dim3(16, BB*NH), 256, F2_SMEM>>>();                       // 8
    gemm_mma<<<dim3(HDIM/128, TOK/128, 1), 256, GEMM_SMEM>>>(ga, 3);      // 9: O
}

// round 13
// speedup vs baseline: 1.0152x; 1.0152x over previous
#include <cuda_runtime.h>
#include <cuda_bf16.h>
#include <math.h>
#include <stdint.h>

#define BB     4
#define SS     2048
#define DMODEL 1024
#define NH     16
#define HD     64
#define HDIM   1024
#define RK     8
#define TOK    (BB*SS)   // 8192

// ------------------- device scratch (static; allocation-free) -------------------
__device__ float g_beq[HDIM];
__device__ float g_bek[HDIM];
__device__ float g_bev[HDIM];
__device__ float g_V[(size_t)TOK*HDIM];
__device__ float g_colsum[(size_t)BB*NH*SS];
__device__ float g_KA[(size_t)TOK*RK];

__device__ __nv_bfloat16 g_qh[(size_t)TOK*DMODEL], g_ql[(size_t)TOK*DMODEL];
__device__ __nv_bfloat16 g_kh[(size_t)TOK*DMODEL], g_kl[(size_t)TOK*DMODEL];
__device__ __nv_bfloat16 g_vh[(size_t)TOK*DMODEL], g_vl[(size_t)TOK*DMODEL];
__device__ __nv_bfloat16 g_Qph[(size_t)TOK*HDIM], g_Qpl[(size_t)TOK*HDIM];
__device__ __nv_bfloat16 g_Kph[(size_t)TOK*HDIM], g_Kpl[(size_t)TOK*HDIM];
__device__ __nv_bfloat16 g_aoh[(size_t)TOK*HDIM], g_aol[(size_t)TOK*HDIM];
__device__ __nv_bfloat16 g_Vrth[(size_t)BB*NH*64*SS];
__device__ __nv_bfloat16 g_Vrtl[(size_t)BB*NH*64*SS];
__device__ __nv_bfloat16 g_wqh[DMODEL*HDIM], g_wql[DMODEL*HDIM];
__device__ __nv_bfloat16 g_wkh[DMODEL*HDIM], g_wkl[DMODEL*HDIM];
__device__ __nv_bfloat16 g_wvh[DMODEL*HDIM], g_wvl[DMODEL*HDIM];
__device__ __nv_bfloat16 g_woh[DMODEL*HDIM], g_wol[DMODEL*HDIM];

// ------------------- helpers ------------------------------------------------------
__device__ __forceinline__ uint32_t smem_u32(const void* p) {
    uint32_t a;
    asm("{ .reg .u64 t; cvta.to.shared.u64 t, %1; cvt.u32.u64 %0, t; }" : "=r"(a) : "l"(p));
    return a;
}
__device__ __forceinline__ void cpa16(uint32_t dst, const void* src) {
    asm volatile("cp.async.cg.shared.global [%0], [%1], 16;"
                 :: "r"(dst), "l"(__cvta_generic_to_global(src)));
}
#define CPA_COMMIT() asm volatile("cp.async.commit_group;")
#define CPA_WAIT2()  asm volatile("cp.async.wait_group 2;")
#define CPA_WAIT1()  asm volatile("cp.async.wait_group 1;")
#define CPA_WAIT0()  asm volatile("cp.async.wait_group 0;")

#define LDSM4(r, a) \
    asm volatile("ldmatrix.sync.aligned.m8n8.x4.shared.b16 {%0,%1,%2,%3}, [%4];" \
        : "=r"((r)[0]), "=r"((r)[1]), "=r"((r)[2]), "=r"((r)[3]) : "r"(a))

#define MMA16816(c, a, b0, b1) \
    asm volatile("mma.sync.aligned.m16n8k16.row.col.f32.bf16.bf16.f32 " \
        "{%0,%1,%2,%3}, {%4,%5,%6,%7}, {%8,%9}, {%0,%1,%2,%3};" \
        : "+f"((c)[0]), "+f"((c)[1]), "+f"((c)[2]), "+f"((c)[3]) \
        : "r"((a)[0]), "r"((a)[1]), "r"((a)[2]), "r"((a)[3]), "r"(b0), "r"(b1))

__device__ __forceinline__ uint32_t pack_bf2(float lo, float hi) {
    __nv_bfloat162 p = {__float2bfloat16(lo), __float2bfloat16(hi)};
    return *(uint32_t*)&p;
}

#define SWZ128(x) ((x) ^ (((x) >> 3) & 0x70))
// logical 64B rows packed 2-per-128B-physical-row, SW128 XOR swizzle.
__device__ __forceinline__ uint32_t swz_off(int row, int chunk) {
    uint32_t o = (uint32_t)((row >> 1) * 128 + (row & 1) * 64 + chunk * 16);
    return SWZ128(o);
}

// ------------------- fused prep kernels -------------------------------------------
struct ActArgs { const float* X[3]; __nv_bfloat16 *hi[3], *lo[3]; };
__global__ void actconv_kernel(ActArgs aa)
{
    int z = blockIdx.z;
    const float* X = aa.X[z];
    __nv_bfloat16* hi = aa.hi[z];
    __nv_bfloat16* lo = aa.lo[z];
    size_t i = ((size_t)blockIdx.x * 256 + threadIdx.x) * 4;
    float4 v = *(const float4*)&X[i];
    __nv_bfloat16 h0 = __float2bfloat16(v.x), h1 = __float2bfloat16(v.y);
    __nv_bfloat16 h2 = __float2bfloat16(v.z), h3 = __float2bfloat16(v.w);
    __nv_bfloat162 ph0 = {h0, h1}, ph1 = {h2, h3};
    __nv_bfloat162 pl0 = {__float2bfloat16(v.x - __bfloat162float(h0)),
                          __float2bfloat16(v.y - __bfloat162float(h1))};
    __nv_bfloat162 pl1 = {__float2bfloat16(v.z - __bfloat162float(h2)),
                          __float2bfloat16(v.w - __bfloat162float(h3))};
    *(__nv_bfloat162*)&hi[i]   = ph0;  *(__nv_bfloat162*)&hi[i+2] = ph1;
    *(__nv_bfloat162*)&lo[i]   = pl0;  *(__nv_bfloat162*)&lo[i+2] = pl1;
}

struct WprepArgs { const float *W[4], *A[4], *Bw[4]; __nv_bfloat16 *hi[4], *lo[4]; };
__global__ __launch_bounds__(256) void wprep_kernel(WprepArgs wa)
{
    __shared__ float t[32][33];
    int z = blockIdx.z;
    const float* W = wa.W[z];
    const float* A = wa.A[z];
    const float* Bw = wa.Bw[z];
    __nv_bfloat16* hi = wa.hi[z];
    __nv_bfloat16* lo = wa.lo[z];
    int kb = blockIdx.x * 32, nb = blockIdx.y * 32;
    int x = threadIdx.x & 31, y = threadIdx.x >> 5;
#pragma unroll
    for (int i = y; i < 32; i += 8) {
        int k = kb + i, n = nb + x;
        float v = W[(size_t)k*HDIM + n];
        if (A) {
#pragma unroll
            for (int r = 0; r < RK; r++) v += A[k*RK + r] * Bw[r*HDIM + n];
        }
        t[i][x] = v;
    }
    __syncthreads();
#pragma unroll
    for (int i = y; i < 32; i += 8) {
        int n = nb + i, k = kb + x;
        float v = t[x][i];
        __nv_bfloat16 h = __float2bfloat16(v);
        hi[(size_t)n*DMODEL + k] = h;
        lo[(size_t)n*DMODEL + k] = __float2bfloat16(v - __bfloat162float(h));
    }
}

struct BeffArgs { const float *Wb[3], *Ab[3], *Bw[3], *Bb[3]; float* out[3]; };
__global__ void beff_kernel(BeffArgs ba)
{
    int z = blockIdx.z;
    int j = blockIdx.x * 256 + threadIdx.x;
    float acc = ba.Wb[z][j] + ba.Bb[z][j];
    const float* Ab = ba.Ab[z];
    const float* Bw = ba.Bw[z];
#pragma unroll
    for (int r = 0; r < RK; r++) acc += Ab[r] * Bw[r*HDIM + j];
    ba.out[z][j] = acc;
}

__global__ void zero_kernel(float* p) { p[blockIdx.x * 256 + threadIdx.x] = 0.f; }

__global__ __launch_bounds__(256) void ka_kernel(const float* __restrict__ keys,
                                                 const float* __restrict__ Av,
                                                 float* __restrict__ KA)
{
    __shared__ float avT[RK][DMODEL];
    int tid = threadIdx.x;
#pragma unroll
    for (int f = tid; f < DMODEL*RK/4; f += 256) {
        int k = f >> 1, j = (f & 1) * 4;
        float4 v = ((const float4*)Av)[f];
        avT[j+0][k] = v.x; avT[j+1][k] = v.y;
        avT[j+2][k] = v.z; avT[j+3][k] = v.w;
    }
    __syncthreads();

    int warp = tid >> 5, lane = tid & 31;
    int row = blockIdx.x * 8 + warp;
    const float4* kr = (const float4*)(keys + (size_t)row * DMODEL);
    float acc[RK];
#pragma unroll
    for (int r = 0; r < RK; r++) acc[r] = 0.f;
#pragma unroll
    for (int i = 0; i < 8; i++) {
        int k4 = lane + i * 32;
        float4 kv = kr[k4];
        int k = 4 * k4;
#pragma unroll
        for (int r = 0; r < RK; r++) {
            float4 av = *(const float4*)&avT[r][k];
            acc[r] += kv.x*av.x + kv.y*av.y + kv.z*av.z + kv.w*av.w;
        }
    }
#pragma unroll
    for (int r = 0; r < RK; r++) {
#pragma unroll
        for (int off = 16; off > 0; off >>= 1)
            acc[r] += __shfl_down_sync(0xffffffffu, acc[r], off);
    }
    if (lane == 0) {
#pragma unroll
        for (int r = 0; r < RK; r++) KA[(size_t)row*RK + r] = acc[r];
    }
}

// ------------------- fused mma.sync split-bf16 GEMM -------------------------------
static constexpr int G_TILE  = 8192;
static constexpr int G_STAGE = 4 * G_TILE;
static constexpr int GEMM_SMEM = 3 * G_STAGE;    // 98304

struct GemmArgs {
    const __nv_bfloat16 *Ah[4], *Al[4], *Bh[4], *Bl[4];
    const float* bias[4];
    float* outF[4];
    __nv_bfloat16 *outH[4], *outL[4];
    const float *loraKA, *loraB;
};

// op==0: z = blockIdx.z (QKV fused, grid.z=3). op==3: O projection.
__global__ __launch_bounds__(256, 2)
void gemm_mma(GemmArgs ga, int op)
{
    extern __shared__ char smem[];
    const uint32_t sb = smem_u32(smem);
    const int z = (op == 0) ? blockIdx.z : op;
    const __nv_bfloat16* Ah = ga.Ah[z];
    const __nv_bfloat16* Al = ga.Al[z];
    const __nv_bfloat16* Bh = ga.Bh[z];
    const __nv_bfloat16* Bl = ga.Bl[z];
    const float* bias = ga.bias[z];
    float* outF = ga.outF[z];
    __nv_bfloat16* outH = ga.outH[z];
    __nv_bfloat16* outL = ga.outL[z];
    const float* loraKA = (z == 2) ? ga.loraKA : nullptr;
    const float* loraB  = ga.loraB;

    const int tid  = threadIdx.x;
    const int lane = tid & 31;
    const int warp = tid >> 5;
    const int wm = warp >> 2, wn = warp & 3;
    const int m0 = blockIdx.y * 128, n0 = blockIdx.x * 128;

    float acc[4][4][4];
#pragma unroll
    for (int i = 0; i < 4; i++)
#pragma unroll
        for (int j = 0; j < 4; j++)
#pragma unroll
            for (int k = 0; k < 4; k++) acc[i][j][k] = 0.f;

    auto load_stage = [&](int st, int chunk) {
        int k0 = chunk * 32;
        const __nv_bfloat16* tp[4] = {Ah, Al, Bh, Bl};
        uint32_t sbase = sb + st * G_STAGE;
#pragma unroll
        for (int i = 0; i < 8; i++) {
            const int t = i >> 1;
            int j = (i & 1) ? tid + 256 : tid;
            int row = j >> 2, sg = j & 3;
            int r0 = (t < 2) ? m0 : n0;
            cpa16(sbase + t * G_TILE + swz_off(row, sg),
                  tp[t] + (size_t)(r0 + row) * 1024 + k0 + sg * 8);
        }
    };

    auto compute_stage = [&](int st) {
        uint32_t ab = sb + st * G_STAGE;
#pragma unroll
        for (int kk = 0; kk < 2; kk++) {
            uint32_t ahr[4][4], alr[4][4], bh2[4][2], bl2[4][2];
            int arow = wm*64 + (lane & 15);
            int ac   = kk*2 + (lane >> 4);
            uint32_t abase = ab + swz_off(arow, ac);
#pragma unroll
            for (int mt = 0; mt < 4; mt++) {
                LDSM4(ahr[mt], abase + mt * 1024);
                LDSM4(alr[mt], abase + G_TILE + mt * 1024);
            }
            int brow = wn*32 + (lane & 7) + ((lane >> 4) << 3);
            int bc   = kk*2 + ((lane >> 3) & 1);
            uint32_t bbase = ab + 2*G_TILE + swz_off(brow, bc);
            {
                uint32_t t0[4], t1[4];
                LDSM4(t0, bbase);
                LDSM4(t1, bbase + 1024);
                bh2[0][0]=t0[0]; bh2[0][1]=t0[1]; bh2[1][0]=t0[2]; bh2[1][1]=t0[3];
                bh2[2][0]=t1[0]; bh2[2][1]=t1[1]; bh2[3][0]=t1[2]; bh2[3][1]=t1[3];
                LDSM4(t0, bbase + G_TILE);
                LDSM4(t1, bbase + G_TILE + 1024);
                bl2[0][0]=t0[0]; bl2[0][1]=t0[1]; bl2[1][0]=t0[2]; bl2[1][1]=t0[3];
                bl2[2][0]=t1[0]; bl2[2][1]=t1[1]; bl2[3][0]=t1[2]; bl2[3][1]=t1[3];
            }
#pragma unroll
            for (int mt = 0; mt < 4; mt++)
#pragma unroll
                for (int nt = 0; nt < 4; nt++) {
                    MMA16816(acc[mt][nt], ahr[mt], bh2[nt][0], bh2[nt][1]);
                    MMA16816(acc[mt][nt], ahr[mt], bl2[nt][0], bl2[nt][1]);
                    MMA16816(acc[mt][nt], alr[mt], bh2[nt][0], bh2[nt][1]);
                }
        }
    };

    load_stage(0, 0);
    CPA_COMMIT();
    load_stage(1, 1);
    CPA_COMMIT();

#pragma unroll 1
    for (int c = 0; c < 32; c++) {
        CPA_WAIT1();
        __syncthreads();
        if (c + 2 < 32) load_stage((c + 2) % 3, c + 2);
        CPA_COMMIT();
        compute_stage(c % 3);
    }

    int r_ = lane >> 2, c_ = (lane & 3) * 2;
#pragma unroll
    for (int mt = 0; mt < 4; mt++) {
        int row = m0 + wm*64 + mt*16 + r_;
        float ka0[RK], ka1[RK];
        if (loraKA) {
#pragma unroll
            for (int r = 0; r < RK; r++) {
                ka0[r] = loraKA[(size_t)row*RK + r];
                ka1[r] = loraKA[(size_t)(row+8)*RK + r];
            }
        }
#pragma unroll
        for (int nt = 0; nt < 4; nt++) {
            int col = n0 + wn*32 + nt*8 + c_;
            float b0 = bias[col], b1 = bias[col + 1];
            float v00 = acc[mt][nt][0] + b0, v01 = acc[mt][nt][1] + b1;
            float v10 = acc[mt][nt][2] + b0, v11 = acc[mt][nt][3] + b1;
            if (loraKA) {
#pragma unroll
                for (int r = 0; r < RK; r++) {
                    float w0 = loraB[r*HDIM + col], w1 = loraB[r*HDIM + col + 1];
                    v00 += ka0[r] * w0;  v01 += ka0[r] * w1;
                    v10 += ka1[r] * w0;  v11 += ka1[r] * w1;
                }
            }
            if (outF) {
                *(float2*)&outF[(size_t)row * 1024 + col] = {v00, v01};
                *(float2*)&outF[(size_t)(row + 8) * 1024 + col] = {v10, v11};
            } else {
                __nv_bfloat16 h00 = __float2bfloat16(v00), h01 = __float2bfloat16(v01);
                __nv_bfloat16 h10 = __float2bfloat16(v10), h11 = __float2bfloat16(v11);
                __nv_bfloat162 hp0 = {h00, h01}, hp1 = {h10, h11};
                __nv_bfloat162 lp0 = {__float2bfloat16(v00 - __bfloat162float(h00)),
                                      __float2bfloat16(v01 - __bfloat162float(h01))};
                __nv_bfloat162 lp1 = {__float2bfloat16(v10 - __bfloat162float(h10)),
                                      __float2bfloat16(v11 - __bfloat162float(h11))};
                *(__nv_bfloat162*)&outH[(size_t)row * 1024 + col] = hp0;
                *(__nv_bfloat162*)&outH[(size_t)(row + 8) * 1024 + col] = hp1;
                *(__nv_bfloat162*)&outL[(size_t)row * 1024 + col] = lp0;
                *(__nv_bfloat162*)&outL[(size_t)(row + 8) * 1024 + col] = lp1;
            }
        }
    }
}

// ------------------- pass 1 (slim): column sums of exp(QK^T) masked --------------
static constexpr int A1_PITCH = 144;
static constexpr int A1_TILE  = 128 * A1_PITCH;
static constexpr int A1_SMEM  = 4 * A1_TILE;

__global__ __launch_bounds__(256, 2) void attn1_mma()
{
    extern __shared__ char smem[];
    int idx = blockIdx.x;
    int qt = (int)((sqrtf(8.f*idx + 1.f) - 1.f) * 0.5f);
    if ((qt+1)*(qt+2)/2 <= idx) qt++;
    if (qt*(qt+1)/2 > idx) qt--;
    int kt = idx - qt*(qt+1)/2;
    int bh = blockIdx.y;
    const uint32_t sb = smem_u32(smem);
    int b = bh >> 4, h = bh & 15;
    int q0 = qt * 128, k0 = kt * 128;
    int tid = threadIdx.x, lane = tid & 31, warp = tid >> 5;
    int wm = warp >> 2, wn = warp & 3;

    {
        const __nv_bfloat16* tp[4] = {g_Qph, g_Qpl, g_Kph, g_Kpl};
#pragma unroll
        for (int t = 0; t < 4; t++) {
            int r0 = (t < 2) ? q0 : k0;
#pragma unroll
            for (int i = 0; i < 4; i++) {
                int ix = tid + i * 256;
                int row = ix >> 3, sg = ix & 7;
                cpa16(sb + t * A1_TILE + row * A1_PITCH + sg * 16,
                      tp[t] + (size_t)(b*SS + r0 + row) * 1024 + h*64 + sg * 8);
            }
        }
    }
    CPA_COMMIT(); CPA_WAIT0();
    __syncthreads();

    float acc[4][4][4];
#pragma unroll
    for (int i = 0; i < 4; i++)
#pragma unroll
        for (int j = 0; j < 4; j++)
#pragma unroll
            for (int k = 0; k < 4; k++) acc[i][j][k] = 0.f;

#pragma unroll
    for (int kk = 0; kk < 4; kk++) {
        uint32_t ahr[4][4], alr[4][4], bhf[4][2], blf[4][2];
        uint32_t aoff = (uint32_t)(wm*64 + (lane & 15)) * A1_PITCH
                      + (uint32_t)(kk*16 + (lane >> 4) * 8) * 2;
#pragma unroll
        for (int mt = 0; mt < 4; mt++) {
            LDSM4(ahr[mt], sb + aoff + mt * (16*A1_PITCH));
            LDSM4(alr[mt], sb + A1_TILE + aoff + mt * (16*A1_PITCH));
        }
        uint32_t boff = (uint32_t)(wn*32 + (lane & 7) + ((lane >> 4) << 3)) * A1_PITCH
                      + (uint32_t)(kk*16 + ((lane >> 3) & 1) * 8) * 2;
        {
            uint32_t t0[4], t1[4];
            LDSM4(t0, sb + 2*A1_TILE + boff);
            LDSM4(t1, sb + 2*A1_TILE + boff + 16*A1_PITCH);
            bhf[0][0]=t0[0]; bhf[0][1]=t0[1]; bhf[1][0]=t0[2]; bhf[1][1]=t0[3];
            bhf[2][0]=t1[0]; bhf[2][1]=t1[1]; bhf[3][0]=t1[2]; bhf[3][1]=t1[3];
            LDSM4(t0, sb + 3*A1_TILE + boff);
            LDSM4(t1, sb + 3*A1_TILE + boff + 16*A1_PITCH);
            blf[0][0]=t0[0]; blf[0][1]=t0[1]; blf[1][0]=t0[2]; blf[1][1]=t0[3];
            blf[2][0]=t1[0]; blf[2][1]=t1[1]; blf[3][0]=t1[2]; blf[3][1]=t1[3];
        }
#pragma unroll
        for (int mt = 0; mt < 4; mt++)
#pragma unroll
            for (int nt = 0; nt < 4; nt++) {
                MMA16816(acc[mt][nt], ahr[mt], bhf[nt][0], bhf[nt][1]);
                MMA16816(acc[mt][nt], ahr[mt], blf[nt][0], blf[nt][1]);
                MMA16816(acc[mt][nt], alr[mt], bhf[nt][0], bhf[nt][1]);
            }
    }

    __syncthreads();
    float* cs = (float*)smem;
    if (tid < 128) cs[tid] = 0.f;
    __syncthreads();

    const bool diag = (qt == kt);
    int r_ = lane >> 2, c_ = (lane & 3) * 2;
    float cs0[4] = {0,0,0,0}, cs1[4] = {0,0,0,0};
#pragma unroll
    for (int mt = 0; mt < 4; mt++) {
        int qb = q0 + wm*64 + mt*16;
#pragma unroll
        for (int nt = 0; nt < 4; nt++) {
            int k = k0 + wn*32 + nt*8 + c_;
            float e00 = __expf(acc[mt][nt][0]);
            float e01 = __expf(acc[mt][nt][1]);
            float e10 = __expf(acc[mt][nt][2]);
            float e11 = __expf(acc[mt][nt][3]);
            int qr0 = qb + r_, qr1 = qb + r_ + 8;
            if (diag) {
                if (qr0 < k)     e00 = 0.f;
                if (qr0 < k + 1) e01 = 0.f;
                if (qr1 < k)     e10 = 0.f;
                if (qr1 < k + 1) e11 = 0.f;
            }
            cs0[nt] += e00 + e10;
            cs1[nt] += e01 + e11;
        }
    }
#pragma unroll
    for (int nt = 0; nt < 4; nt++) {
        atomicAdd(&cs[wn*32 + nt*8 + c_],     cs0[nt]);
        atomicAdd(&cs[wn*32 + nt*8 + c_ + 1], cs1[nt]);
    }
    __syncthreads();
    if (tid < 128)
        atomicAdd(&g_colsum[(size_t)bh*SS + k0 + tid], cs[tid]);
}

// ------------------- Vrt prep: bf16 hi/lo ----------------------------------------
__global__ __launch_bounds__(256) void vrt_kernel()
{
    __shared__ float t[32][33];
    int kt = blockIdx.x, dt = blockIdx.y, bh = blockIdx.z;
    int b = bh >> 4, h = bh & 15;
    int k0 = kt * 32, d0 = dt * 32;
    int x = threadIdx.x & 31, y = threadIdx.x >> 5;
#pragma unroll
    for (int i = y; i < 32; i += 8) {
        int k = k0 + i;
        float r = 1.0f / (g_colsum[(size_t)bh*SS + k] * 8.0f);
        t[i][x] = g_V[(size_t)(b*SS + k) * HDIM + h*64 + d0 + x] * r;
    }
    __syncthreads();
#pragma unroll
    for (int i = y; i < 32; i += 8) {
        int d = d0 + i, k = k0 + x;
        float v = t[x][i];
        __nv_bfloat16 hh = __float2bfloat16(v);
        size_t idx = ((size_t)bh*64 + d) * SS + k;
        g_Vrth[idx] = hh;
        g_Vrtl[idx] = __float2bfloat16(v - __bfloat162float(hh));
    }
}

// ------------------- pass 2 (flash): recompute P = exp(QK^T), out = P @ Vrt^T ----
// Per CTA: q-tile 128, loop k-chunks of 32. Q resident; K+Vr 4-stage pipeline.
// Warp layout: 8 warps x m16 (round-11 proven operating point, oacc = 32 regs).
static constexpr int F2_QTILE = 16384;                        // 128 rows x 128B (per hi/lo)
static constexpr int F2_KTILE = 4096;                         // 32 k-rows x 128B
static constexpr int F2_VTILE = 4096;                         // 64 d-rows x 64B packed
static constexpr int F2_STAGE = 2*F2_KTILE + 2*F2_VTILE;      // 16384
static constexpr int F2_SMEM  = 2*F2_QTILE + 4*F2_STAGE;      // 98304

__global__ __launch_bounds__(256, 2) void attn2_mma()
{
    extern __shared__ char smem[];
    const uint32_t sb = smem_u32(smem);
    int qt = (int)gridDim.x - 1 - (int)blockIdx.x;   // LPT: heavy tiles first
    int bh = blockIdx.y;
    int b = bh >> 4, h = bh & 15;
    int q0 = qt * 128;
    int tid = threadIdx.x, lane = tid & 31, warp = tid >> 5;
    int nch = (qt + 1) * 4;

    const uint32_t qbh = sb;
    const uint32_t qbl = sb + F2_QTILE;
    const uint32_t stb = sb + 2*F2_QTILE;

    // resident Q tile (hi+lo), grouped with stage 0
#pragma unroll
    for (int i = 0; i < 4; i++) {
        int ix = tid + i * 256;
        int row = ix >> 3, sg = ix & 7;
        size_t gi = (size_t)(b*SS + q0 + row) * 1024 + h*64 + sg * 8;
        uint32_t off = SWZ128((uint32_t)(row * 128 + sg * 16));
        cpa16(qbh + off, &g_Qph[gi]);
        cpa16(qbl + off, &g_Qpl[gi]);
    }

    auto load_stage = [&](int st, int c) {
        int k0 = c * 32;
        uint32_t s = stb + st * F2_STAGE;
        {   // K chunk: 32 k-rows x 128B, hi & lo
            int row = tid >> 3, sg = tid & 7;
            size_t gi = (size_t)(b*SS + k0 + row) * 1024 + h*64 + sg * 8;
            uint32_t off = SWZ128((uint32_t)(row * 128 + sg * 16));
            cpa16(s + off, &g_Kph[gi]);
            cpa16(s + F2_KTILE + off, &g_Kpl[gi]);
        }
        {   // Vr chunk: 64 d-rows x 64B (packed swizzle), hi & lo
            int row = tid >> 2, sg = tid & 3;
            size_t gi = ((size_t)bh*64 + row) * SS + k0 + sg * 8;
            uint32_t off = swz_off(row, sg);
            cpa16(s + 2*F2_KTILE + off, &g_Vrth[gi]);
            cpa16(s + 2*F2_KTILE + F2_VTILE + off, &g_Vrtl[gi]);
        }
    };

    load_stage(0, 0); CPA_COMMIT();     // group: Q + stage0
    load_stage(1, 1); CPA_COMMIT();
    load_stage(2, 2); CPA_COMMIT();

    float oacc[8][4];
#pragma unroll
    for (int i = 0; i < 8; i++)
#pragma unroll
        for (int j = 0; j < 4; j++) oacc[i][j] = 0.f;

    const int r_ = lane >> 2, t2 = (lane & 3) * 2;
    const int qrow = q0 + warp*16 + r_;

#pragma unroll 1
    for (int c = 0; c < nch; c++) {
        CPA_WAIT2();
        __syncthreads();
        if (c + 3 < nch) load_stage((c + 3) & 3, c + 3);
        CPA_COMMIT();
        uint32_t s = stb + (c & 3) * F2_STAGE;
        int k0 = c * 32;

        // ---- S = Q @ K^T (m16 per warp, n32, d=64) split-bf16 3 products
        float sacc[4][4];
#pragma unroll
        for (int i = 0; i < 4; i++)
#pragma unroll
            for (int j = 0; j < 4; j++) sacc[i][j] = 0.f;

#pragma unroll
        for (int kk = 0; kk < 4; kk++) {
            uint32_t aqh[4], aql[4];
            uint32_t arow = (uint32_t)(warp*16 + (lane & 15));
            uint32_t aoff = SWZ128(arow * 128 + (uint32_t)(kk*32 + (lane >> 4) * 16));
            LDSM4(aqh, qbh + aoff);
            LDSM4(aql, qbl + aoff);
            uint32_t bh2[4][2], bl2[4][2];
            uint32_t brow = (uint32_t)((lane & 7) + ((lane >> 4) << 3));
            uint32_t bcol = (uint32_t)(kk*32 + ((lane >> 3) & 1) * 16);
            {
                uint32_t t0[4], t1[4];
                LDSM4(t0, s + SWZ128(brow * 128 + bcol));
                LDSM4(t1, s + SWZ128((brow + 16) * 128 + bcol));
                bh2[0][0]=t0[0]; bh2[0][1]=t0[1]; bh2[1][0]=t0[2]; bh2[1][1]=t0[3];
                bh2[2][0]=t1[0]; bh2[2][1]=t1[1]; bh2[3][0]=t1[2]; bh2[3][1]=t1[3];
                LDSM4(t0, s + F2_KTILE + SWZ128(brow * 128 + bcol));
                LDSM4(t1, s + F2_KTILE + SWZ128((brow + 16) * 128 + bcol));
                bl2[0][0]=t0[0]; bl2[0][1]=t0[1]; bl2[1][0]=t0[2]; bl2[1][1]=t0[3];
                bl2[2][0]=t1[0]; bl2[2][1]=t1[1]; bl2[3][0]=t1[2]; bl2[3][1]=t1[3];
            }
#pragma unroll
            for (int nt = 0; nt < 4; nt++) {
                MMA16816(sacc[nt], aqh, bh2[nt][0], bh2[nt][1]);
                MMA16816(sacc[nt], aqh, bl2[nt][0], bl2[nt][1]);
                MMA16816(sacc[nt], aql, bh2[nt][0], bh2[nt][1]);
            }
        }

        // ---- P = exp(S) masked -> bf16 hi/lo A-fragments (FA2 register reuse)
        uint32_t pah[2][4], pal[2][4];
        const bool needmask = (k0 + 32 > q0 + warp*16);
#pragma unroll
        for (int nf = 0; nf < 4; nf++) {
            int kc = k0 + nf*8 + t2;
            float e0 = __expf(sacc[nf][0]);
            float e1 = __expf(sacc[nf][1]);
            float e2 = __expf(sacc[nf][2]);
            float e3 = __expf(sacc[nf][3]);
            if (needmask) {
                if (kc     > qrow)     e0 = 0.f;
                if (kc + 1 > qrow)     e1 = 0.f;
                if (kc     > qrow + 8) e2 = 0.f;
                if (kc + 1 > qrow + 8) e3 = 0.f;
            }
            float h0 = __bfloat162float(__float2bfloat16(e0));
            float h1 = __bfloat162float(__float2bfloat16(e1));
            float h2 = __bfloat162float(__float2bfloat16(e2));
            float h3 = __bfloat162float(__float2bfloat16(e3));
            int kk2 = nf >> 1;
            int ro  = (nf & 1) * 2;
            pah[kk2][ro+0] = pack_bf2(h0, h1);
            pah[kk2][ro+1] = pack_bf2(h2, h3);
            pal[kk2][ro+0] = pack_bf2(e0 - h0, e1 - h1);
            pal[kk2][ro+1] = pack_bf2(e2 - h2, e3 - h3);
        }

        // ---- oacc += P @ Vr^T (n=64 d, k=32)
#pragma unroll
        for (int kk2 = 0; kk2 < 2; kk2++) {
            int brow = (lane & 7) + ((lane >> 4) << 3);
            int bc = kk2*2 + ((lane >> 3) & 1);
#pragma unroll
            for (int g = 0; g < 4; g++) {
                uint32_t th[4], tl[4];
                LDSM4(th, s + 2*F2_KTILE + swz_off(brow + g*16, bc));
                LDSM4(tl, s + 2*F2_KTILE + F2_VTILE + swz_off(brow + g*16, bc));
                MMA16816(oacc[2*g],   pah[kk2], th[0], th[1]);
                MMA16816(oacc[2*g],   pah[kk2], tl[0], tl[1]);
                MMA16816(oacc[2*g],   pal[kk2], th[0], th[1]);
                MMA16816(oacc[2*g+1], pah[kk2], th[2], th[3]);
                MMA16816(oacc[2*g+1], pah[kk2], tl[2], tl[3]);
                MMA16816(oacc[2*g+1], pal[kk2], th[2], th[3]);
            }
        }
    }

    // epilogue: warp rows q = qrow, qrow+8; cols d = nt*8 + t2
#pragma unroll
    for (int nt = 0; nt < 8; nt++) {
        int d = nt*8 + t2;
        float v00 = oacc[nt][0], v01 = oacc[nt][1];
        float v10 = oacc[nt][2], v11 = oacc[nt][3];
        size_t i0 = (size_t)(b*SS + qrow) * HDIM + h*64 + d;
        size_t i1 = (size_t)(b*SS + qrow + 8) * HDIM + h*64 + d;
        __nv_bfloat16 h00 = __float2bfloat16(v00), h01 = __float2bfloat16(v01);
        __nv_bfloat16 h10 = __float2bfloat16(v10), h11 = __float2bfloat16(v11);
        __nv_bfloat162 hp0 = {h00, h01}, hp1 = {h10, h11};
        __nv_bfloat162 lp0 = {__float2bfloat16(v00 - __bfloat162float(h00)),
                              __float2bfloat16(v01 - __bfloat162float(h01))};
        __nv_bfloat162 lp1 = {__float2bfloat16(v10 - __bfloat162float(h10)),
                              __float2bfloat16(v11 - __bfloat162float(h11))};
        *(__nv_bfloat162*)&g_aoh[i0] = hp0;  *(__nv_bfloat162*)&g_aol[i0] = lp0;
        *(__nv_bfloat162*)&g_aoh[i1] = hp1;  *(__nv_bfloat162*)&g_aol[i1] = lp1;
    }
}

// ------------------- launch ------------------------------------------------------
extern "C" void kernel_launch(void* const* d_in, const int* in_sizes, int n_in,
                              void* d_out, int out_size)
{
    const float* queries = (const float*)d_in[0];
    const float* keys    = (const float*)d_in[1];
    const float* values  = (const float*)d_in[2];
    const float* Wq_w = (const float*)d_in[3];  const float* Wq_b = (const float*)d_in[4];
    const float* Wk_w = (const float*)d_in[5];  const float* Wk_b = (const float*)d_in[6];
    const float* Wv_w = (const float*)d_in[7];  const float* Wv_b = (const float*)d_in[8];
    const float* Aq_w = (const float*)d_in[9];  const float* Aq_b = (const float*)d_in[10];
    const float* Bq_w = (const float*)d_in[11]; const float* Bq_b = (const float*)d_in[12];
    const float* Ak_w = (const float*)d_in[13]; const float* Ak_b = (const float*)d_in[14];
    const float* Bk_w = (const float*)d_in[15]; const float* Bk_b = (const float*)d_in[16];
    const float* Av_w = (const float*)d_in[17]; const float* Av_b = (const float*)d_in[18];
    const float* Bv_w = (const float*)d_in[19]; const float* Bv_b = (const float*)d_in[20];
    const float* Wo_w = (const float*)d_in[21]; const float* Wo_b = (const float*)d_in[22];
    float* out = (float*)d_out;

    cudaFuncSetAttribute(gemm_mma, cudaFuncAttributeMaxDynamicSharedMemorySize, GEMM_SMEM);
    cudaFuncSetAttribute(attn1_mma, cudaFuncAttributeMaxDynamicSharedMemorySize, A1_SMEM);
    cudaFuncSetAttribute(attn2_mma, cudaFuncAttributeMaxDynamicSharedMemorySize, F2_SMEM);

    void *pbeq, *pbek, *pbev, *pV, *pcs, *pKA;
    void *pqh, *pql, *pkh, *pkl, *pvh, *pvl, *paoh, *paol;
    void *pQph, *pQpl, *pKph, *pKpl;
    void *pwqh, *pwql, *pwkh, *pwkl, *pwvh, *pwvl, *pwoh, *pwol;
    cudaGetSymbolAddress(&pbeq, g_beq); cudaGetSymbolAddress(&pbek, g_bek);
    cudaGetSymbolAddress(&pbev, g_bev); cudaGetSymbolAddress(&pV, g_V);
    cudaGetSymbolAddress(&pcs, g_colsum); cudaGetSymbolAddress(&pKA, g_KA);
    cudaGetSymbolAddress(&pqh, g_qh); cudaGetSymbolAddress(&pql, g_ql);
    cudaGetSymbolAddress(&pkh, g_kh); cudaGetSymbolAddress(&pkl, g_kl);
    cudaGetSymbolAddress(&pvh, g_vh); cudaGetSymbolAddress(&pvl, g_vl);
    cudaGetSymbolAddress(&paoh, g_aoh); cudaGetSymbolAddress(&paol, g_aol);
    cudaGetSymbolAddress(&pQph, g_Qph); cudaGetSymbolAddress(&pQpl, g_Qpl);
    cudaGetSymbolAddress(&pKph, g_Kph); cudaGetSymbolAddress(&pKpl, g_Kpl);
    cudaGetSymbolAddress(&pwqh, g_wqh); cudaGetSymbolAddress(&pwql, g_wql);
    cudaGetSymbolAddress(&pwkh, g_wkh); cudaGetSymbolAddress(&pwkl, g_wkl);
    cudaGetSymbolAddress(&pwvh, g_wvh); cudaGetSymbolAddress(&pwvl, g_wvl);
    cudaGetSymbolAddress(&pwoh, g_woh); cudaGetSymbolAddress(&pwol, g_wol);

    ActArgs aa;
    aa.X[0] = queries; aa.X[1] = keys; aa.X[2] = values;
    aa.hi[0] = (__nv_bfloat16*)pqh; aa.hi[1] = (__nv_bfloat16*)pkh; aa.hi[2] = (__nv_bfloat16*)pvh;
    aa.lo[0] = (__nv_bfloat16*)pql; aa.lo[1] = (__nv_bfloat16*)pkl; aa.lo[2] = (__nv_bfloat16*)pvl;

    WprepArgs wa;
    wa.W[0] = Wq_w; wa.W[1] = Wk_w; wa.W[2] = Wv_w; wa.W[3] = Wo_w;
    wa.A[0] = Aq_w; wa.A[1] = Ak_w; wa.A[2] = nullptr; wa.A[3] = nullptr;
    wa.Bw[0] = Bq_w; wa.Bw[1] = Bk_w; wa.Bw[2] = nullptr; wa.Bw[3] = nullptr;
    wa.hi[0] = (__nv_bfloat16*)pwqh; wa.hi[1] = (__nv_bfloat16*)pwkh;
    wa.hi[2] = (__nv_bfloat16*)pwvh; wa.hi[3] = (__nv_bfloat16*)pwoh;
    wa.lo[0] = (__nv_bfloat16*)pwql; wa.lo[1] = (__nv_bfloat16*)pwkl;
    wa.lo[2] = (__nv_bfloat16*)pwvl; wa.lo[3] = (__nv_bfloat16*)pwol;

    BeffArgs ba;
    ba.Wb[0] = Wq_b; ba.Wb[1] = Wk_b; ba.Wb[2] = Wv_b;
    ba.Ab[0] = Aq_b; ba.Ab[1] = Ak_b; ba.Ab[2] = Av_b;
    ba.Bw[0] = Bq_w; ba.Bw[1] = Bk_w; ba.Bw[2] = Bv_w;
    ba.Bb[0] = Bq_b; ba.Bb[1] = Bk_b; ba.Bb[2] = Bv_b;
    ba.out[0] = (float*)pbeq; ba.out[1] = (float*)pbek; ba.out[2] = (float*)pbev;

    GemmArgs ga;
    ga.Ah[0] = (const __nv_bfloat16*)pqh;  ga.Al[0] = (const __nv_bfloat16*)pql;
    ga.Ah[1] = (const __nv_bfloat16*)pkh;  ga.Al[1] = (const __nv_bfloat16*)pkl;
    ga.Ah[2] = (const __nv_bfloat16*)pvh;  ga.Al[2] = (const __nv_bfloat16*)pvl;
    ga.Ah[3] = (const __nv_bfloat16*)paoh; ga.Al[3] = (const __nv_bfloat16*)paol;
    ga.Bh[0] = (const __nv_bfloat16*)pwqh; ga.Bl[0] = (const __nv_bfloat16*)pwql;
    ga.Bh[1] = (const __nv_bfloat16*)pwkh; ga.Bl[1] = (const __nv_bfloat16*)pwkl;
    ga.Bh[2] = (const __nv_bfloat16*)pwvh; ga.Bl[2] = (const __nv_bfloat16*)pwvl;
    ga.Bh[3] = (const __nv_bfloat16*)pwoh; ga.Bl[3] = (const __nv_bfloat16*)pwol;
    ga.bias[0] = (const float*)pbeq; ga.bias[1] = (const float*)pbek;
    ga.bias[2] = (const float*)pbev; ga.bias[3] = Wo_b;
    ga.outF[0] = nullptr; ga.outF[1] = nullptr; ga.outF[2] = (float*)pV; ga.outF[3] = out;
    ga.outH[0] = (__nv_bfloat16*)pQph; ga.outL[0] = (__nv_bfloat16*)pQpl;
    ga.outH[1] = (__nv_bfloat16*)pKph; ga.outL[1] = (__nv_bfloat16*)pKpl;
    ga.outH[2] = nullptr; ga.outL[2] = nullptr;
    ga.outH[3] = nullptr; ga.outL[3] = nullptr;
    ga.loraKA = (const float*)pKA; ga.loraB = Bv_w;

    actconv_kernel<<<dim3((TOK*DMODEL/4)/256, 1, 3), 256>>>(aa);          // 0
    wprep_kernel<<<dim3(DMODEL/32, HDIM/32, 4), 256>>>(wa);               // 1
    beff_kernel<<<dim3(HDIM/256, 1, 3), 256>>>(ba);                       // 2
    ka_kernel<<<TOK/8, 256>>>(keys, Av_w, (float*)pKA);                   // 3
    zero_kernel<<<(BB*NH*SS)/256, 256>>>((float*)pcs);                    // 4
    gemm_mma<<<dim3(HDIM/128, TOK/128, 3), 256, GEMM_SMEM>>>(ga, 0);      // 5: QKV fused
    attn1_mma<<<dim3(136, BB*NH), 256, A1_SMEM>>>();                      // 6
    vrt_kernel<<<dim3(SS/32, 2, BB*NH), 256>>>();                         // 7
    attn2_mma<<<dim3(16, BB*NH), 256, F2_SMEM>>>();                       // 8
    gemm_mma<<<dim3(HDIM/128, TOK/128, 1), 256, GEMM_SMEM>>>(ga, 3);      // 9: O
}

// round 14
// speedup vs baseline: 1.0637x; 1.0478x over previous
#include <cuda_runtime.h>
#include <cuda_bf16.h>
#include <cuda_fp16.h>
#include <math.h>
#include <stdint.h>

#define BB     4
#define SS     2048
#define DMODEL 1024
#define NH     16
#define HD     64
#define HDIM   1024
#define RK     8
#define TOK    (BB*SS)   // 8192

// ------------------- device scratch (static; allocation-free) -------------------
__device__ float g_beq[HDIM];
__device__ float g_bek[HDIM];
__device__ float g_bev[HDIM];
__device__ float g_V[(size_t)TOK*HDIM];
__device__ float g_colsum[(size_t)BB*NH*SS];
__device__ float g_KA[(size_t)TOK*RK];

// 16-bit buffers; z<2 hold bf16 hi/lo, z>=2 hold f16 hi/lo (reinterpreted)
__device__ __nv_bfloat16 g_qh[(size_t)TOK*DMODEL], g_ql[(size_t)TOK*DMODEL];
__device__ __nv_bfloat16 g_kh[(size_t)TOK*DMODEL], g_kl[(size_t)TOK*DMODEL];
__device__ __nv_bfloat16 g_vh[(size_t)TOK*DMODEL], g_vl[(size_t)TOK*DMODEL];   // f16
__device__ __nv_bfloat16 g_Qph[(size_t)TOK*HDIM], g_Qpl[(size_t)TOK*HDIM];
__device__ __nv_bfloat16 g_Kph[(size_t)TOK*HDIM], g_Kpl[(size_t)TOK*HDIM];
__device__ __nv_bfloat16 g_aoh[(size_t)TOK*HDIM], g_aol[(size_t)TOK*HDIM];     // f16
__device__ __nv_bfloat16 g_Vrth[(size_t)BB*NH*64*SS];
__device__ __nv_bfloat16 g_Vrtl[(size_t)BB*NH*64*SS];
__device__ __nv_bfloat16 g_wqh[DMODEL*HDIM], g_wql[DMODEL*HDIM];
__device__ __nv_bfloat16 g_wkh[DMODEL*HDIM], g_wkl[DMODEL*HDIM];
__device__ __nv_bfloat16 g_wvh[DMODEL*HDIM], g_wvl[DMODEL*HDIM];               // f16
__device__ __nv_bfloat16 g_woh[DMODEL*HDIM], g_wol[DMODEL*HDIM];               // f16

// ------------------- helpers ------------------------------------------------------
__device__ __forceinline__ uint32_t smem_u32(const void* p) {
    uint32_t a;
    asm("{ .reg .u64 t; cvta.to.shared.u64 t, %1; cvt.u32.u64 %0, t; }" : "=r"(a) : "l"(p));
    return a;
}
__device__ __forceinline__ void cpa16(uint32_t dst, const void* src) {
    asm volatile("cp.async.cg.shared.global [%0], [%1], 16;"
                 :: "r"(dst), "l"(__cvta_generic_to_global(src)));
}
#define CPA_COMMIT() asm volatile("cp.async.commit_group;")
#define CPA_WAIT2()  asm volatile("cp.async.wait_group 2;")
#define CPA_WAIT1()  asm volatile("cp.async.wait_group 1;")
#define CPA_WAIT0()  asm volatile("cp.async.wait_group 0;")

#define LDSM4(r, a) \
    asm volatile("ldmatrix.sync.aligned.m8n8.x4.shared.b16 {%0,%1,%2,%3}, [%4];" \
        : "=r"((r)[0]), "=r"((r)[1]), "=r"((r)[2]), "=r"((r)[3]) : "r"(a))

#define MMA16816(c, a, b0, b1) \
    asm volatile("mma.sync.aligned.m16n8k16.row.col.f32.bf16.bf16.f32 " \
        "{%0,%1,%2,%3}, {%4,%5,%6,%7}, {%8,%9}, {%0,%1,%2,%3};" \
        : "+f"((c)[0]), "+f"((c)[1]), "+f"((c)[2]), "+f"((c)[3]) \
        : "r"((a)[0]), "r"((a)[1]), "r"((a)[2]), "r"((a)[3]), "r"(b0), "r"(b1))

#define MMAF16(c, a, b0, b1) \
    asm volatile("mma.sync.aligned.m16n8k16.row.col.f32.f16.f16.f32 " \
        "{%0,%1,%2,%3}, {%4,%5,%6,%7}, {%8,%9}, {%0,%1,%2,%3};" \
        : "+f"((c)[0]), "+f"((c)[1]), "+f"((c)[2]), "+f"((c)[3]) \
        : "r"((a)[0]), "r"((a)[1]), "r"((a)[2]), "r"((a)[3]), "r"(b0), "r"(b1))

__device__ __forceinline__ uint32_t pack_bf2(float lo, float hi) {
    __nv_bfloat162 p = {__float2bfloat16(lo), __float2bfloat16(hi)};
    return *(uint32_t*)&p;
}

#define SWZ128(x) ((x) ^ (((x) >> 3) & 0x70))
__device__ __forceinline__ uint32_t swz_off(int row, int chunk) {
    uint32_t o = (uint32_t)((row >> 1) * 128 + (row & 1) * 64 + chunk * 16);
    return SWZ128(o);
}

// ------------------- fused prep kernels -------------------------------------------
// z<2: bf16 hi/lo;  z==2 (values): f16 hi/lo
struct ActArgs { const float* X[3]; __nv_bfloat16 *hi[3], *lo[3]; };
__global__ void actconv_kernel(ActArgs aa)
{
    int z = blockIdx.z;
    const float* X = aa.X[z];
    size_t i = ((size_t)blockIdx.x * 256 + threadIdx.x) * 4;
    float4 v = *(const float4*)&X[i];
    if (z < 2) {
        __nv_bfloat16* hi = aa.hi[z];
        __nv_bfloat16* lo = aa.lo[z];
        __nv_bfloat16 h0 = __float2bfloat16(v.x), h1 = __float2bfloat16(v.y);
        __nv_bfloat16 h2 = __float2bfloat16(v.z), h3 = __float2bfloat16(v.w);
        __nv_bfloat162 ph0 = {h0, h1}, ph1 = {h2, h3};
        __nv_bfloat162 pl0 = {__float2bfloat16(v.x - __bfloat162float(h0)),
                              __float2bfloat16(v.y - __bfloat162float(h1))};
        __nv_bfloat162 pl1 = {__float2bfloat16(v.z - __bfloat162float(h2)),
                              __float2bfloat16(v.w - __bfloat162float(h3))};
        *(__nv_bfloat162*)&hi[i]   = ph0;  *(__nv_bfloat162*)&hi[i+2] = ph1;
        *(__nv_bfloat162*)&lo[i]   = pl0;  *(__nv_bfloat162*)&lo[i+2] = pl1;
    } else {
        __half* hi = (__half*)aa.hi[z];
        __half* lo = (__half*)aa.lo[z];
        __half h0 = __float2half_rn(v.x), h1 = __float2half_rn(v.y);
        __half h2 = __float2half_rn(v.z), h3 = __float2half_rn(v.w);
        __half2 ph0 = {h0, h1}, ph1 = {h2, h3};
        __half2 pl0 = {__float2half_rn(v.x - __half2float(h0)),
                       __float2half_rn(v.y - __half2float(h1))};
        __half2 pl1 = {__float2half_rn(v.z - __half2float(h2)),
                       __float2half_rn(v.w - __half2float(h3))};
        *(__half2*)&hi[i]   = ph0;  *(__half2*)&hi[i+2] = ph1;
        *(__half2*)&lo[i]   = pl0;  *(__half2*)&lo[i+2] = pl1;
    }
}

// z<2: bf16 (Q,K weights).  z>=2: f16 (V, O weights).
struct WprepArgs { const float *W[4], *A[4], *Bw[4]; __nv_bfloat16 *hi[4], *lo[4]; };
__global__ __launch_bounds__(256) void wprep_kernel(WprepArgs wa)
{
    __shared__ float t[32][33];
    int z = blockIdx.z;
    const float* W = wa.W[z];
    const float* A = wa.A[z];
    const float* Bw = wa.Bw[z];
    int kb = blockIdx.x * 32, nb = blockIdx.y * 32;
    int x = threadIdx.x & 31, y = threadIdx.x >> 5;
#pragma unroll
    for (int i = y; i < 32; i += 8) {
        int k = kb + i, n = nb + x;
        float v = W[(size_t)k*HDIM + n];
        if (A) {
#pragma unroll
            for (int r = 0; r < RK; r++) v += A[k*RK + r] * Bw[r*HDIM + n];
        }
        t[i][x] = v;
    }
    __syncthreads();
    if (z < 2) {
        __nv_bfloat16* hi = wa.hi[z];
        __nv_bfloat16* lo = wa.lo[z];
#pragma unroll
        for (int i = y; i < 32; i += 8) {
            int n = nb + i, k = kb + x;
            float v = t[x][i];
            __nv_bfloat16 h = __float2bfloat16(v);
            hi[(size_t)n*DMODEL + k] = h;
            lo[(size_t)n*DMODEL + k] = __float2bfloat16(v - __bfloat162float(h));
        }
    } else {
        __half* hi = (__half*)wa.hi[z];
        __half* lo = (__half*)wa.lo[z];
#pragma unroll
        for (int i = y; i < 32; i += 8) {
            int n = nb + i, k = kb + x;
            float v = t[x][i];
            __half h = __float2half_rn(v);
            hi[(size_t)n*DMODEL + k] = h;
            lo[(size_t)n*DMODEL + k] = __float2half_rn(v - __half2float(h));
        }
    }
}

struct BeffArgs { const float *Wb[3], *Ab[3], *Bw[3], *Bb[3]; float* out[3]; };
__global__ void beff_kernel(BeffArgs ba)
{
    int z = blockIdx.z;
    int j = blockIdx.x * 256 + threadIdx.x;
    float acc = ba.Wb[z][j] + ba.Bb[z][j];
    const float* Ab = ba.Ab[z];
    const float* Bw = ba.Bw[z];
#pragma unroll
    for (int r = 0; r < RK; r++) acc += Ab[r] * Bw[r*HDIM + j];
    ba.out[z][j] = acc;
}

__global__ void zero_kernel(float* p) { p[blockIdx.x * 256 + threadIdx.x] = 0.f; }

__global__ __launch_bounds__(256) void ka_kernel(const float* __restrict__ keys,
                                                 const float* __restrict__ Av,
                                                 float* __restrict__ KA)
{
    __shared__ float avT[RK][DMODEL];
    int tid = threadIdx.x;
#pragma unroll
    for (int f = tid; f < DMODEL*RK/4; f += 256) {
        int k = f >> 1, j = (f & 1) * 4;
        float4 v = ((const float4*)Av)[f];
        avT[j+0][k] = v.x; avT[j+1][k] = v.y;
        avT[j+2][k] = v.z; avT[j+3][k] = v.w;
    }
    __syncthreads();

    int warp = tid >> 5, lane = tid & 31;
    int row = blockIdx.x * 8 + warp;
    const float4* kr = (const float4*)(keys + (size_t)row * DMODEL);
    float acc[RK];
#pragma unroll
    for (int r = 0; r < RK; r++) acc[r] = 0.f;
#pragma unroll
    for (int i = 0; i < 8; i++) {
        int k4 = lane + i * 32;
        float4 kv = kr[k4];
        int k = 4 * k4;
#pragma unroll
        for (int r = 0; r < RK; r++) {
            float4 av = *(const float4*)&avT[r][k];
            acc[r] += kv.x*av.x + kv.y*av.y + kv.z*av.z + kv.w*av.w;
        }
    }
#pragma unroll
    for (int r = 0; r < RK; r++) {
#pragma unroll
        for (int off = 16; off > 0; off >>= 1)
            acc[r] += __shfl_down_sync(0xffffffffu, acc[r], off);
    }
    if (lane == 0) {
#pragma unroll
        for (int r = 0; r < RK; r++) KA[(size_t)row*RK + r] = acc[r];
    }
}

// ------------------- fused mma.sync GEMM: bf16 3-prod (z<2) / f16 2-prod (z>=2) ---
static constexpr int G_TILE  = 8192;
static constexpr int G_STAGE = 4 * G_TILE;
static constexpr int GEMM_SMEM = 3 * G_STAGE;    // 98304

struct GemmArgs {
    const __nv_bfloat16 *Ah[4], *Al[4], *Bh[4], *Bl[4];
    const float* bias[4];
    float* outF[4];
    __nv_bfloat16 *outH[4], *outL[4];
    const float *loraKA, *loraB;
};

// op==0: z = blockIdx.z (QKV fused, grid.z=3). op==3: O projection.
__global__ __launch_bounds__(256, 2)
void gemm_mma(GemmArgs ga, int op)
{
    extern __shared__ char smem[];
    const uint32_t sb = smem_u32(smem);
    const int z = (op == 0) ? blockIdx.z : op;
    const bool F16 = (z >= 2);      // f16 2-product path (V, O)
    const __nv_bfloat16* Ah = ga.Ah[z];
    const __nv_bfloat16* Al = ga.Al[z];
    const __nv_bfloat16* Bh = ga.Bh[z];
    const __nv_bfloat16* Bl = ga.Bl[z];
    const float* bias = ga.bias[z];
    float* outF = ga.outF[z];
    __nv_bfloat16* outH = ga.outH[z];
    __nv_bfloat16* outL = ga.outL[z];
    const float* loraKA = (z == 2) ? ga.loraKA : nullptr;
    const float* loraB  = ga.loraB;

    const int tid  = threadIdx.x;
    const int lane = tid & 31;
    const int warp = tid >> 5;
    const int wm = warp >> 2, wn = warp & 3;
    const int m0 = blockIdx.y * 128, n0 = blockIdx.x * 128;

    float acc[4][4][4];
#pragma unroll
    for (int i = 0; i < 4; i++)
#pragma unroll
        for (int j = 0; j < 4; j++)
#pragma unroll
            for (int k = 0; k < 4; k++) acc[i][j][k] = 0.f;

    auto load_stage = [&](int st, int chunk) {
        int k0 = chunk * 32;
        const __nv_bfloat16* tp[4] = {Ah, Al, Bh, Bl};
        uint32_t sbase = sb + st * G_STAGE;
#pragma unroll
        for (int i = 0; i < 8; i++) {
            const int t = i >> 1;
            if (F16 && t == 3) continue;          // f16 path: B-lo never used
            int j = (i & 1) ? tid + 256 : tid;
            int row = j >> 2, sg = j & 3;
            int r0 = (t < 2) ? m0 : n0;
            cpa16(sbase + t * G_TILE + swz_off(row, sg),
                  tp[t] + (size_t)(r0 + row) * 1024 + k0 + sg * 8);
        }
    };

    auto compute_stage = [&](int st) {
        uint32_t ab = sb + st * G_STAGE;
#pragma unroll
        for (int kk = 0; kk < 2; kk++) {
            uint32_t ahr[4][4], alr[4][4], bh2[4][2], bl2[4][2];
            int arow = wm*64 + (lane & 15);
            int ac   = kk*2 + (lane >> 4);
            uint32_t abase = ab + swz_off(arow, ac);
#pragma unroll
            for (int mt = 0; mt < 4; mt++) {
                LDSM4(ahr[mt], abase + mt * 1024);
                LDSM4(alr[mt], abase + G_TILE + mt * 1024);
            }
            int brow = wn*32 + (lane & 7) + ((lane >> 4) << 3);
            int bc   = kk*2 + ((lane >> 3) & 1);
            uint32_t bbase = ab + 2*G_TILE + swz_off(brow, bc);
            {
                uint32_t t0[4], t1[4];
                LDSM4(t0, bbase);
                LDSM4(t1, bbase + 1024);
                bh2[0][0]=t0[0]; bh2[0][1]=t0[1]; bh2[1][0]=t0[2]; bh2[1][1]=t0[3];
                bh2[2][0]=t1[0]; bh2[2][1]=t1[1]; bh2[3][0]=t1[2]; bh2[3][1]=t1[3];
                if (!F16) {
                    LDSM4(t0, bbase + G_TILE);
                    LDSM4(t1, bbase + G_TILE + 1024);
                    bl2[0][0]=t0[0]; bl2[0][1]=t0[1]; bl2[1][0]=t0[2]; bl2[1][1]=t0[3];
                    bl2[2][0]=t1[0]; bl2[2][1]=t1[1]; bl2[3][0]=t1[2]; bl2[3][1]=t1[3];
                }
            }
            if (!F16) {
#pragma unroll
                for (int mt = 0; mt < 4; mt++)
#pragma unroll
                    for (int nt = 0; nt < 4; nt++) {
                        MMA16816(acc[mt][nt], ahr[mt], bh2[nt][0], bh2[nt][1]);
                        MMA16816(acc[mt][nt], ahr[mt], bl2[nt][0], bl2[nt][1]);
                        MMA16816(acc[mt][nt], alr[mt], bh2[nt][0], bh2[nt][1]);
                    }
            } else {
#pragma unroll
                for (int mt = 0; mt < 4; mt++)
#pragma unroll
                    for (int nt = 0; nt < 4; nt++) {
                        MMAF16(acc[mt][nt], ahr[mt], bh2[nt][0], bh2[nt][1]);
                        MMAF16(acc[mt][nt], alr[mt], bh2[nt][0], bh2[nt][1]);
                    }
            }
        }
    };

    load_stage(0, 0);
    CPA_COMMIT();
    load_stage(1, 1);
    CPA_COMMIT();

#pragma unroll 1
    for (int c = 0; c < 32; c++) {
        CPA_WAIT1();
        __syncthreads();
        if (c + 2 < 32) load_stage((c + 2) % 3, c + 2);
        CPA_COMMIT();
        compute_stage(c % 3);
    }

    int r_ = lane >> 2, c_ = (lane & 3) * 2;
#pragma unroll
    for (int mt = 0; mt < 4; mt++) {
        int row = m0 + wm*64 + mt*16 + r_;
        float ka0[RK], ka1[RK];
        if (loraKA) {
#pragma unroll
            for (int r = 0; r < RK; r++) {
                ka0[r] = loraKA[(size_t)row*RK + r];
                ka1[r] = loraKA[(size_t)(row+8)*RK + r];
            }
        }
#pragma unroll
        for (int nt = 0; nt < 4; nt++) {
            int col = n0 + wn*32 + nt*8 + c_;
            float b0 = bias[col], b1 = bias[col + 1];
            float v00 = acc[mt][nt][0] + b0, v01 = acc[mt][nt][1] + b1;
            float v10 = acc[mt][nt][2] + b0, v11 = acc[mt][nt][3] + b1;
            if (loraKA) {
#pragma unroll
                for (int r = 0; r < RK; r++) {
                    float w0 = loraB[r*HDIM + col], w1 = loraB[r*HDIM + col + 1];
                    v00 += ka0[r] * w0;  v01 += ka0[r] * w1;
                    v10 += ka1[r] * w0;  v11 += ka1[r] * w1;
                }
            }
            if (outF) {
                *(float2*)&outF[(size_t)row * 1024 + col] = {v00, v01};
                *(float2*)&outF[(size_t)(row + 8) * 1024 + col] = {v10, v11};
            } else {
                __nv_bfloat16 h00 = __float2bfloat16(v00), h01 = __float2bfloat16(v01);
                __nv_bfloat16 h10 = __float2bfloat16(v10), h11 = __float2bfloat16(v11);
                __nv_bfloat162 hp0 = {h00, h01}, hp1 = {h10, h11};
                __nv_bfloat162 lp0 = {__float2bfloat16(v00 - __bfloat162float(h00)),
                                      __float2bfloat16(v01 - __bfloat162float(h01))};
                __nv_bfloat162 lp1 = {__float2bfloat16(v10 - __bfloat162float(h10)),
                                      __float2bfloat16(v11 - __bfloat162float(h11))};
                *(__nv_bfloat162*)&outH[(size_t)row * 1024 + col] = hp0;
                *(__nv_bfloat162*)&outH[(size_t)(row + 8) * 1024 + col] = hp1;
                *(__nv_bfloat162*)&outL[(size_t)row * 1024 + col] = lp0;
                *(__nv_bfloat162*)&outL[(size_t)(row + 8) * 1024 + col] = lp1;
            }
        }
    }
}

// ------------------- pass 1 (slim): column sums of exp(QK^T) masked --------------
static constexpr int A1_PITCH = 144;
static constexpr int A1_TILE  = 128 * A1_PITCH;
static constexpr int A1_SMEM  = 4 * A1_TILE;

__global__ __launch_bounds__(256, 2) void attn1_mma()
{
    extern __shared__ char smem[];
    int idx = blockIdx.x;
    int qt = (int)((sqrtf(8.f*idx + 1.f) - 1.f) * 0.5f);
    if ((qt+1)*(qt+2)/2 <= idx) qt++;
    if (qt*(qt+1)/2 > idx) qt--;
    int kt = idx - qt*(qt+1)/2;
    int bh = blockIdx.y;
    const uint32_t sb = smem_u32(smem);
    int b = bh >> 4, h = bh & 15;
    int q0 = qt * 128, k0 = kt * 128;
    int tid = threadIdx.x, lane = tid & 31, warp = tid >> 5;
    int wm = warp >> 2, wn = warp & 3;

    {
        const __nv_bfloat16* tp[4] = {g_Qph, g_Qpl, g_Kph, g_Kpl};
#pragma unroll
        for (int t = 0; t < 4; t++) {
            int r0 = (t < 2) ? q0 : k0;
#pragma unroll
            for (int i = 0; i < 4; i++) {
                int ix = tid + i * 256;
                int row = ix >> 3, sg = ix & 7;
                cpa16(sb + t * A1_TILE + row * A1_PITCH + sg * 16,
                      tp[t] + (size_t)(b*SS + r0 + row) * 1024 + h*64 + sg * 8);
            }
        }
    }
    CPA_COMMIT(); CPA_WAIT0();
    __syncthreads();

    float acc[4][4][4];
#pragma unroll
    for (int i = 0; i < 4; i++)
#pragma unroll
        for (int j = 0; j < 4; j++)
#pragma unroll
            for (int k = 0; k < 4; k++) acc[i][j][k] = 0.f;

#pragma unroll
    for (int kk = 0; kk < 4; kk++) {
        uint32_t ahr[4][4], alr[4][4], bhf[4][2], blf[4][2];
        uint32_t aoff = (uint32_t)(wm*64 + (lane & 15)) * A1_PITCH
                      + (uint32_t)(kk*16 + (lane >> 4) * 8) * 2;
#pragma unroll
        for (int mt = 0; mt < 4; mt++) {
            LDSM4(ahr[mt], sb + aoff + mt * (16*A1_PITCH));
            LDSM4(alr[mt], sb + A1_TILE + aoff + mt * (16*A1_PITCH));
        }
        uint32_t boff = (uint32_t)(wn*32 + (lane & 7) + ((lane >> 4) << 3)) * A1_PITCH
                      + (uint32_t)(kk*16 + ((lane >> 3) & 1) * 8) * 2;
        {
            uint32_t t0[4], t1[4];
            LDSM4(t0, sb + 2*A1_TILE + boff);
            LDSM4(t1, sb + 2*A1_TILE + boff + 16*A1_PITCH);
            bhf[0][0]=t0[0]; bhf[0][1]=t0[1]; bhf[1][0]=t0[2]; bhf[1][1]=t0[3];
            bhf[2][0]=t1[0]; bhf[2][1]=t1[1]; bhf[3][0]=t1[2]; bhf[3][1]=t1[3];
            LDSM4(t0, sb + 3*A1_TILE + boff);
            LDSM4(t1, sb + 3*A1_TILE + boff + 16*A1_PITCH);
            blf[0][0]=t0[0]; blf[0][1]=t0[1]; blf[1][0]=t0[2]; blf[1][1]=t0[3];
            blf[2][0]=t1[0]; blf[2][1]=t1[1]; blf[3][0]=t1[2]; blf[3][1]=t1[3];
        }
#pragma unroll
        for (int mt = 0; mt < 4; mt++)
#pragma unroll
            for (int nt = 0; nt < 4; nt++) {
                MMA16816(acc[mt][nt], ahr[mt], bhf[nt][0], bhf[nt][1]);
                MMA16816(acc[mt][nt], ahr[mt], blf[nt][0], blf[nt][1]);
                MMA16816(acc[mt][nt], alr[mt], bhf[nt][0], bhf[nt][1]);
            }
    }

    __syncthreads();
    float* cs = (float*)smem;
    if (tid < 128) cs[tid] = 0.f;
    __syncthreads();

    const bool diag = (qt == kt);
    int r_ = lane >> 2, c_ = (lane & 3) * 2;
    float cs0[4] = {0,0,0,0}, cs1[4] = {0,0,0,0};
#pragma unroll
    for (int mt = 0; mt < 4; mt++) {
        int qb = q0 + wm*64 + mt*16;
#pragma unroll
        for (int nt = 0; nt < 4; nt++) {
            int k = k0 + wn*32 + nt*8 + c_;
            float e00 = __expf(acc[mt][nt][0]);
            float e01 = __expf(acc[mt][nt][1]);
            float e10 = __expf(acc[mt][nt][2]);
            float e11 = __expf(acc[mt][nt][3]);
            int qr0 = qb + r_, qr1 = qb + r_ + 8;
            if (diag) {
                if (qr0 < k)     e00 = 0.f;
                if (qr0 < k + 1) e01 = 0.f;
                if (qr1 < k)     e10 = 0.f;
                if (qr1 < k + 1) e11 = 0.f;
            }
            cs0[nt] += e00 + e10;
            cs1[nt] += e01 + e11;
        }
    }
#pragma unroll
    for (int nt = 0; nt < 4; nt++) {
        atomicAdd(&cs[wn*32 + nt*8 + c_],     cs0[nt]);
        atomicAdd(&cs[wn*32 + nt*8 + c_ + 1], cs1[nt]);
    }
    __syncthreads();
    if (tid < 128)
        atomicAdd(&g_colsum[(size_t)bh*SS + k0 + tid], cs[tid]);
}

// ------------------- Vrt prep: bf16 hi/lo ----------------------------------------
__global__ __launch_bounds__(256) void vrt_kernel()
{
    __shared__ float t[32][33];
    int kt = blockIdx.x, dt = blockIdx.y, bh = blockIdx.z;
    int b = bh >> 4, h = bh & 15;
    int k0 = kt * 32, d0 = dt * 32;
    int x = threadIdx.x & 31, y = threadIdx.x >> 5;
#pragma unroll
    for (int i = y; i < 32; i += 8) {
        int k = k0 + i;
        float r = 1.0f / (g_colsum[(size_t)bh*SS + k] * 8.0f);
        t[i][x] = g_V[(size_t)(b*SS + k) * HDIM + h*64 + d0 + x] * r;
    }
    __syncthreads();
#pragma unroll
    for (int i = y; i < 32; i += 8) {
        int d = d0 + i, k = k0 + x;
        float v = t[x][i];
        __nv_bfloat16 hh = __float2bfloat16(v);
        size_t idx = ((size_t)bh*64 + d) * SS + k;
        g_Vrth[idx] = hh;
        g_Vrtl[idx] = __float2bfloat16(v - __bfloat162float(hh));
    }
}

// ------------------- pass 2 (flash): recompute P = exp(QK^T), out = P @ Vrt^T ----
static constexpr int F2_QTILE = 16384;
static constexpr int F2_KTILE = 4096;
static constexpr int F2_VTILE = 4096;
static constexpr int F2_STAGE = 2*F2_KTILE + 2*F2_VTILE;
static constexpr int F2_SMEM  = 2*F2_QTILE + 4*F2_STAGE;      // 98304

__global__ __launch_bounds__(256, 2) void attn2_mma()
{
    extern __shared__ char smem[];
    const uint32_t sb = smem_u32(smem);
    int qt = (int)gridDim.x - 1 - (int)blockIdx.x;
    int bh = blockIdx.y;
    int b = bh >> 4, h = bh & 15;
    int q0 = qt * 128;
    int tid = threadIdx.x, lane = tid & 31, warp = tid >> 5;
    int nch = (qt + 1) * 4;

    const uint32_t qbh = sb;
    const uint32_t qbl = sb + F2_QTILE;
    const uint32_t stb = sb + 2*F2_QTILE;

#pragma unroll
    for (int i = 0; i < 4; i++) {
        int ix = tid + i * 256;
        int row = ix >> 3, sg = ix & 7;
        size_t gi = (size_t)(b*SS + q0 + row) * 1024 + h*64 + sg * 8;
        uint32_t off = SWZ128((uint32_t)(row * 128 + sg * 16));
        cpa16(qbh + off, &g_Qph[gi]);
        cpa16(qbl + off, &g_Qpl[gi]);
    }

    auto load_stage = [&](int st, int c) {
        int k0 = c * 32;
        uint32_t s = stb + st * F2_STAGE;
        {
            int row = tid >> 3, sg = tid & 7;
            size_t gi = (size_t)(b*SS + k0 + row) * 1024 + h*64 + sg * 8;
            uint32_t off = SWZ128((uint32_t)(row * 128 + sg * 16));
            cpa16(s + off, &g_Kph[gi]);
            cpa16(s + F2_KTILE + off, &g_Kpl[gi]);
        }
        {
            int row = tid >> 2, sg = tid & 3;
            size_t gi = ((size_t)bh*64 + row) * SS + k0 + sg * 8;
            uint32_t off = swz_off(row, sg);
            cpa16(s + 2*F2_KTILE + off, &g_Vrth[gi]);
            cpa16(s + 2*F2_KTILE + F2_VTILE + off, &g_Vrtl[gi]);
        }
    };

    load_stage(0, 0); CPA_COMMIT();
    load_stage(1, 1); CPA_COMMIT();
    load_stage(2, 2); CPA_COMMIT();

    float oacc[8][4];
#pragma unroll
    for (int i = 0; i < 8; i++)
#pragma unroll
        for (int j = 0; j < 4; j++) oacc[i][j] = 0.f;

    const int r_ = lane >> 2, t2 = (lane & 3) * 2;
    const int qrow = q0 + warp*16 + r_;

#pragma unroll 1
    for (int c = 0; c < nch; c++) {
        CPA_WAIT2();
        __syncthreads();
        if (c + 3 < nch) load_stage((c + 3) & 3, c + 3);
        CPA_COMMIT();
        uint32_t s = stb + (c & 3) * F2_STAGE;
        int k0 = c * 32;

        float sacc[4][4];
#pragma unroll
        for (int i = 0; i < 4; i++)
#pragma unroll
            for (int j = 0; j < 4; j++) sacc[i][j] = 0.f;

#pragma unroll
        for (int kk = 0; kk < 4; kk++) {
            uint32_t aqh[4], aql[4];
            uint32_t arow = (uint32_t)(warp*16 + (lane & 15));
            uint32_t aoff = SWZ128(arow * 128 + (uint32_t)(kk*32 + (lane >> 4) * 16));
            LDSM4(aqh, qbh + aoff);
            LDSM4(aql, qbl + aoff);
            uint32_t bh2[4][2], bl2[4][2];
            uint32_t brow = (uint32_t)((lane & 7) + ((lane >> 4) << 3));
            uint32_t bcol = (uint32_t)(kk*32 + ((lane >> 3) & 1) * 16);
            {
                uint32_t t0[4], t1[4];
                LDSM4(t0, s + SWZ128(brow * 128 + bcol));
                LDSM4(t1, s + SWZ128((brow + 16) * 128 + bcol));
                bh2[0][0]=t0[0]; bh2[0][1]=t0[1]; bh2[1][0]=t0[2]; bh2[1][1]=t0[3];
                bh2[2][0]=t1[0]; bh2[2][1]=t1[1]; bh2[3][0]=t1[2]; bh2[3][1]=t1[3];
                LDSM4(t0, s + F2_KTILE + SWZ128(brow * 128 + bcol));
                LDSM4(t1, s + F2_KTILE + SWZ128((brow + 16) * 128 + bcol));
                bl2[0][0]=t0[0]; bl2[0][1]=t0[1]; bl2[1][0]=t0[2]; bl2[1][1]=t0[3];
                bl2[2][0]=t1[0]; bl2[2][1]=t1[1]; bl2[3][0]=t1[2]; bl2[3][1]=t1[3];
            }
#pragma unroll
            for (int nt = 0; nt < 4; nt++) {
                MMA16816(sacc[nt], aqh, bh2[nt][0], bh2[nt][1]);
                MMA16816(sacc[nt], aqh, bl2[nt][0], bl2[nt][1]);
                MMA16816(sacc[nt], aql, bh2[nt][0], bh2[nt][1]);
            }
        }

        uint32_t pah[2][4], pal[2][4];
        const bool needmask = (k0 + 32 > q0 + warp*16);
#pragma unroll
        for (int nf = 0; nf < 4; nf++) {
            int kc = k0 + nf*8 + t2;
            float e0 = __expf(sacc[nf][0]);
            float e1 = __expf(sacc[nf][1]);
            float e2 = __expf(sacc[nf][2]);
            float e3 = __expf(sacc[nf][3]);
            if (needmask) {
                if (kc     > qrow)     e0 = 0.f;
                if (kc + 1 > qrow)     e1 = 0.f;
                if (kc     > qrow + 8) e2 = 0.f;
                if (kc + 1 > qrow + 8) e3 = 0.f;
            }
            float h0 = __bfloat162float(__float2bfloat16(e0));
            float h1 = __bfloat162float(__float2bfloat16(e1));
            float h2 = __bfloat162float(__float2bfloat16(e2));
            float h3 = __bfloat162float(__float2bfloat16(e3));
            int kk2 = nf >> 1;
            int ro  = (nf & 1) * 2;
            pah[kk2][ro+0] = pack_bf2(h0, h1);
            pah[kk2][ro+1] = pack_bf2(h2, h3);
            pal[kk2][ro+0] = pack_bf2(e0 - h0, e1 - h1);
            pal[kk2][ro+1] = pack_bf2(e2 - h2, e3 - h3);
        }

#pragma unroll
        for (int kk2 = 0; kk2 < 2; kk2++) {
            int brow = (lane & 7) + ((lane >> 4) << 3);
            int bc = kk2*2 + ((lane >> 3) & 1);
#pragma unroll
            for (int g = 0; g < 4; g++) {
                uint32_t th[4], tl[4];
                LDSM4(th, s + 2*F2_KTILE + swz_off(brow + g*16, bc));
                LDSM4(tl, s + 2*F2_KTILE + F2_VTILE + swz_off(brow + g*16, bc));
                MMA16816(oacc[2*g],   pah[kk2], th[0], th[1]);
                MMA16816(oacc[2*g],   pah[kk2], tl[0], tl[1]);
                MMA16816(oacc[2*g],   pal[kk2], th[0], th[1]);
                MMA16816(oacc[2*g+1], pah[kk2], th[2], th[3]);
                MMA16816(oacc[2*g+1], pah[kk2], tl[2], tl[3]);
                MMA16816(oacc[2*g+1], pal[kk2], th[2], th[3]);
            }
        }
    }

    // epilogue: write attO as f16 hi/lo (feeds f16 2-product O GEMM)
#pragma unroll
    for (int nt = 0; nt < 8; nt++) {
        int d = nt*8 + t2;
        float v00 = oacc[nt][0], v01 = oacc[nt][1];
        float v10 = oacc[nt][2], v11 = oacc[nt][3];
        size_t i0 = (size_t)(b*SS + qrow) * HDIM + h*64 + d;
        size_t i1 = (size_t)(b*SS + qrow + 8) * HDIM + h*64 + d;
        __half h00 = __float2half_rn(v00), h01 = __float2half_rn(v01);
        __half h10 = __float2half_rn(v10), h11 = __float2half_rn(v11);
        __half2 hp0 = {h00, h01}, hp1 = {h10, h11};
        __half2 lp0 = {__float2half_rn(v00 - __half2float(h00)),
                       __float2half_rn(v01 - __half2float(h01))};
        __half2 lp1 = {__float2half_rn(v10 - __half2float(h10)),
                       __float2half_rn(v11 - __half2float(h11))};
        *(__half2*)&g_aoh[i0] = hp0;  *(__half2*)&g_aol[i0] = lp0;
        *(__half2*)&g_aoh[i1] = hp1;  *(__half2*)&g_aol[i1] = lp1;
    }
}

// ------------------- launch ------------------------------------------------------
extern "C" void kernel_launch(void* const* d_in, const int* in_sizes, int n_in,
                              void* d_out, int out_size)
{
    const float* queries = (const float*)d_in[0];
    const float* keys    = (const float*)d_in[1];
    const float* values  = (const float*)d_in[2];
    const float* Wq_w = (const float*)d_in[3];  const float* Wq_b = (const float*)d_in[4];
    const float* Wk_w = (const float*)d_in[5];  const float* Wk_b = (const float*)d_in[6];
    const float* Wv_w = (const float*)d_in[7];  const float* Wv_b = (const float*)d_in[8];
    const float* Aq_w = (const float*)d_in[9];  const float* Aq_b = (const float*)d_in[10];
    const float* Bq_w = (const float*)d_in[11]; const float* Bq_b = (const float*)d_in[12];
    const float* Ak_w = (const float*)d_in[13]; const float* Ak_b = (const float*)d_in[14];
    const float* Bk_w = (const float*)d_in[15]; const float* Bk_b = (const float*)d_in[16];
    const float* Av_w = (const float*)d_in[17]; const float* Av_b = (const float*)d_in[18];
    const float* Bv_w = (const float*)d_in[19]; const float* Bv_b = (const float*)d_in[20];
    const float* Wo_w = (const float*)d_in[21]; const float* Wo_b = (const float*)d_in[22];
    float* out = (float*)d_out;

    cudaFuncSetAttribute(gemm_mma, cudaFuncAttributeMaxDynamicSharedMemorySize, GEMM_SMEM);
    cudaFuncSetAttribute(attn1_mma, cudaFuncAttributeMaxDynamicSharedMemorySize, A1_SMEM);
    cudaFuncSetAttribute(attn2_mma, cudaFuncAttributeMaxDynamicSharedMemorySize, F2_SMEM);

    void *pbeq, *pbek, *pbev, *pV, *pcs, *pKA;
    void *pqh, *pql, *pkh, *pkl, *pvh, *pvl, *paoh, *paol;
    void *pQph, *pQpl, *pKph, *pKpl;
    void *pwqh, *pwql, *pwkh, *pwkl, *pwvh, *pwvl, *pwoh, *pwol;
    cudaGetSymbolAddress(&pbeq, g_beq); cudaGetSymbolAddress(&pbek, g_bek);
    cudaGetSymbolAddress(&pbev, g_bev); cudaGetSymbolAddress(&pV, g_V);
    cudaGetSymbolAddress(&pcs, g_colsum); cudaGetSymbolAddress(&pKA, g_KA);
    cudaGetSymbolAddress(&pqh, g_qh); cudaGetSymbolAddress(&pql, g_ql);
    cudaGetSymbolAddress(&pkh, g_kh); cudaGetSymbolAddress(&pkl, g_kl);
    cudaGetSymbolAddress(&pvh, g_vh); cudaGetSymbolAddress(&pvl, g_vl);
    cudaGetSymbolAddress(&paoh, g_aoh); cudaGetSymbolAddress(&paol, g_aol);
    cudaGetSymbolAddress(&pQph, g_Qph); cudaGetSymbolAddress(&pQpl, g_Qpl);
    cudaGetSymbolAddress(&pKph, g_Kph); cudaGetSymbolAddress(&pKpl, g_Kpl);
    cudaGetSymbolAddress(&pwqh, g_wqh); cudaGetSymbolAddress(&pwql, g_wql);
    cudaGetSymbolAddress(&pwkh, g_wkh); cudaGetSymbolAddress(&pwkl, g_wkl);
    cudaGetSymbolAddress(&pwvh, g_wvh); cudaGetSymbolAddress(&pwvl, g_wvl);
    cudaGetSymbolAddress(&pwoh, g_woh); cudaGetSymbolAddress(&pwol, g_wol);

    ActArgs aa;
    aa.X[0] = queries; aa.X[1] = keys; aa.X[2] = values;
    aa.hi[0] = (__nv_bfloat16*)pqh; aa.hi[1] = (__nv_bfloat16*)pkh; aa.hi[2] = (__nv_bfloat16*)pvh;
    aa.lo[0] = (__nv_bfloat16*)pql; aa.lo[1] = (__nv_bfloat16*)pkl; aa.lo[2] = (__nv_bfloat16*)pvl;

    WprepArgs wa;
    wa.W[0] = Wq_w; wa.W[1] = Wk_w; wa.W[2] = Wv_w; wa.W[3] = Wo_w;
    wa.A[0] = Aq_w; wa.A[1] = Ak_w; wa.A[2] = nullptr; wa.A[3] = nullptr;
    wa.Bw[0] = Bq_w; wa.Bw[1] = Bk_w; wa.Bw[2] = nullptr; wa.Bw[3] = nullptr;
    wa.hi[0] = (__nv_bfloat16*)pwqh; wa.hi[1] = (__nv_bfloat16*)pwkh;
    wa.hi[2] = (__nv_bfloat16*)pwvh; wa.hi[3] = (__nv_bfloat16*)pwoh;
    wa.lo[0] = (__nv_bfloat16*)pwql; wa.lo[1] = (__nv_bfloat16*)pwkl;
    wa.lo[2] = (__nv_bfloat16*)pwvl; wa.lo[3] = (__nv_bfloat16*)pwol;

    BeffArgs ba;
    ba.Wb[0] = Wq_b; ba.Wb[1] = Wk_b; ba.Wb[2] = Wv_b;
    ba.Ab[0] = Aq_b; ba.Ab[1] = Ak_b; ba.Ab[2] = Av_b;
    ba.Bw[0] = Bq_w; ba.Bw[1] = Bk_w; ba.Bw[2] = Bv_w;
    ba.Bb[0] = Bq_b; ba.Bb[1] = Bk_b; ba.Bb[2] = Bv_b;
    ba.out[0] = (float*)pbeq; ba.out[1] = (float*)pbek; ba.out[2] = (float*)pbev;

    GemmArgs ga;
    ga.Ah[0] = (const __nv_bfloat16*)pqh;  ga.Al[0] = (const __nv_bfloat16*)pql;
    ga.Ah[1] = (const __nv_bfloat16*)pkh;  ga.Al[1] = (const __nv_bfloat16*)pkl;
    ga.Ah[2] = (const __nv_bfloat16*)pvh;  ga.Al[2] = (const __nv_bfloat16*)pvl;
    ga.Ah[3] = (const __nv_bfloat16*)paoh; ga.Al[3] = (const __nv_bfloat16*)paol;
    ga.Bh[0] = (const __nv_bfloat16*)pwqh; ga.Bl[0] = (const __nv_bfloat16*)pwql;
    ga.Bh[1] = (const __nv_bfloat16*)pwkh; ga.Bl[1] = (const __nv_bfloat16*)pwkl;
    ga.Bh[2] = (const __nv_bfloat16*)pwvh; ga.Bl[2] = (const __nv_bfloat16*)pwvl;
    ga.Bh[3] = (const __nv_bfloat16*)pwoh; ga.Bl[3] = (const __nv_bfloat16*)pwol;
    ga.bias[0] = (const float*)pbeq; ga.bias[1] = (const float*)pbek;
    ga.bias[2] = (const float*)pbev; ga.bias[3] = Wo_b;
    ga.outF[0] = nullptr; ga.outF[1] = nullptr; ga.outF[2] = (float*)pV; ga.outF[3] = out;
    ga.outH[0] = (__nv_bfloat16*)pQph; ga.outL[0] = (__nv_bfloat16*)pQpl;
    ga.outH[1] = (__nv_bfloat16*)pKph; ga.outL[1] = (__nv_bfloat16*)pKpl;
    ga.outH[2] = nullptr; ga.outL[2] = nullptr;
    ga.outH[3] = nullptr; ga.outL[3] = nullptr;
    ga.loraKA = (const float*)pKA; ga.loraB = Bv_w;

    actconv_kernel<<<dim3((TOK*DMODEL/4)/256, 1, 3), 256>>>(aa);          // 0
    wprep_kernel<<<dim3(DMODEL/32, HDIM/32, 4), 256>>>(wa);               // 1
    beff_kernel<<<dim3(HDIM/256, 1, 3), 256>>>(ba);                       // 2
    ka_kernel<<<TOK/8, 256>>>(keys, Av_w, (float*)pKA);                   // 3
    zero_kernel<<<(BB*NH*SS)/256, 256>>>((float*)pcs);                    // 4
    gemm_mma<<<dim3(HDIM/128, TOK/128, 3), 256, GEMM_SMEM>>>(ga, 0);      // 5: QKV fused
    attn1_mma<<<dim3(136, BB*NH), 256, A1_SMEM>>>();                      // 6
    vrt_kernel<<<dim3(SS/32, 2, BB*NH), 256>>>();                         // 7
    attn2_mma<<<dim3(16, BB*NH), 256, F2_SMEM>>>();                       // 8
    gemm_mma<<<dim3(HDIM/128, TOK/128, 1), 256, GEMM_SMEM>>>(ga, 3);      // 9: O
}

// round 15
// speedup vs baseline: 1.0649x; 1.0012x over previous
#include <cuda_runtime.h>
#include <cuda_bf16.h>
#include <cuda_fp16.h>
#include <math.h>
#include <stdint.h>

#define BB     4
#define SS     2048
#define DMODEL 1024
#define NH     16
#define HD     64
#define HDIM   1024
#define RK     8
#define TOK    (BB*SS)   // 8192

// ------------------- device scratch (static; allocation-free) -------------------
__device__ float g_beq[HDIM];
__device__ float g_bek[HDIM];
__device__ float g_bev[HDIM];
__device__ float g_V[(size_t)TOK*HDIM];
__device__ float g_colsum[(size_t)BB*NH*SS];
__device__ float g_KA[(size_t)TOK*RK];

// 16-bit buffers; z<2 hold bf16 hi/lo, z>=2 hold f16 hi/lo (reinterpreted)
__device__ __nv_bfloat16 g_qh[(size_t)TOK*DMODEL], g_ql[(size_t)TOK*DMODEL];
__device__ __nv_bfloat16 g_kh[(size_t)TOK*DMODEL], g_kl[(size_t)TOK*DMODEL];
__device__ __nv_bfloat16 g_vh[(size_t)TOK*DMODEL], g_vl[(size_t)TOK*DMODEL];   // f16
__device__ __nv_bfloat16 g_Qph[(size_t)TOK*HDIM], g_Qpl[(size_t)TOK*HDIM];
__device__ __nv_bfloat16 g_Kph[(size_t)TOK*HDIM], g_Kpl[(size_t)TOK*HDIM];
__device__ __nv_bfloat16 g_aoh[(size_t)TOK*HDIM], g_aol[(size_t)TOK*HDIM];     // f16
__device__ __nv_bfloat16 g_Vrth[(size_t)BB*NH*64*SS];
__device__ __nv_bfloat16 g_Vrtl[(size_t)BB*NH*64*SS];
__device__ __nv_bfloat16 g_wqh[DMODEL*HDIM], g_wql[DMODEL*HDIM];
__device__ __nv_bfloat16 g_wkh[DMODEL*HDIM], g_wkl[DMODEL*HDIM];
__device__ __nv_bfloat16 g_wvh[DMODEL*HDIM], g_wvl[DMODEL*HDIM];               // f16
__device__ __nv_bfloat16 g_woh[DMODEL*HDIM], g_wol[DMODEL*HDIM];               // f16

// ------------------- helpers ------------------------------------------------------
__device__ __forceinline__ uint32_t smem_u32(const void* p) {
    uint32_t a;
    asm("{ .reg .u64 t; cvta.to.shared.u64 t, %1; cvt.u32.u64 %0, t; }" : "=r"(a) : "l"(p));
    return a;
}
__device__ __forceinline__ void cpa16(uint32_t dst, const void* src) {
    asm volatile("cp.async.cg.shared.global [%0], [%1], 16;"
                 :: "r"(dst), "l"(__cvta_generic_to_global(src)));
}
#define CPA_COMMIT() asm volatile("cp.async.commit_group;")
#define CPA_WAIT2()  asm volatile("cp.async.wait_group 2;")
#define CPA_WAIT1()  asm volatile("cp.async.wait_group 1;")
#define CPA_WAIT0()  asm volatile("cp.async.wait_group 0;")

#define LDSM4(r, a) \
    asm volatile("ldmatrix.sync.aligned.m8n8.x4.shared.b16 {%0,%1,%2,%3}, [%4];" \
        : "=r"((r)[0]), "=r"((r)[1]), "=r"((r)[2]), "=r"((r)[3]) : "r"(a))

#define MMA16816(c, a, b0, b1) \
    asm volatile("mma.sync.aligned.m16n8k16.row.col.f32.bf16.bf16.f32 " \
        "{%0,%1,%2,%3}, {%4,%5,%6,%7}, {%8,%9}, {%0,%1,%2,%3};" \
        : "+f"((c)[0]), "+f"((c)[1]), "+f"((c)[2]), "+f"((c)[3]) \
        : "r"((a)[0]), "r"((a)[1]), "r"((a)[2]), "r"((a)[3]), "r"(b0), "r"(b1))

#define MMAF16(c, a, b0, b1) \
    asm volatile("mma.sync.aligned.m16n8k16.row.col.f32.f16.f16.f32 " \
        "{%0,%1,%2,%3}, {%4,%5,%6,%7}, {%8,%9}, {%0,%1,%2,%3};" \
        : "+f"((c)[0]), "+f"((c)[1]), "+f"((c)[2]), "+f"((c)[3]) \
        : "r"((a)[0]), "r"((a)[1]), "r"((a)[2]), "r"((a)[3]), "r"(b0), "r"(b1))

__device__ __forceinline__ uint32_t pack_bf2(float lo, float hi) {
    __nv_bfloat162 p = {__float2bfloat16(lo), __float2bfloat16(hi)};
    return *(uint32_t*)&p;
}
// single-instruction bf16x2 pack (rn): lo -> low half, hi -> high half
__device__ __forceinline__ uint32_t cvt_bf2(float lo, float hi) {
    uint32_t r;
    asm("cvt.rn.bf16x2.f32 %0, %1, %2;" : "=r"(r) : "f"(hi), "f"(lo));
    return r;
}

#define SWZ128(x) ((x) ^ (((x) >> 3) & 0x70))
__device__ __forceinline__ uint32_t swz_off(int row, int chunk) {
    uint32_t o = (uint32_t)((row >> 1) * 128 + (row & 1) * 64 + chunk * 16);
    return SWZ128(o);
}

// ------------------- fused prep kernels -------------------------------------------
struct ActArgs { const float* X[3]; __nv_bfloat16 *hi[3], *lo[3]; };
__global__ void actconv_kernel(ActArgs aa)
{
    int z = blockIdx.z;
    const float* X = aa.X[z];
    size_t i = ((size_t)blockIdx.x * 256 + threadIdx.x) * 4;
    float4 v = *(const float4*)&X[i];
    if (z < 2) {
        __nv_bfloat16* hi = aa.hi[z];
        __nv_bfloat16* lo = aa.lo[z];
        __nv_bfloat16 h0 = __float2bfloat16(v.x), h1 = __float2bfloat16(v.y);
        __nv_bfloat16 h2 = __float2bfloat16(v.z), h3 = __float2bfloat16(v.w);
        __nv_bfloat162 ph0 = {h0, h1}, ph1 = {h2, h3};
        __nv_bfloat162 pl0 = {__float2bfloat16(v.x - __bfloat162float(h0)),
                              __float2bfloat16(v.y - __bfloat162float(h1))};
        __nv_bfloat162 pl1 = {__float2bfloat16(v.z - __bfloat162float(h2)),
                              __float2bfloat16(v.w - __bfloat162float(h3))};
        *(__nv_bfloat162*)&hi[i]   = ph0;  *(__nv_bfloat162*)&hi[i+2] = ph1;
        *(__nv_bfloat162*)&lo[i]   = pl0;  *(__nv_bfloat162*)&lo[i+2] = pl1;
    } else {
        __half* hi = (__half*)aa.hi[z];
        __half* lo = (__half*)aa.lo[z];
        __half h0 = __float2half_rn(v.x), h1 = __float2half_rn(v.y);
        __half h2 = __float2half_rn(v.z), h3 = __float2half_rn(v.w);
        __half2 ph0 = {h0, h1}, ph1 = {h2, h3};
        __half2 pl0 = {__float2half_rn(v.x - __half2float(h0)),
                       __float2half_rn(v.y - __half2float(h1))};
        __half2 pl1 = {__float2half_rn(v.z - __half2float(h2)),
                       __float2half_rn(v.w - __half2float(h3))};
        *(__half2*)&hi[i]   = ph0;  *(__half2*)&hi[i+2] = ph1;
        *(__half2*)&lo[i]   = pl0;  *(__half2*)&lo[i+2] = pl1;
    }
}

struct WprepArgs { const float *W[4], *A[4], *Bw[4]; __nv_bfloat16 *hi[4], *lo[4]; };
__global__ __launch_bounds__(256) void wprep_kernel(WprepArgs wa)
{
    __shared__ float t[32][33];
    int z = blockIdx.z;
    const float* W = wa.W[z];
    const float* A = wa.A[z];
    const float* Bw = wa.Bw[z];
    int kb = blockIdx.x * 32, nb = blockIdx.y * 32;
    int x = threadIdx.x & 31, y = threadIdx.x >> 5;
#pragma unroll
    for (int i = y; i < 32; i += 8) {
        int k = kb + i, n = nb + x;
        float v = W[(size_t)k*HDIM + n];
        if (A) {
#pragma unroll
            for (int r = 0; r < RK; r++) v += A[k*RK + r] * Bw[r*HDIM + n];
        }
        t[i][x] = v;
    }
    __syncthreads();
    if (z < 2) {
        __nv_bfloat16* hi = wa.hi[z];
        __nv_bfloat16* lo = wa.lo[z];
#pragma unroll
        for (int i = y; i < 32; i += 8) {
            int n = nb + i, k = kb + x;
            float v = t[x][i];
            __nv_bfloat16 h = __float2bfloat16(v);
            hi[(size_t)n*DMODEL + k] = h;
            lo[(size_t)n*DMODEL + k] = __float2bfloat16(v - __bfloat162float(h));
        }
    } else {
        __half* hi = (__half*)wa.hi[z];
        __half* lo = (__half*)wa.lo[z];
#pragma unroll
        for (int i = y; i < 32; i += 8) {
            int n = nb + i, k = kb + x;
            float v = t[x][i];
            __half h = __float2half_rn(v);
            hi[(size_t)n*DMODEL + k] = h;
            lo[(size_t)n*DMODEL + k] = __float2half_rn(v - __half2float(h));
        }
    }
}

struct BeffArgs { const float *Wb[3], *Ab[3], *Bw[3], *Bb[3]; float* out[3]; };
__global__ void beff_kernel(BeffArgs ba)
{
    int z = blockIdx.z;
    int j = blockIdx.x * 256 + threadIdx.x;
    float acc = ba.Wb[z][j] + ba.Bb[z][j];
    const float* Ab = ba.Ab[z];
    const float* Bw = ba.Bw[z];
#pragma unroll
    for (int r = 0; r < RK; r++) acc += Ab[r] * Bw[r*HDIM + j];
    ba.out[z][j] = acc;
}

__global__ void zero_kernel(float* p) { p[blockIdx.x * 256 + threadIdx.x] = 0.f; }

__global__ __launch_bounds__(256) void ka_kernel(const float* __restrict__ keys,
                                                 const float* __restrict__ Av,
                                                 float* __restrict__ KA)
{
    __shared__ float avT[RK][DMODEL];
    int tid = threadIdx.x;
#pragma unroll
    for (int f = tid; f < DMODEL*RK/4; f += 256) {
        int k = f >> 1, j = (f & 1) * 4;
        float4 v = ((const float4*)Av)[f];
        avT[j+0][k] = v.x; avT[j+1][k] = v.y;
        avT[j+2][k] = v.z; avT[j+3][k] = v.w;
    }
    __syncthreads();

    int warp = tid >> 5, lane = tid & 31;
    int row = blockIdx.x * 8 + warp;
    const float4* kr = (const float4*)(keys + (size_t)row * DMODEL);
    float acc[RK];
#pragma unroll
    for (int r = 0; r < RK; r++) acc[r] = 0.f;
#pragma unroll
    for (int i = 0; i < 8; i++) {
        int k4 = lane + i * 32;
        float4 kv = kr[k4];
        int k = 4 * k4;
#pragma unroll
        for (int r = 0; r < RK; r++) {
            float4 av = *(const float4*)&avT[r][k];
            acc[r] += kv.x*av.x + kv.y*av.y + kv.z*av.z + kv.w*av.w;
        }
    }
#pragma unroll
    for (int r = 0; r < RK; r++) {
#pragma unroll
        for (int off = 16; off > 0; off >>= 1)
            acc[r] += __shfl_down_sync(0xffffffffu, acc[r], off);
    }
    if (lane == 0) {
#pragma unroll
        for (int r = 0; r < RK; r++) KA[(size_t)row*RK + r] = acc[r];
    }
}

// ------------------- fused mma.sync GEMM: bf16 3-prod (z<2) / f16 2-prod (z>=2) ---
static constexpr int G_TILE  = 8192;
static constexpr int G_STAGE = 4 * G_TILE;
static constexpr int GEMM_SMEM = 3 * G_STAGE;    // 98304

struct GemmArgs {
    const __nv_bfloat16 *Ah[4], *Al[4], *Bh[4], *Bl[4];
    const float* bias[4];
    float* outF[4];
    __nv_bfloat16 *outH[4], *outL[4];
    const float *loraKA, *loraB;
};

__global__ __launch_bounds__(256, 2)
void gemm_mma(GemmArgs ga, int op)
{
    extern __shared__ char smem[];
    const uint32_t sb = smem_u32(smem);
    const int z = (op == 0) ? blockIdx.z : op;
    const bool F16 = (z >= 2);
    const __nv_bfloat16* Ah = ga.Ah[z];
    const __nv_bfloat16* Al = ga.Al[z];
    const __nv_bfloat16* Bh = ga.Bh[z];
    const __nv_bfloat16* Bl = ga.Bl[z];
    const float* bias = ga.bias[z];
    float* outF = ga.outF[z];
    __nv_bfloat16* outH = ga.outH[z];
    __nv_bfloat16* outL = ga.outL[z];
    const float* loraKA = (z == 2) ? ga.loraKA : nullptr;
    const float* loraB  = ga.loraB;

    const int tid  = threadIdx.x;
    const int lane = tid & 31;
    const int warp = tid >> 5;
    const int wm = warp >> 2, wn = warp & 3;
    const int m0 = blockIdx.y * 128, n0 = blockIdx.x * 128;

    float acc[4][4][4];
#pragma unroll
    for (int i = 0; i < 4; i++)
#pragma unroll
        for (int j = 0; j < 4; j++)
#pragma unroll
            for (int k = 0; k < 4; k++) acc[i][j][k] = 0.f;

    auto load_stage = [&](int st, int chunk) {
        int k0 = chunk * 32;
        const __nv_bfloat16* tp[4] = {Ah, Al, Bh, Bl};
        uint32_t sbase = sb + st * G_STAGE;
#pragma unroll
        for (int i = 0; i < 8; i++) {
            const int t = i >> 1;
            if (F16 && t == 3) continue;
            int j = (i & 1) ? tid + 256 : tid;
            int row = j >> 2, sg = j & 3;
            int r0 = (t < 2) ? m0 : n0;
            cpa16(sbase + t * G_TILE + swz_off(row, sg),
                  tp[t] + (size_t)(r0 + row) * 1024 + k0 + sg * 8);
        }
    };

    auto compute_stage = [&](int st) {
        uint32_t ab = sb + st * G_STAGE;
#pragma unroll
        for (int kk = 0; kk < 2; kk++) {
            uint32_t ahr[4][4], alr[4][4], bh2[4][2], bl2[4][2];
            int arow = wm*64 + (lane & 15);
            int ac   = kk*2 + (lane >> 4);
            uint32_t abase = ab + swz_off(arow, ac);
#pragma unroll
            for (int mt = 0; mt < 4; mt++) {
                LDSM4(ahr[mt], abase + mt * 1024);
                LDSM4(alr[mt], abase + G_TILE + mt * 1024);
            }
            int brow = wn*32 + (lane & 7) + ((lane >> 4) << 3);
            int bc   = kk*2 + ((lane >> 3) & 1);
            uint32_t bbase = ab + 2*G_TILE + swz_off(brow, bc);
            {
                uint32_t t0[4], t1[4];
                LDSM4(t0, bbase);
                LDSM4(t1, bbase + 1024);
                bh2[0][0]=t0[0]; bh2[0][1]=t0[1]; bh2[1][0]=t0[2]; bh2[1][1]=t0[3];
                bh2[2][0]=t1[0]; bh2[2][1]=t1[1]; bh2[3][0]=t1[2]; bh2[3][1]=t1[3];
                if (!F16) {
                    LDSM4(t0, bbase + G_TILE);
                    LDSM4(t1, bbase + G_TILE + 1024);
                    bl2[0][0]=t0[0]; bl2[0][1]=t0[1]; bl2[1][0]=t0[2]; bl2[1][1]=t0[3];
                    bl2[2][0]=t1[0]; bl2[2][1]=t1[1]; bl2[3][0]=t1[2]; bl2[3][1]=t1[3];
                }
            }
            if (!F16) {
#pragma unroll
                for (int mt = 0; mt < 4; mt++)
#pragma unroll
                    for (int nt = 0; nt < 4; nt++) {
                        MMA16816(acc[mt][nt], ahr[mt], bh2[nt][0], bh2[nt][1]);
                        MMA16816(acc[mt][nt], ahr[mt], bl2[nt][0], bl2[nt][1]);
                        MMA16816(acc[mt][nt], alr[mt], bh2[nt][0], bh2[nt][1]);
                    }
            } else {
#pragma unroll
                for (int mt = 0; mt < 4; mt++)
#pragma unroll
                    for (int nt = 0; nt < 4; nt++) {
                        MMAF16(acc[mt][nt], ahr[mt], bh2[nt][0], bh2[nt][1]);
                        MMAF16(acc[mt][nt], alr[mt], bh2[nt][0], bh2[nt][1]);
                    }
            }
        }
    };

    load_stage(0, 0);
    CPA_COMMIT();
    load_stage(1, 1);
    CPA_COMMIT();

#pragma unroll 1
    for (int c = 0; c < 32; c++) {
        CPA_WAIT1();
        __syncthreads();
        if (c + 2 < 32) load_stage((c + 2) % 3, c + 2);
        CPA_COMMIT();
        compute_stage(c % 3);
    }

    int r_ = lane >> 2, c_ = (lane & 3) * 2;
#pragma unroll
    for (int mt = 0; mt < 4; mt++) {
        int row = m0 + wm*64 + mt*16 + r_;
        float ka0[RK], ka1[RK];
        if (loraKA) {
#pragma unroll
            for (int r = 0; r < RK; r++) {
                ka0[r] = loraKA[(size_t)row*RK + r];
                ka1[r] = loraKA[(size_t)(row+8)*RK + r];
            }
        }
#pragma unroll
        for (int nt = 0; nt < 4; nt++) {
            int col = n0 + wn*32 + nt*8 + c_;
            float b0 = bias[col], b1 = bias[col + 1];
            float v00 = acc[mt][nt][0] + b0, v01 = acc[mt][nt][1] + b1;
            float v10 = acc[mt][nt][2] + b0, v11 = acc[mt][nt][3] + b1;
            if (loraKA) {
#pragma unroll
                for (int r = 0; r < RK; r++) {
                    float w0 = loraB[r*HDIM + col], w1 = loraB[r*HDIM + col + 1];
                    v00 += ka0[r] * w0;  v01 += ka0[r] * w1;
                    v10 += ka1[r] * w0;  v11 += ka1[r] * w1;
                }
            }
            if (outF) {
                *(float2*)&outF[(size_t)row * 1024 + col] = {v00, v01};
                *(float2*)&outF[(size_t)(row + 8) * 1024 + col] = {v10, v11};
            } else {
                __nv_bfloat16 h00 = __float2bfloat16(v00), h01 = __float2bfloat16(v01);
                __nv_bfloat16 h10 = __float2bfloat16(v10), h11 = __float2bfloat16(v11);
                __nv_bfloat162 hp0 = {h00, h01}, hp1 = {h10, h11};
                __nv_bfloat162 lp0 = {__float2bfloat16(v00 - __bfloat162float(h00)),
                                      __float2bfloat16(v01 - __bfloat162float(h01))};
                __nv_bfloat162 lp1 = {__float2bfloat16(v10 - __bfloat162float(h10)),
                                      __float2bfloat16(v11 - __bfloat162float(h11))};
                *(__nv_bfloat162*)&outH[(size_t)row * 1024 + col] = hp0;
                *(__nv_bfloat162*)&outH[(size_t)(row + 8) * 1024 + col] = hp1;
                *(__nv_bfloat162*)&outL[(size_t)row * 1024 + col] = lp0;
                *(__nv_bfloat162*)&outL[(size_t)(row + 8) * 1024 + col] = lp1;
            }
        }
    }
}

// ------------------- pass 1 (slim): column sums of exp(QK^T) masked --------------
static constexpr int A1_PITCH = 144;
static constexpr int A1_TILE  = 128 * A1_PITCH;
static constexpr int A1_SMEM  = 4 * A1_TILE;

__global__ __launch_bounds__(256, 2) void attn1_mma()
{
    extern __shared__ char smem[];
    int idx = blockIdx.x;
    int qt = (int)((sqrtf(8.f*idx + 1.f) - 1.f) * 0.5f);
    if ((qt+1)*(qt+2)/2 <= idx) qt++;
    if (qt*(qt+1)/2 > idx) qt--;
    int kt = idx - qt*(qt+1)/2;
    int bh = blockIdx.y;
    const uint32_t sb = smem_u32(smem);
    int b = bh >> 4, h = bh & 15;
    int q0 = qt * 128, k0 = kt * 128;
    int tid = threadIdx.x, lane = tid & 31, warp = tid >> 5;
    int wm = warp >> 2, wn = warp & 3;

    {
        const __nv_bfloat16* tp[4] = {g_Qph, g_Qpl, g_Kph, g_Kpl};
#pragma unroll
        for (int t = 0; t < 4; t++) {
            int r0 = (t < 2) ? q0 : k0;
#pragma unroll
            for (int i = 0; i < 4; i++) {
                int ix = tid + i * 256;
                int row = ix >> 3, sg = ix & 7;
                cpa16(sb + t * A1_TILE + row * A1_PITCH + sg * 16,
                      tp[t] + (size_t)(b*SS + r0 + row) * 1024 + h*64 + sg * 8);
            }
        }
    }
    CPA_COMMIT(); CPA_WAIT0();
    __syncthreads();

    float acc[4][4][4];
#pragma unroll
    for (int i = 0; i < 4; i++)
#pragma unroll
        for (int j = 0; j < 4; j++)
#pragma unroll
            for (int k = 0; k < 4; k++) acc[i][j][k] = 0.f;

#pragma unroll
    for (int kk = 0; kk < 4; kk++) {
        uint32_t ahr[4][4], alr[4][4], bhf[4][2], blf[4][2];
        uint32_t aoff = (uint32_t)(wm*64 + (lane & 15)) * A1_PITCH
                      + (uint32_t)(kk*16 + (lane >> 4) * 8) * 2;
#pragma unroll
        for (int mt = 0; mt < 4; mt++) {
            LDSM4(ahr[mt], sb + aoff + mt * (16*A1_PITCH));
            LDSM4(alr[mt], sb + A1_TILE + aoff + mt * (16*A1_PITCH));
        }
        uint32_t boff = (uint32_t)(wn*32 + (lane & 7) + ((lane >> 4) << 3)) * A1_PITCH
                      + (uint32_t)(kk*16 + ((lane >> 3) & 1) * 8) * 2;
        {
            uint32_t t0[4], t1[4];
            LDSM4(t0, sb + 2*A1_TILE + boff);
            LDSM4(t1, sb + 2*A1_TILE + boff + 16*A1_PITCH);
            bhf[0][0]=t0[0]; bhf[0][1]=t0[1]; bhf[1][0]=t0[2]; bhf[1][1]=t0[3];
            bhf[2][0]=t1[0]; bhf[2][1]=t1[1]; bhf[3][0]=t1[2]; bhf[3][1]=t1[3];
            LDSM4(t0, sb + 3*A1_TILE + boff);
            LDSM4(t1, sb + 3*A1_TILE + boff + 16*A1_PITCH);
            blf[0][0]=t0[0]; blf[0][1]=t0[1]; blf[1][0]=t0[2]; blf[1][1]=t0[3];
            blf[2][0]=t1[0]; blf[2][1]=t1[1]; blf[3][0]=t1[2]; blf[3][1]=t1[3];
        }
#pragma unroll
        for (int mt = 0; mt < 4; mt++)
#pragma unroll
            for (int nt = 0; nt < 4; nt++) {
                MMA16816(acc[mt][nt], ahr[mt], bhf[nt][0], bhf[nt][1]);
                MMA16816(acc[mt][nt], ahr[mt], blf[nt][0], blf[nt][1]);
                MMA16816(acc[mt][nt], alr[mt], bhf[nt][0], bhf[nt][1]);
            }
    }

    __syncthreads();
    float* cs = (float*)smem;
    if (tid < 128) cs[tid] = 0.f;
    __syncthreads();

    const bool diag = (qt == kt);
    int r_ = lane >> 2, c_ = (lane & 3) * 2;
    float cs0[4] = {0,0,0,0}, cs1[4] = {0,0,0,0};
#pragma unroll
    for (int mt = 0; mt < 4; mt++) {
        int qb = q0 + wm*64 + mt*16;
#pragma unroll
        for (int nt = 0; nt < 4; nt++) {
            int k = k0 + wn*32 + nt*8 + c_;
            float e00 = __expf(acc[mt][nt][0]);
            float e01 = __expf(acc[mt][nt][1]);
            float e10 = __expf(acc[mt][nt][2]);
            float e11 = __expf(acc[mt][nt][3]);
            int qr0 = qb + r_, qr1 = qb + r_ + 8;
            if (diag) {
                if (qr0 < k)     e00 = 0.f;
                if (qr0 < k + 1) e01 = 0.f;
                if (qr1 < k)     e10 = 0.f;
                if (qr1 < k + 1) e11 = 0.f;
            }
            cs0[nt] += e00 + e10;
            cs1[nt] += e01 + e11;
        }
    }
#pragma unroll
    for (int nt = 0; nt < 4; nt++) {
        atomicAdd(&cs[wn*32 + nt*8 + c_],     cs0[nt]);
        atomicAdd(&cs[wn*32 + nt*8 + c_ + 1], cs1[nt]);
    }
    __syncthreads();
    if (tid < 128)
        atomicAdd(&g_colsum[(size_t)bh*SS + k0 + tid], cs[tid]);
}

// ------------------- Vrt prep: bf16 hi/lo ----------------------------------------
__global__ __launch_bounds__(256) void vrt_kernel()
{
    __shared__ float t[32][33];
    int kt = blockIdx.x, dt = blockIdx.y, bh = blockIdx.z;
    int b = bh >> 4, h = bh & 15;
    int k0 = kt * 32, d0 = dt * 32;
    int x = threadIdx.x & 31, y = threadIdx.x >> 5;
#pragma unroll
    for (int i = y; i < 32; i += 8) {
        int k = k0 + i;
        float r = 1.0f / (g_colsum[(size_t)bh*SS + k] * 8.0f);
        t[i][x] = g_V[(size_t)(b*SS + k) * HDIM + h*64 + d0 + x] * r;
    }
    __syncthreads();
#pragma unroll
    for (int i = y; i < 32; i += 8) {
        int d = d0 + i, k = k0 + x;
        float v = t[x][i];
        __nv_bfloat16 hh = __float2bfloat16(v);
        size_t idx = ((size_t)bh*64 + d) * SS + k;
        g_Vrth[idx] = hh;
        g_Vrtl[idx] = __float2bfloat16(v - __bfloat162float(hh));
    }
}

// ------------------- pass 2 (flash): recompute P = exp(QK^T), out = P @ Vrt^T ----
// Q fragments hoisted to registers (loaded once); bf16x2 packed P conversion.
static constexpr int F2_QTILE = 16384;
static constexpr int F2_KTILE = 4096;
static constexpr int F2_VTILE = 4096;
static constexpr int F2_STAGE = 2*F2_KTILE + 2*F2_VTILE;
static constexpr int F2_SMEM  = 2*F2_QTILE + 4*F2_STAGE;      // 98304

__global__ __launch_bounds__(256, 2) void attn2_mma()
{
    extern __shared__ char smem[];
    const uint32_t sb = smem_u32(smem);
    int qt = (int)gridDim.x - 1 - (int)blockIdx.x;
    int bh = blockIdx.y;
    int b = bh >> 4, h = bh & 15;
    int q0 = qt * 128;
    int tid = threadIdx.x, lane = tid & 31, warp = tid >> 5;
    int nch = (qt + 1) * 4;

    const uint32_t qbh = sb;
    const uint32_t qbl = sb + F2_QTILE;
    const uint32_t stb = sb + 2*F2_QTILE;

#pragma unroll
    for (int i = 0; i < 4; i++) {
        int ix = tid + i * 256;
        int row = ix >> 3, sg = ix & 7;
        size_t gi = (size_t)(b*SS + q0 + row) * 1024 + h*64 + sg * 8;
        uint32_t off = SWZ128((uint32_t)(row * 128 + sg * 16));
        cpa16(qbh + off, &g_Qph[gi]);
        cpa16(qbl + off, &g_Qpl[gi]);
    }

    auto load_stage = [&](int st, int c) {
        int k0 = c * 32;
        uint32_t s = stb + st * F2_STAGE;
        {
            int row = tid >> 3, sg = tid & 7;
            size_t gi = (size_t)(b*SS + k0 + row) * 1024 + h*64 + sg * 8;
            uint32_t off = SWZ128((uint32_t)(row * 128 + sg * 16));
            cpa16(s + off, &g_Kph[gi]);
            cpa16(s + F2_KTILE + off, &g_Kpl[gi]);
        }
        {
            int row = tid >> 2, sg = tid & 3;
            size_t gi = ((size_t)bh*64 + row) * SS + k0 + sg * 8;
            uint32_t off = swz_off(row, sg);
            cpa16(s + 2*F2_KTILE + off, &g_Vrth[gi]);
            cpa16(s + 2*F2_KTILE + F2_VTILE + off, &g_Vrtl[gi]);
        }
    };

    load_stage(0, 0); CPA_COMMIT();
    load_stage(1, 1); CPA_COMMIT();
    load_stage(2, 2); CPA_COMMIT();

    float oacc[8][4];
#pragma unroll
    for (int i = 0; i < 8; i++)
#pragma unroll
        for (int j = 0; j < 4; j++) oacc[i][j] = 0.f;

    const int r_ = lane >> 2, t2 = (lane & 3) * 2;
    const int qrow = q0 + warp*16 + r_;

    // Q fragments: loaded once after the Q/stage0 group completes
    uint32_t qfh[4][4], qfl[4][4];

#pragma unroll 1
    for (int c = 0; c < nch; c++) {
        CPA_WAIT2();
        __syncthreads();
        if (c == 0) {
#pragma unroll
            for (int kk = 0; kk < 4; kk++) {
                uint32_t arow = (uint32_t)(warp*16 + (lane & 15));
                uint32_t aoff = SWZ128(arow * 128 + (uint32_t)(kk*32 + (lane >> 4) * 16));
                LDSM4(qfh[kk], qbh + aoff);
                LDSM4(qfl[kk], qbl + aoff);
            }
        }
        if (c + 3 < nch) load_stage((c + 3) & 3, c + 3);
        CPA_COMMIT();
        uint32_t s = stb + (c & 3) * F2_STAGE;
        int k0 = c * 32;

        float sacc[4][4];
#pragma unroll
        for (int i = 0; i < 4; i++)
#pragma unroll
            for (int j = 0; j < 4; j++) sacc[i][j] = 0.f;

#pragma unroll
        for (int kk = 0; kk < 4; kk++) {
            uint32_t bh2[4][2], bl2[4][2];
            uint32_t brow = (uint32_t)((lane & 7) + ((lane >> 4) << 3));
            uint32_t bcol = (uint32_t)(kk*32 + ((lane >> 3) & 1) * 16);
            {
                uint32_t t0[4], t1[4];
                LDSM4(t0, s + SWZ128(brow * 128 + bcol));
                LDSM4(t1, s + SWZ128((brow + 16) * 128 + bcol));
                bh2[0][0]=t0[0]; bh2[0][1]=t0[1]; bh2[1][0]=t0[2]; bh2[1][1]=t0[3];
                bh2[2][0]=t1[0]; bh2[2][1]=t1[1]; bh2[3][0]=t1[2]; bh2[3][1]=t1[3];
                LDSM4(t0, s + F2_KTILE + SWZ128(brow * 128 + bcol));
                LDSM4(t1, s + F2_KTILE + SWZ128((brow + 16) * 128 + bcol));
                bl2[0][0]=t0[0]; bl2[0][1]=t0[1]; bl2[1][0]=t0[2]; bl2[1][1]=t0[3];
                bl2[2][0]=t1[0]; bl2[2][1]=t1[1]; bl2[3][0]=t1[2]; bl2[3][1]=t1[3];
            }
#pragma unroll
            for (int nt = 0; nt < 4; nt++) {
                MMA16816(sacc[nt], qfh[kk], bh2[nt][0], bh2[nt][1]);
                MMA16816(sacc[nt], qfh[kk], bl2[nt][0], bl2[nt][1]);
                MMA16816(sacc[nt], qfl[kk], bh2[nt][0], bh2[nt][1]);
            }
        }

        uint32_t pah[2][4], pal[2][4];
        const bool needmask = (k0 + 32 > q0 + warp*16);
#pragma unroll
        for (int nf = 0; nf < 4; nf++) {
            int kc = k0 + nf*8 + t2;
            float e0 = __expf(sacc[nf][0]);
            float e1 = __expf(sacc[nf][1]);
            float e2 = __expf(sacc[nf][2]);
            float e3 = __expf(sacc[nf][3]);
            if (needmask) {
                if (kc     > qrow)     e0 = 0.f;
                if (kc + 1 > qrow)     e1 = 0.f;
                if (kc     > qrow + 8) e2 = 0.f;
                if (kc + 1 > qrow + 8) e3 = 0.f;
            }
            // packed bf16 conversion; hi floats recovered exactly via bit ops
            uint32_t p0 = cvt_bf2(e0, e1);
            uint32_t p1 = cvt_bf2(e2, e3);
            float h0 = __uint_as_float(p0 << 16);
            float h1 = __uint_as_float(p0 & 0xFFFF0000u);
            float h2 = __uint_as_float(p1 << 16);
            float h3 = __uint_as_float(p1 & 0xFFFF0000u);
            int kk2 = nf >> 1;
            int ro  = (nf & 1) * 2;
            pah[kk2][ro+0] = p0;
            pah[kk2][ro+1] = p1;
            pal[kk2][ro+0] = cvt_bf2(e0 - h0, e1 - h1);
            pal[kk2][ro+1] = cvt_bf2(e2 - h2, e3 - h3);
        }

#pragma unroll
        for (int kk2 = 0; kk2 < 2; kk2++) {
            int brow = (lane & 7) + ((lane >> 4) << 3);
            int bc = kk2*2 + ((lane >> 3) & 1);
#pragma unroll
            for (int g = 0; g < 4; g++) {
                uint32_t th[4], tl[4];
                LDSM4(th, s + 2*F2_KTILE + swz_off(brow + g*16, bc));
                LDSM4(tl, s + 2*F2_KTILE + F2_VTILE + swz_off(brow + g*16, bc));
                MMA16816(oacc[2*g],   pah[kk2], th[0], th[1]);
                MMA16816(oacc[2*g],   pah[kk2], tl[0], tl[1]);
                MMA16816(oacc[2*g],   pal[kk2], th[0], th[1]);
                MMA16816(oacc[2*g+1], pah[kk2], th[2], th[3]);
                MMA16816(oacc[2*g+1], pah[kk2], tl[2], tl[3]);
                MMA16816(oacc[2*g+1], pal[kk2], th[2], th[3]);
            }
        }
    }

    // epilogue: write attO as f16 hi/lo (feeds f16 2-product O GEMM)
#pragma unroll
    for (int nt = 0; nt < 8; nt++) {
        int d = nt*8 + t2;
        float v00 = oacc[nt][0], v01 = oacc[nt][1];
        float v10 = oacc[nt][2], v11 = oacc[nt][3];
        size_t i0 = (size_t)(b*SS + qrow) * HDIM + h*64 + d;
        size_t i1 = (size_t)(b*SS + qrow + 8) * HDIM + h*64 + d;
        __half h00 = __float2half_rn(v00), h01 = __float2half_rn(v01);
        __half h10 = __float2half_rn(v10), h11 = __float2half_rn(v11);
        __half2 hp0 = {h00, h01}, hp1 = {h10, h11};
        __half2 lp0 = {__float2half_rn(v00 - __half2float(h00)),
                       __float2half_rn(v01 - __half2float(h01))};
        __half2 lp1 = {__float2half_rn(v10 - __half2float(h10)),
                       __float2half_rn(v11 - __half2float(h11))};
        *(__half2*)&g_aoh[i0] = hp0;  *(__half2*)&g_aol[i0] = lp0;
        *(__half2*)&g_aoh[i1] = hp1;  *(__half2*)&g_aol[i1] = lp1;
    }
}

// ------------------- launch ------------------------------------------------------
extern "C" void kernel_launch(void* const* d_in, const int* in_sizes, int n_in,
                              void* d_out, int out_size)
{
    const float* queries = (const float*)d_in[0];
    const float* keys    = (const float*)d_in[1];
    const float* values  = (const float*)d_in[2];
    const float* Wq_w = (const float*)d_in[3];  const float* Wq_b = (const float*)d_in[4];
    const float* Wk_w = (const float*)d_in[5];  const float* Wk_b = (const float*)d_in[6];
    const float* Wv_w = (const float*)d_in[7];  const float* Wv_b = (const float*)d_in[8];
    const float* Aq_w = (const float*)d_in[9];  const float* Aq_b = (const float*)d_in[10];
    const float* Bq_w = (const float*)d_in[11]; const float* Bq_b = (const float*)d_in[12];
    const float* Ak_w = (const float*)d_in[13]; const float* Ak_b = (const float*)d_in[14];
    const float* Bk_w = (const float*)d_in[15]; const float* Bk_b = (const float*)d_in[16];
    const float* Av_w = (const float*)d_in[17]; const float* Av_b = (const float*)d_in[18];
    const float* Bv_w = (const float*)d_in[19]; const float* Bv_b = (const float*)d_in[20];
    const float* Wo_w = (const float*)d_in[21]; const float* Wo_b = (const float*)d_in[22];
    float* out = (float*)d_out;

    cudaFuncSetAttribute(gemm_mma, cudaFuncAttributeMaxDynamicSharedMemorySize, GEMM_SMEM);
    cudaFuncSetAttribute(attn1_mma, cudaFuncAttributeMaxDynamicSharedMemorySize, A1_SMEM);
    cudaFuncSetAttribute(attn2_mma, cudaFuncAttributeMaxDynamicSharedMemorySize, F2_SMEM);

    void *pbeq, *pbek, *pbev, *pV, *pcs, *pKA;
    void *pqh, *pql, *pkh, *pkl, *pvh, *pvl, *paoh, *paol;
    void *pQph, *pQpl, *pKph, *pKpl;
    void *pwqh, *pwql, *pwkh, *pwkl, *pwvh, *pwvl, *pwoh, *pwol;
    cudaGetSymbolAddress(&pbeq, g_beq); cudaGetSymbolAddress(&pbek, g_bek);
    cudaGetSymbolAddress(&pbev, g_bev); cudaGetSymbolAddress(&pV, g_V);
    cudaGetSymbolAddress(&pcs, g_colsum); cudaGetSymbolAddress(&pKA, g_KA);
    cudaGetSymbolAddress(&pqh, g_qh); cudaGetSymbolAddress(&pql, g_ql);
    cudaGetSymbolAddress(&pkh, g_kh); cudaGetSymbolAddress(&pkl, g_kl);
    cudaGetSymbolAddress(&pvh, g_vh); cudaGetSymbolAddress(&pvl, g_vl);
    cudaGetSymbolAddress(&paoh, g_aoh); cudaGetSymbolAddress(&paol, g_aol);
    cudaGetSymbolAddress(&pQph, g_Qph); cudaGetSymbolAddress(&pQpl, g_Qpl);
    cudaGetSymbolAddress(&pKph, g_Kph); cudaGetSymbolAddress(&pKpl, g_Kpl);
    cudaGetSymbolAddress(&pwqh, g_wqh); cudaGetSymbolAddress(&pwql, g_wql);
    cudaGetSymbolAddress(&pwkh, g_wkh); cudaGetSymbolAddress(&pwkl, g_wkl);
    cudaGetSymbolAddress(&pwvh, g_wvh); cudaGetSymbolAddress(&pwvl, g_wvl);
    cudaGetSymbolAddress(&pwoh, g_woh); cudaGetSymbolAddress(&pwol, g_wol);

    ActArgs aa;
    aa.X[0] = queries; aa.X[1] = keys; aa.X[2] = values;
    aa.hi[0] = (__nv_bfloat16*)pqh; aa.hi[1] = (__nv_bfloat16*)pkh; aa.hi[2] = (__nv_bfloat16*)pvh;
    aa.lo[0] = (__nv_bfloat16*)pql; aa.lo[1] = (__nv_bfloat16*)pkl; aa.lo[2] = (__nv_bfloat16*)pvl;

    WprepArgs wa;
    wa.W[0] = Wq_w; wa.W[1] = Wk_w; wa.W[2] = Wv_w; wa.W[3] = Wo_w;
    wa.A[0] = Aq_w; wa.A[1] = Ak_w; wa.A[2] = nullptr; wa.A[3] = nullptr;
    wa.Bw[0] = Bq_w; wa.Bw[1] = Bk_w; wa.Bw[2] = nullptr; wa.Bw[3] = nullptr;
    wa.hi[0] = (__nv_bfloat16*)pwqh; wa.hi[1] = (__nv_bfloat16*)pwkh;
    wa.hi[2] = (__nv_bfloat16*)pwvh; wa.hi[3] = (__nv_bfloat16*)pwoh;
    wa.lo[0] = (__nv_bfloat16*)pwql; wa.lo[1] = (__nv_bfloat16*)pwkl;
    wa.lo[2] = (__nv_bfloat16*)pwvl; wa.lo[3] = (__nv_bfloat16*)pwol;

    BeffArgs ba;
    ba.Wb[0] = Wq_b; ba.Wb[1] = Wk_b; ba.Wb[2] = Wv_b;
    ba.Ab[0] = Aq_b; ba.Ab[1] = Ak_b; ba.Ab[2] = Av_b;
    ba.Bw[0] = Bq_w; ba.Bw[1] = Bk_w; ba.Bw[2] = Bv_w;
    ba.Bb[0] = Bq_b; ba.Bb[1] = Bk_b; ba.Bb[2] = Bv_b;
    ba.out[0] = (float*)pbeq; ba.out[1] = (float*)pbek; ba.out[2] = (float*)pbev;

    GemmArgs ga;
    ga.Ah[0] = (const __nv_bfloat16*)pqh;  ga.Al[0] = (const __nv_bfloat16*)pql;
    ga.Ah[1] = (const __nv_bfloat16*)pkh;  ga.Al[1] = (const __nv_bfloat16*)pkl;
    ga.Ah[2] = (const __nv_bfloat16*)pvh;  ga.Al[2] = (const __nv_bfloat16*)pvl;
    ga.Ah[3] = (const __nv_bfloat16*)paoh; ga.Al[3] = (const __nv_bfloat16*)paol;
    ga.Bh[0] = (const __nv_bfloat16*)pwqh; ga.Bl[0] = (const __nv_bfloat16*)pwql;
    ga.Bh[1] = (const __nv_bfloat16*)pwkh; ga.Bl[1] = (const __nv_bfloat16*)pwkl;
    ga.Bh[2] = (const __nv_bfloat16*)pwvh; ga.Bl[2] = (const __nv_bfloat16*)pwvl;
    ga.Bh[3] = (const __nv_bfloat16*)pwoh; ga.Bl[3] = (const __nv_bfloat16*)pwol;
    ga.bias[0] = (const float*)pbeq; ga.bias[1] = (const float*)pbek;
    ga.bias[2] = (const float*)pbev; ga.bias[3] = Wo_b;
    ga.outF[0] = nullptr; ga.outF[1] = nullptr; ga.outF[2] = (float*)pV; ga.outF[3] = out;
    ga.outH[0] = (__nv_bfloat16*)pQph; ga.outL[0] = (__nv_bfloat16*)pQpl;
    ga.outH[1] = (__nv_bfloat16*)pKph; ga.outL[1] = (__nv_bfloat16*)pKpl;
    ga.outH[2] = nullptr; ga.outL[2] = nullptr;
    ga.outH[3] = nullptr; ga.outL[3] = nullptr;
    ga.loraKA = (const float*)pKA; ga.loraB = Bv_w;

    actconv_kernel<<<dim3((TOK*DMODEL/4)/256, 1, 3), 256>>>(aa);          // 0
    wprep_kernel<<<dim3(DMODEL/32, HDIM/32, 4), 256>>>(wa);               // 1
    beff_kernel<<<dim3(HDIM/256, 1, 3), 256>>>(ba);                       // 2
    ka_kernel<<<TOK/8, 256>>>(keys, Av_w, (float*)pKA);                   // 3
    zero_kernel<<<(BB*NH*SS)/256, 256>>>((float*)pcs);                    // 4
    gemm_mma<<<dim3(HDIM/128, TOK/128, 3), 256, GEMM_SMEM>>>(ga, 0);      // 5: QKV fused
    attn1_mma<<<dim3(136, BB*NH), 256, A1_SMEM>>>();                      // 6
    vrt_kernel<<<dim3(SS/32, 2, BB*NH), 256>>>();                         // 7
    attn2_mma<<<dim3(16, BB*NH), 256, F2_SMEM>>>();                       // 8
    gemm_mma<<<dim3(HDIM/128, TOK/128, 1), 256, GEMM_SMEM>>>(ga, 3);      // 9: O
}

// round 16
// speedup vs baseline: 1.0756x; 1.0100x over previous
#include <cuda_runtime.h>
#include <cuda_bf16.h>
#include <cuda_fp16.h>
#include <math.h>
#include <stdint.h>

#define BB     4
#define SS     2048
#define DMODEL 1024
#define NH     16
#define HD     64
#define HDIM   1024
#define RK     8
#define TOK    (BB*SS)   // 8192

// ------------------- device scratch (static; allocation-free) -------------------
__device__ float g_beq[HDIM];
__device__ float g_bek[HDIM];
__device__ float g_bev[HDIM];
__device__ float g_V[(size_t)TOK*HDIM];
__device__ float g_colsum[(size_t)BB*NH*SS];
__device__ float g_KA[(size_t)TOK*RK];

// 16-bit buffers; z<2 hold bf16 hi/lo, z>=2 hold f16 hi/lo (reinterpreted)
__device__ __nv_bfloat16 g_qh[(size_t)TOK*DMODEL], g_ql[(size_t)TOK*DMODEL];
__device__ __nv_bfloat16 g_kh[(size_t)TOK*DMODEL], g_kl[(size_t)TOK*DMODEL];
__device__ __nv_bfloat16 g_vh[(size_t)TOK*DMODEL], g_vl[(size_t)TOK*DMODEL];   // f16
__device__ __nv_bfloat16 g_Qph[(size_t)TOK*HDIM], g_Qpl[(size_t)TOK*HDIM];
__device__ __nv_bfloat16 g_Kph[(size_t)TOK*HDIM], g_Kpl[(size_t)TOK*HDIM];
__device__ __nv_bfloat16 g_aoh[(size_t)TOK*HDIM], g_aol[(size_t)TOK*HDIM];     // f16
__device__ __nv_bfloat16 g_Vrth[(size_t)BB*NH*64*SS];
__device__ __nv_bfloat16 g_Vrtl[(size_t)BB*NH*64*SS];
__device__ __nv_bfloat16 g_wqh[DMODEL*HDIM], g_wql[DMODEL*HDIM];
__device__ __nv_bfloat16 g_wkh[DMODEL*HDIM], g_wkl[DMODEL*HDIM];
__device__ __nv_bfloat16 g_wvh[DMODEL*HDIM], g_wvl[DMODEL*HDIM];               // f16
__device__ __nv_bfloat16 g_woh[DMODEL*HDIM], g_wol[DMODEL*HDIM];               // f16

// ------------------- helpers ------------------------------------------------------
__device__ __forceinline__ uint32_t smem_u32(const void* p) {
    uint32_t a;
    asm("{ .reg .u64 t; cvta.to.shared.u64 t, %1; cvt.u32.u64 %0, t; }" : "=r"(a) : "l"(p));
    return a;
}
__device__ __forceinline__ void cpa16(uint32_t dst, const void* src) {
    asm volatile("cp.async.cg.shared.global [%0], [%1], 16;"
                 :: "r"(dst), "l"(__cvta_generic_to_global(src)));
}
#define CPA_COMMIT() asm volatile("cp.async.commit_group;")
#define CPA_WAIT2()  asm volatile("cp.async.wait_group 2;")
#define CPA_WAIT1()  asm volatile("cp.async.wait_group 1;")
#define CPA_WAIT0()  asm volatile("cp.async.wait_group 0;")

#define LDSM4(r, a) \
    asm volatile("ldmatrix.sync.aligned.m8n8.x4.shared.b16 {%0,%1,%2,%3}, [%4];" \
        : "=r"((r)[0]), "=r"((r)[1]), "=r"((r)[2]), "=r"((r)[3]) : "r"(a))

#define MMA16816(c, a, b0, b1) \
    asm volatile("mma.sync.aligned.m16n8k16.row.col.f32.bf16.bf16.f32 " \
        "{%0,%1,%2,%3}, {%4,%5,%6,%7}, {%8,%9}, {%0,%1,%2,%3};" \
        : "+f"((c)[0]), "+f"((c)[1]), "+f"((c)[2]), "+f"((c)[3]) \
        : "r"((a)[0]), "r"((a)[1]), "r"((a)[2]), "r"((a)[3]), "r"(b0), "r"(b1))

#define MMAF16(c, a, b0, b1) \
    asm volatile("mma.sync.aligned.m16n8k16.row.col.f32.f16.f16.f32 " \
        "{%0,%1,%2,%3}, {%4,%5,%6,%7}, {%8,%9}, {%0,%1,%2,%3};" \
        : "+f"((c)[0]), "+f"((c)[1]), "+f"((c)[2]), "+f"((c)[3]) \
        : "r"((a)[0]), "r"((a)[1]), "r"((a)[2]), "r"((a)[3]), "r"(b0), "r"(b1))

__device__ __forceinline__ uint32_t pack_bf2(float lo, float hi) {
    __nv_bfloat162 p = {__float2bfloat16(lo), __float2bfloat16(hi)};
    return *(uint32_t*)&p;
}
__device__ __forceinline__ uint32_t cvt_bf2(float lo, float hi) {
    uint32_t r;
    asm("cvt.rn.bf16x2.f32 %0, %1, %2;" : "=r"(r) : "f"(hi), "f"(lo));
    return r;
}

#define SWZ128(x) ((x) ^ (((x) >> 3) & 0x70))
__device__ __forceinline__ uint32_t swz_off(int row, int chunk) {
    uint32_t o = (uint32_t)((row >> 1) * 128 + (row & 1) * 64 + chunk * 16);
    return SWZ128(o);
}

// ------------------- fused prep kernels -------------------------------------------
struct ActArgs { const float* X[3]; __nv_bfloat16 *hi[3], *lo[3]; };
__global__ void actconv_kernel(ActArgs aa)
{
    int z = blockIdx.z;
    const float* X = aa.X[z];
    size_t i = ((size_t)blockIdx.x * 256 + threadIdx.x) * 4;
    float4 v = *(const float4*)&X[i];
    if (z < 2) {
        __nv_bfloat16* hi = aa.hi[z];
        __nv_bfloat16* lo = aa.lo[z];
        __nv_bfloat16 h0 = __float2bfloat16(v.x), h1 = __float2bfloat16(v.y);
        __nv_bfloat16 h2 = __float2bfloat16(v.z), h3 = __float2bfloat16(v.w);
        __nv_bfloat162 ph0 = {h0, h1}, ph1 = {h2, h3};
        __nv_bfloat162 pl0 = {__float2bfloat16(v.x - __bfloat162float(h0)),
                              __float2bfloat16(v.y - __bfloat162float(h1))};
        __nv_bfloat162 pl1 = {__float2bfloat16(v.z - __bfloat162float(h2)),
                              __float2bfloat16(v.w - __bfloat162float(h3))};
        *(__nv_bfloat162*)&hi[i]   = ph0;  *(__nv_bfloat162*)&hi[i+2] = ph1;
        *(__nv_bfloat162*)&lo[i]   = pl0;  *(__nv_bfloat162*)&lo[i+2] = pl1;
    } else {
        __half* hi = (__half*)aa.hi[z];
        __half* lo = (__half*)aa.lo[z];
        __half h0 = __float2half_rn(v.x), h1 = __float2half_rn(v.y);
        __half h2 = __float2half_rn(v.z), h3 = __float2half_rn(v.w);
        __half2 ph0 = {h0, h1}, ph1 = {h2, h3};
        __half2 pl0 = {__float2half_rn(v.x - __half2float(h0)),
                       __float2half_rn(v.y - __half2float(h1))};
        __half2 pl1 = {__float2half_rn(v.z - __half2float(h2)),
                       __float2half_rn(v.w - __half2float(h3))};
        *(__half2*)&hi[i]   = ph0;  *(__half2*)&hi[i+2] = ph1;
        *(__half2*)&lo[i]   = pl0;  *(__half2*)&lo[i+2] = pl1;
    }
}

struct WprepArgs { const float *W[4], *A[4], *Bw[4]; __nv_bfloat16 *hi[4], *lo[4]; };
__global__ __launch_bounds__(256) void wprep_kernel(WprepArgs wa)
{
    __shared__ float t[32][33];
    int z = blockIdx.z;
    const float* W = wa.W[z];
    const float* A = wa.A[z];
    const float* Bw = wa.Bw[z];
    int kb = blockIdx.x * 32, nb = blockIdx.y * 32;
    int x = threadIdx.x & 31, y = threadIdx.x >> 5;
#pragma unroll
    for (int i = y; i < 32; i += 8) {
        int k = kb + i, n = nb + x;
        float v = W[(size_t)k*HDIM + n];
        if (A) {
#pragma unroll
            for (int r = 0; r < RK; r++) v += A[k*RK + r] * Bw[r*HDIM + n];
        }
        t[i][x] = v;
    }
    __syncthreads();
    if (z < 2) {
        __nv_bfloat16* hi = wa.hi[z];
        __nv_bfloat16* lo = wa.lo[z];
#pragma unroll
        for (int i = y; i < 32; i += 8) {
            int n = nb + i, k = kb + x;
            float v = t[x][i];
            __nv_bfloat16 h = __float2bfloat16(v);
            hi[(size_t)n*DMODEL + k] = h;
            lo[(size_t)n*DMODEL + k] = __float2bfloat16(v - __bfloat162float(h));
        }
    } else {
        __half* hi = (__half*)wa.hi[z];
        __half* lo = (__half*)wa.lo[z];
#pragma unroll
        for (int i = y; i < 32; i += 8) {
            int n = nb + i, k = kb + x;
            float v = t[x][i];
            __half h = __float2half_rn(v);
            hi[(size_t)n*DMODEL + k] = h;
            lo[(size_t)n*DMODEL + k] = __float2half_rn(v - __half2float(h));
        }
    }
}

struct BeffArgs { const float *Wb[3], *Ab[3], *Bw[3], *Bb[3]; float* out[3]; };
__global__ void beff_kernel(BeffArgs ba)
{
    int z = blockIdx.z;
    int j = blockIdx.x * 256 + threadIdx.x;
    float acc = ba.Wb[z][j] + ba.Bb[z][j];
    const float* Ab = ba.Ab[z];
    const float* Bw = ba.Bw[z];
#pragma unroll
    for (int r = 0; r < RK; r++) acc += Ab[r] * Bw[r*HDIM + j];
    ba.out[z][j] = acc;
}

__global__ void zero_kernel(float* p) { p[blockIdx.x * 256 + threadIdx.x] = 0.f; }

__global__ __launch_bounds__(256) void ka_kernel(const float* __restrict__ keys,
                                                 const float* __restrict__ Av,
                                                 float* __restrict__ KA)
{
    __shared__ float avT[RK][DMODEL];
    int tid = threadIdx.x;
#pragma unroll
    for (int f = tid; f < DMODEL*RK/4; f += 256) {
        int k = f >> 1, j = (f & 1) * 4;
        float4 v = ((const float4*)Av)[f];
        avT[j+0][k] = v.x; avT[j+1][k] = v.y;
        avT[j+2][k] = v.z; avT[j+3][k] = v.w;
    }
    __syncthreads();

    int warp = tid >> 5, lane = tid & 31;
    int row = blockIdx.x * 8 + warp;
    const float4* kr = (const float4*)(keys + (size_t)row * DMODEL);
    float acc[RK];
#pragma unroll
    for (int r = 0; r < RK; r++) acc[r] = 0.f;
#pragma unroll
    for (int i = 0; i < 8; i++) {
        int k4 = lane + i * 32;
        float4 kv = kr[k4];
        int k = 4 * k4;
#pragma unroll
        for (int r = 0; r < RK; r++) {
            float4 av = *(const float4*)&avT[r][k];
            acc[r] += kv.x*av.x + kv.y*av.y + kv.z*av.z + kv.w*av.w;
        }
    }
#pragma unroll
    for (int r = 0; r < RK; r++) {
#pragma unroll
        for (int off = 16; off > 0; off >>= 1)
            acc[r] += __shfl_down_sync(0xffffffffu, acc[r], off);
    }
    if (lane == 0) {
#pragma unroll
        for (int r = 0; r < RK; r++) KA[(size_t)row*RK + r] = acc[r];
    }
}

// ------------------- fused mma.sync GEMM: bf16 3-prod (z<2, 3-stage) /
//                     f16 2-prod (z>=2, 4-stage: stage = 3 tiles only) ------------
static constexpr int G_TILE  = 8192;
static constexpr int GEMM_SMEM = 98304;   // bf16: 3 x 32KB; f16: 4 x 24KB

struct GemmArgs {
    const __nv_bfloat16 *Ah[4], *Al[4], *Bh[4], *Bl[4];
    const float* bias[4];
    float* outF[4];
    __nv_bfloat16 *outH[4], *outL[4];
    const float *loraKA, *loraB;
};

__global__ __launch_bounds__(256, 2)
void gemm_mma(GemmArgs ga, int op)
{
    extern __shared__ char smem[];
    const uint32_t sb = smem_u32(smem);
    const int z = (op == 0) ? blockIdx.z : op;
    const bool F16 = (z >= 2);
    const uint32_t STG = F16 ? (uint32_t)(3*G_TILE) : (uint32_t)(4*G_TILE);
    const __nv_bfloat16* Ah = ga.Ah[z];
    const __nv_bfloat16* Al = ga.Al[z];
    const __nv_bfloat16* Bh = ga.Bh[z];
    const __nv_bfloat16* Bl = ga.Bl[z];
    const float* bias = ga.bias[z];
    float* outF = ga.outF[z];
    __nv_bfloat16* outH = ga.outH[z];
    __nv_bfloat16* outL = ga.outL[z];
    const float* loraKA = (z == 2) ? ga.loraKA : nullptr;
    const float* loraB  = ga.loraB;

    const int tid  = threadIdx.x;
    const int lane = tid & 31;
    const int warp = tid >> 5;
    const int wm = warp >> 2, wn = warp & 3;
    const int m0 = blockIdx.y * 128, n0 = blockIdx.x * 128;

    float acc[4][4][4];
#pragma unroll
    for (int i = 0; i < 4; i++)
#pragma unroll
        for (int j = 0; j < 4; j++)
#pragma unroll
            for (int k = 0; k < 4; k++) acc[i][j][k] = 0.f;

    auto load_stage = [&](int st, int chunk) {
        int k0 = chunk * 32;
        const __nv_bfloat16* tp[4] = {Ah, Al, Bh, Bl};
        uint32_t sbase = sb + st * STG;
#pragma unroll
        for (int i = 0; i < 8; i++) {
            const int t = i >> 1;
            if (F16 && t == 3) continue;
            int j = (i & 1) ? tid + 256 : tid;
            int row = j >> 2, sg = j & 3;
            int r0 = (t < 2) ? m0 : n0;
            cpa16(sbase + t * G_TILE + swz_off(row, sg),
                  tp[t] + (size_t)(r0 + row) * 1024 + k0 + sg * 8);
        }
    };

    auto compute_stage = [&](int st) {
        uint32_t ab = sb + st * STG;
#pragma unroll
        for (int kk = 0; kk < 2; kk++) {
            uint32_t ahr[4][4], alr[4][4], bh2[4][2], bl2[4][2];
            int arow = wm*64 + (lane & 15);
            int ac   = kk*2 + (lane >> 4);
            uint32_t abase = ab + swz_off(arow, ac);
#pragma unroll
            for (int mt = 0; mt < 4; mt++) {
                LDSM4(ahr[mt], abase + mt * 1024);
                LDSM4(alr[mt], abase + G_TILE + mt * 1024);
            }
            int brow = wn*32 + (lane & 7) + ((lane >> 4) << 3);
            int bc   = kk*2 + ((lane >> 3) & 1);
            uint32_t bbase = ab + 2*G_TILE + swz_off(brow, bc);
            {
                uint32_t t0[4], t1[4];
                LDSM4(t0, bbase);
                LDSM4(t1, bbase + 1024);
                bh2[0][0]=t0[0]; bh2[0][1]=t0[1]; bh2[1][0]=t0[2]; bh2[1][1]=t0[3];
                bh2[2][0]=t1[0]; bh2[2][1]=t1[1]; bh2[3][0]=t1[2]; bh2[3][1]=t1[3];
                if (!F16) {
                    LDSM4(t0, bbase + G_TILE);
                    LDSM4(t1, bbase + G_TILE + 1024);
                    bl2[0][0]=t0[0]; bl2[0][1]=t0[1]; bl2[1][0]=t0[2]; bl2[1][1]=t0[3];
                    bl2[2][0]=t1[0]; bl2[2][1]=t1[1]; bl2[3][0]=t1[2]; bl2[3][1]=t1[3];
                }
            }
            if (!F16) {
#pragma unroll
                for (int mt = 0; mt < 4; mt++)
#pragma unroll
                    for (int nt = 0; nt < 4; nt++) {
                        MMA16816(acc[mt][nt], ahr[mt], bh2[nt][0], bh2[nt][1]);
                        MMA16816(acc[mt][nt], ahr[mt], bl2[nt][0], bl2[nt][1]);
                        MMA16816(acc[mt][nt], alr[mt], bh2[nt][0], bh2[nt][1]);
                    }
            } else {
#pragma unroll
                for (int mt = 0; mt < 4; mt++)
#pragma unroll
                    for (int nt = 0; nt < 4; nt++) {
                        MMAF16(acc[mt][nt], ahr[mt], bh2[nt][0], bh2[nt][1]);
                        MMAF16(acc[mt][nt], alr[mt], bh2[nt][0], bh2[nt][1]);
                    }
            }
        }
    };

    if (!F16) {
        load_stage(0, 0); CPA_COMMIT();
        load_stage(1, 1); CPA_COMMIT();
#pragma unroll 1
        for (int c = 0; c < 32; c++) {
            CPA_WAIT1();
            __syncthreads();
            if (c + 2 < 32) load_stage((c + 2) % 3, c + 2);
            CPA_COMMIT();
            compute_stage(c % 3);
        }
    } else {
        load_stage(0, 0); CPA_COMMIT();
        load_stage(1, 1); CPA_COMMIT();
        load_stage(2, 2); CPA_COMMIT();
#pragma unroll 1
        for (int c = 0; c < 32; c++) {
            CPA_WAIT2();
            __syncthreads();
            if (c + 3 < 32) load_stage((c + 3) & 3, c + 3);
            CPA_COMMIT();
            compute_stage(c & 3);
        }
    }

    int r_ = lane >> 2, c_ = (lane & 3) * 2;
#pragma unroll
    for (int mt = 0; mt < 4; mt++) {
        int row = m0 + wm*64 + mt*16 + r_;
        float ka0[RK], ka1[RK];
        if (loraKA) {
#pragma unroll
            for (int r = 0; r < RK; r++) {
                ka0[r] = loraKA[(size_t)row*RK + r];
                ka1[r] = loraKA[(size_t)(row+8)*RK + r];
            }
        }
#pragma unroll
        for (int nt = 0; nt < 4; nt++) {
            int col = n0 + wn*32 + nt*8 + c_;
            float b0 = bias[col], b1 = bias[col + 1];
            float v00 = acc[mt][nt][0] + b0, v01 = acc[mt][nt][1] + b1;
            float v10 = acc[mt][nt][2] + b0, v11 = acc[mt][nt][3] + b1;
            if (loraKA) {
#pragma unroll
                for (int r = 0; r < RK; r++) {
                    float w0 = loraB[r*HDIM + col], w1 = loraB[r*HDIM + col + 1];
                    v00 += ka0[r] * w0;  v01 += ka0[r] * w1;
                    v10 += ka1[r] * w0;  v11 += ka1[r] * w1;
                }
            }
            if (outF) {
                *(float2*)&outF[(size_t)row * 1024 + col] = {v00, v01};
                *(float2*)&outF[(size_t)(row + 8) * 1024 + col] = {v10, v11};
            } else {
                __nv_bfloat16 h00 = __float2bfloat16(v00), h01 = __float2bfloat16(v01);
                __nv_bfloat16 h10 = __float2bfloat16(v10), h11 = __float2bfloat16(v11);
                __nv_bfloat162 hp0 = {h00, h01}, hp1 = {h10, h11};
                __nv_bfloat162 lp0 = {__float2bfloat16(v00 - __bfloat162float(h00)),
                                      __float2bfloat16(v01 - __bfloat162float(h01))};
                __nv_bfloat162 lp1 = {__float2bfloat16(v10 - __bfloat162float(h10)),
                                      __float2bfloat16(v11 - __bfloat162float(h11))};
                *(__nv_bfloat162*)&outH[(size_t)row * 1024 + col] = hp0;
                *(__nv_bfloat162*)&outH[(size_t)(row + 8) * 1024 + col] = hp1;
                *(__nv_bfloat162*)&outL[(size_t)row * 1024 + col] = lp0;
                *(__nv_bfloat162*)&outL[(size_t)(row + 8) * 1024 + col] = lp1;
            }
        }
    }
}

// ------------------- pass 1 (slim): column sums of exp(QK^T) masked --------------
// Two-phase: hi tiles load+compute overlapped with lo tiles load.
static constexpr int A1_PITCH = 144;
static constexpr int A1_TILE  = 128 * A1_PITCH;
static constexpr int A1_SMEM  = 4 * A1_TILE;

__global__ __launch_bounds__(256, 2) void attn1_mma()
{
    extern __shared__ char smem[];
    int idx = blockIdx.x;
    int qt = (int)((sqrtf(8.f*idx + 1.f) - 1.f) * 0.5f);
    if ((qt+1)*(qt+2)/2 <= idx) qt++;
    if (qt*(qt+1)/2 > idx) qt--;
    int kt = idx - qt*(qt+1)/2;
    int bh = blockIdx.y;
    const uint32_t sb = smem_u32(smem);
    int b = bh >> 4, h = bh & 15;
    int q0 = qt * 128, k0 = kt * 128;
    int tid = threadIdx.x, lane = tid & 31, warp = tid >> 5;
    int wm = warp >> 2, wn = warp & 3;

    {
        const __nv_bfloat16* tp[4] = {g_Qph, g_Qpl, g_Kph, g_Kpl};
        // group 0: hi tiles (t = 0, 2)
#pragma unroll
        for (int tt = 0; tt < 2; tt++) {
            int t = tt * 2;
            int r0 = (t < 2) ? q0 : k0;
#pragma unroll
            for (int i = 0; i < 4; i++) {
                int ix = tid + i * 256;
                int row = ix >> 3, sg = ix & 7;
                cpa16(sb + t * A1_TILE + row * A1_PITCH + sg * 16,
                      tp[t] + (size_t)(b*SS + r0 + row) * 1024 + h*64 + sg * 8);
            }
        }
        CPA_COMMIT();
        // group 1: lo tiles (t = 1, 3)
#pragma unroll
        for (int tt = 0; tt < 2; tt++) {
            int t = tt * 2 + 1;
            int r0 = (t < 2) ? q0 : k0;
#pragma unroll
            for (int i = 0; i < 4; i++) {
                int ix = tid + i * 256;
                int row = ix >> 3, sg = ix & 7;
                cpa16(sb + t * A1_TILE + row * A1_PITCH + sg * 16,
                      tp[t] + (size_t)(b*SS + r0 + row) * 1024 + h*64 + sg * 8);
            }
        }
        CPA_COMMIT();
    }

    float acc[4][4][4];
#pragma unroll
    for (int i = 0; i < 4; i++)
#pragma unroll
        for (int j = 0; j < 4; j++)
#pragma unroll
            for (int k = 0; k < 4; k++) acc[i][j][k] = 0.f;

    // ---- phase A: hi x hi products while lo tiles stream in
    CPA_WAIT1();
    __syncthreads();
#pragma unroll
    for (int kk = 0; kk < 4; kk++) {
        uint32_t ahr[4][4], bhf[4][2];
        uint32_t aoff = (uint32_t)(wm*64 + (lane & 15)) * A1_PITCH
                      + (uint32_t)(kk*16 + (lane >> 4) * 8) * 2;
#pragma unroll
        for (int mt = 0; mt < 4; mt++)
            LDSM4(ahr[mt], sb + aoff + mt * (16*A1_PITCH));
        uint32_t boff = (uint32_t)(wn*32 + (lane & 7) + ((lane >> 4) << 3)) * A1_PITCH
                      + (uint32_t)(kk*16 + ((lane >> 3) & 1) * 8) * 2;
        {
            uint32_t t0[4], t1[4];
            LDSM4(t0, sb + 2*A1_TILE + boff);
            LDSM4(t1, sb + 2*A1_TILE + boff + 16*A1_PITCH);
            bhf[0][0]=t0[0]; bhf[0][1]=t0[1]; bhf[1][0]=t0[2]; bhf[1][1]=t0[3];
            bhf[2][0]=t1[0]; bhf[2][1]=t1[1]; bhf[3][0]=t1[2]; bhf[3][1]=t1[3];
        }
#pragma unroll
        for (int mt = 0; mt < 4; mt++)
#pragma unroll
            for (int nt = 0; nt < 4; nt++)
                MMA16816(acc[mt][nt], ahr[mt], bhf[nt][0], bhf[nt][1]);
    }

    // ---- phase B: cross products (hi x lo + lo x hi)
    CPA_WAIT0();
    __syncthreads();
#pragma unroll
    for (int kk = 0; kk < 4; kk++) {
        uint32_t ahr[4][4], alr[4][4], bhf[4][2], blf[4][2];
        uint32_t aoff = (uint32_t)(wm*64 + (lane & 15)) * A1_PITCH
                      + (uint32_t)(kk*16 + (lane >> 4) * 8) * 2;
#pragma unroll
        for (int mt = 0; mt < 4; mt++) {
            LDSM4(ahr[mt], sb + aoff + mt * (16*A1_PITCH));
            LDSM4(alr[mt], sb + A1_TILE + aoff + mt * (16*A1_PITCH));
        }
        uint32_t boff = (uint32_t)(wn*32 + (lane & 7) + ((lane >> 4) << 3)) * A1_PITCH
                      + (uint32_t)(kk*16 + ((lane >> 3) & 1) * 8) * 2;
        {
            uint32_t t0[4], t1[4];
            LDSM4(t0, sb + 2*A1_TILE + boff);
            LDSM4(t1, sb + 2*A1_TILE + boff + 16*A1_PITCH);
            bhf[0][0]=t0[0]; bhf[0][1]=t0[1]; bhf[1][0]=t0[2]; bhf[1][1]=t0[3];
            bhf[2][0]=t1[0]; bhf[2][1]=t1[1]; bhf[3][0]=t1[2]; bhf[3][1]=t1[3];
            LDSM4(t0, sb + 3*A1_TILE + boff);
            LDSM4(t1, sb + 3*A1_TILE + boff + 16*A1_PITCH);
            blf[0][0]=t0[0]; blf[0][1]=t0[1]; blf[1][0]=t0[2]; blf[1][1]=t0[3];
            blf[2][0]=t1[0]; blf[2][1]=t1[1]; blf[3][0]=t1[2]; blf[3][1]=t1[3];
        }
#pragma unroll
        for (int mt = 0; mt < 4; mt++)
#pragma unroll
            for (int nt = 0; nt < 4; nt++) {
                MMA16816(acc[mt][nt], ahr[mt], blf[nt][0], blf[nt][1]);
                MMA16816(acc[mt][nt], alr[mt], bhf[nt][0], bhf[nt][1]);
            }
    }

    __syncthreads();
    float* cs = (float*)smem;
    if (tid < 128) cs[tid] = 0.f;
    __syncthreads();

    const bool diag = (qt == kt);
    int r_ = lane >> 2, c_ = (lane & 3) * 2;
    float cs0[4] = {0,0,0,0}, cs1[4] = {0,0,0,0};
#pragma unroll
    for (int mt = 0; mt < 4; mt++) {
        int qb = q0 + wm*64 + mt*16;
#pragma unroll
        for (int nt = 0; nt < 4; nt++) {
            int k = k0 + wn*32 + nt*8 + c_;
            float e00 = __expf(acc[mt][nt][0]);
            float e01 = __expf(acc[mt][nt][1]);
            float e10 = __expf(acc[mt][nt][2]);
            float e11 = __expf(acc[mt][nt][3]);
            int qr0 = qb + r_, qr1 = qb + r_ + 8;
            if (diag) {
                if (qr0 < k)     e00 = 0.f;
                if (qr0 < k + 1) e01 = 0.f;
                if (qr1 < k)     e10 = 0.f;
                if (qr1 < k + 1) e11 = 0.f;
            }
            cs0[nt] += e00 + e10;
            cs1[nt] += e01 + e11;
        }
    }
#pragma unroll
    for (int nt = 0; nt < 4; nt++) {
        atomicAdd(&cs[wn*32 + nt*8 + c_],     cs0[nt]);
        atomicAdd(&cs[wn*32 + nt*8 + c_ + 1], cs1[nt]);
    }
    __syncthreads();
    if (tid < 128)
        atomicAdd(&g_colsum[(size_t)bh*SS + k0 + tid], cs[tid]);
}

// ------------------- Vrt prep: bf16 hi/lo ----------------------------------------
__global__ __launch_bounds__(256) void vrt_kernel()
{
    __shared__ float t[32][33];
    int kt = blockIdx.x, dt = blockIdx.y, bh = blockIdx.z;
    int b = bh >> 4, h = bh & 15;
    int k0 = kt * 32, d0 = dt * 32;
    int x = threadIdx.x & 31, y = threadIdx.x >> 5;
#pragma unroll
    for (int i = y; i < 32; i += 8) {
        int k = k0 + i;
        float r = 1.0f / (g_colsum[(size_t)bh*SS + k] * 8.0f);
        t[i][x] = g_V[(size_t)(b*SS + k) * HDIM + h*64 + d0 + x] * r;
    }
    __syncthreads();
#pragma unroll
    for (int i = y; i < 32; i += 8) {
        int d = d0 + i, k = k0 + x;
        float v = t[x][i];
        __nv_bfloat16 hh = __float2bfloat16(v);
        size_t idx = ((size_t)bh*64 + d) * SS + k;
        g_Vrth[idx] = hh;
        g_Vrtl[idx] = __float2bfloat16(v - __bfloat162float(hh));
    }
}

// ------------------- pass 2 (flash): recompute P = exp(QK^T), out = P @ Vrt^T ----
static constexpr int F2_QTILE = 16384;
static constexpr int F2_KTILE = 4096;
static constexpr int F2_VTILE = 4096;
static constexpr int F2_STAGE = 2*F2_KTILE + 2*F2_VTILE;
static constexpr int F2_SMEM  = 2*F2_QTILE + 4*F2_STAGE;      // 98304

__global__ __launch_bounds__(256, 2) void attn2_mma()
{
    extern __shared__ char smem[];
    const uint32_t sb = smem_u32(smem);
    int qt = (int)gridDim.x - 1 - (int)blockIdx.x;
    int bh = blockIdx.y;
    int b = bh >> 4, h = bh & 15;
    int q0 = qt * 128;
    int tid = threadIdx.x, lane = tid & 31, warp = tid >> 5;
    int nch = (qt + 1) * 4;

    const uint32_t qbh = sb;
    const uint32_t qbl = sb + F2_QTILE;
    const uint32_t stb = sb + 2*F2_QTILE;

#pragma unroll
    for (int i = 0; i < 4; i++) {
        int ix = tid + i * 256;
        int row = ix >> 3, sg = ix & 7;
        size_t gi = (size_t)(b*SS + q0 + row) * 1024 + h*64 + sg * 8;
        uint32_t off = SWZ128((uint32_t)(row * 128 + sg * 16));
        cpa16(qbh + off, &g_Qph[gi]);
        cpa16(qbl + off, &g_Qpl[gi]);
    }

    auto load_stage = [&](int st, int c) {
        int k0 = c * 32;
        uint32_t s = stb + st * F2_STAGE;
        {
            int row = tid >> 3, sg = tid & 7;
            size_t gi = (size_t)(b*SS + k0 + row) * 1024 + h*64 + sg * 8;
            uint32_t off = SWZ128((uint32_t)(row * 128 + sg * 16));
            cpa16(s + off, &g_Kph[gi]);
            cpa16(s + F2_KTILE + off, &g_Kpl[gi]);
        }
        {
            int row = tid >> 2, sg = tid & 3;
            size_t gi = ((size_t)bh*64 + row) * SS + k0 + sg * 8;
            uint32_t off = swz_off(row, sg);
            cpa16(s + 2*F2_KTILE + off, &g_Vrth[gi]);
            cpa16(s + 2*F2_KTILE + F2_VTILE + off, &g_Vrtl[gi]);
        }
    };

    load_stage(0, 0); CPA_COMMIT();
    load_stage(1, 1); CPA_COMMIT();
    load_stage(2, 2); CPA_COMMIT();

    float oacc[8][4];
#pragma unroll
    for (int i = 0; i < 8; i++)
#pragma unroll
        for (int j = 0; j < 4; j++) oacc[i][j] = 0.f;

    const int r_ = lane >> 2, t2 = (lane & 3) * 2;
    const int qrow = q0 + warp*16 + r_;

    uint32_t qfh[4][4], qfl[4][4];

#pragma unroll 1
    for (int c = 0; c < nch; c++) {
        CPA_WAIT2();
        __syncthreads();
        if (c == 0) {
#pragma unroll
            for (int kk = 0; kk < 4; kk++) {
                uint32_t arow = (uint32_t)(warp*16 + (lane & 15));
                uint32_t aoff = SWZ128(arow * 128 + (uint32_t)(kk*32 + (lane >> 4) * 16));
                LDSM4(qfh[kk], qbh + aoff);
                LDSM4(qfl[kk], qbl + aoff);
            }
        }
        if (c + 3 < nch) load_stage((c + 3) & 3, c + 3);
        CPA_COMMIT();
        uint32_t s = stb + (c & 3) * F2_STAGE;
        int k0 = c * 32;

        float sacc[4][4];
#pragma unroll
        for (int i = 0; i < 4; i++)
#pragma unroll
            for (int j = 0; j < 4; j++) sacc[i][j] = 0.f;

#pragma unroll
        for (int kk = 0; kk < 4; kk++) {
            uint32_t bh2[4][2], bl2[4][2];
            uint32_t brow = (uint32_t)((lane & 7) + ((lane >> 4) << 3));
            uint32_t bcol = (uint32_t)(kk*32 + ((lane >> 3) & 1) * 16);
            {
                uint32_t t0[4], t1[4];
                LDSM4(t0, s + SWZ128(brow * 128 + bcol));
                LDSM4(t1, s + SWZ128((brow + 16) * 128 + bcol));
                bh2[0][0]=t0[0]; bh2[0][1]=t0[1]; bh2[1][0]=t0[2]; bh2[1][1]=t0[3];
                bh2[2][0]=t1[0]; bh2[2][1]=t1[1]; bh2[3][0]=t1[2]; bh2[3][1]=t1[3];
                LDSM4(t0, s + F2_KTILE + SWZ128(brow * 128 + bcol));
                LDSM4(t1, s + F2_KTILE + SWZ128((brow + 16) * 128 + bcol));
                bl2[0][0]=t0[0]; bl2[0][1]=t0[1]; bl2[1][0]=t0[2]; bl2[1][1]=t0[3];
                bl2[2][0]=t1[0]; bl2[2][1]=t1[1]; bl2[3][0]=t1[2]; bl2[3][1]=t1[3];
            }
#pragma unroll
            for (int nt = 0; nt < 4; nt++) {
                MMA16816(sacc[nt], qfh[kk], bh2[nt][0], bh2[nt][1]);
                MMA16816(sacc[nt], qfh[kk], bl2[nt][0], bl2[nt][1]);
                MMA16816(sacc[nt], qfl[kk], bh2[nt][0], bh2[nt][1]);
            }
        }

        uint32_t pah[2][4], pal[2][4];
        const bool needmask = (k0 + 32 > q0 + warp*16);
#pragma unroll
        for (int nf = 0; nf < 4; nf++) {
            int kc = k0 + nf*8 + t2;
            float e0 = __expf(sacc[nf][0]);
            float e1 = __expf(sacc[nf][1]);
            float e2 = __expf(sacc[nf][2]);
            float e3 = __expf(sacc[nf][3]);
            if (needmask) {
                if (kc     > qrow)     e0 = 0.f;
                if (kc + 1 > qrow)     e1 = 0.f;
                if (kc     > qrow + 8) e2 = 0.f;
                if (kc + 1 > qrow + 8) e3 = 0.f;
            }
            uint32_t p0 = cvt_bf2(e0, e1);
            uint32_t p1 = cvt_bf2(e2, e3);
            float h0 = __uint_as_float(p0 << 16);
            float h1 = __uint_as_float(p0 & 0xFFFF0000u);
            float h2 = __uint_as_float(p1 << 16);
            float h3 = __uint_as_float(p1 & 0xFFFF0000u);
            int kk2 = nf >> 1;
            int ro  = (nf & 1) * 2;
            pah[kk2][ro+0] = p0;
            pah[kk2][ro+1] = p1;
            pal[kk2][ro+0] = cvt_bf2(e0 - h0, e1 - h1);
            pal[kk2][ro+1] = cvt_bf2(e2 - h2, e3 - h3);
        }

#pragma unroll
        for (int kk2 = 0; kk2 < 2; kk2++) {
            int brow = (lane & 7) + ((lane >> 4) << 3);
            int bc = kk2*2 + ((lane >> 3) & 1);
#pragma unroll
            for (int g = 0; g < 4; g++) {
                uint32_t th[4], tl[4];
                LDSM4(th, s + 2*F2_KTILE + swz_off(brow + g*16, bc));
                LDSM4(tl, s + 2*F2_KTILE + F2_VTILE + swz_off(brow + g*16, bc));
                MMA16816(oacc[2*g],   pah[kk2], th[0], th[1]);
                MMA16816(oacc[2*g],   pah[kk2], tl[0], tl[1]);
                MMA16816(oacc[2*g],   pal[kk2], th[0], th[1]);
                MMA16816(oacc[2*g+1], pah[kk2], th[2], th[3]);
                MMA16816(oacc[2*g+1], pah[kk2], tl[2], tl[3]);
                MMA16816(oacc[2*g+1], pal[kk2], th[2], th[3]);
            }
        }
    }

#pragma unroll
    for (int nt = 0; nt < 8; nt++) {
        int d = nt*8 + t2;
        float v00 = oacc[nt][0], v01 = oacc[nt][1];
        float v10 = oacc[nt][2], v11 = oacc[nt][3];
        size_t i0 = (size_t)(b*SS + qrow) * HDIM + h*64 + d;
        size_t i1 = (size_t)(b*SS + qrow + 8) * HDIM + h*64 + d;
        __half h00 = __float2half_rn(v00), h01 = __float2half_rn(v01);
        __half h10 = __float2half_rn(v10), h11 = __float2half_rn(v11);
        __half2 hp0 = {h00, h01}, hp1 = {h10, h11};
        __half2 lp0 = {__float2half_rn(v00 - __half2float(h00)),
                       __float2half_rn(v01 - __half2float(h01))};
        __half2 lp1 = {__float2half_rn(v10 - __half2float(h10)),
                       __float2half_rn(v11 - __half2float(h11))};
        *(__half2*)&g_aoh[i0] = hp0;  *(__half2*)&g_aol[i0] = lp0;
        *(__half2*)&g_aoh[i1] = hp1;  *(__half2*)&g_aol[i1] = lp1;
    }
}

// ------------------- launch ------------------------------------------------------
extern "C" void kernel_launch(void* const* d_in, const int* in_sizes, int n_in,
                              void* d_out, int out_size)
{
    const float* queries = (const float*)d_in[0];
    const float* keys    = (const float*)d_in[1];
    const float* values  = (const float*)d_in[2];
    const float* Wq_w = (const float*)d_in[3];  const float* Wq_b = (const float*)d_in[4];
    const float* Wk_w = (const float*)d_in[5];  const float* Wk_b = (const float*)d_in[6];
    const float* Wv_w = (const float*)d_in[7];  const float* Wv_b = (const float*)d_in[8];
    const float* Aq_w = (const float*)d_in[9];  const float* Aq_b = (const float*)d_in[10];
    const float* Bq_w = (const float*)d_in[11]; const float* Bq_b = (const float*)d_in[12];
    const float* Ak_w = (const float*)d_in[13]; const float* Ak_b = (const float*)d_in[14];
    const float* Bk_w = (const float*)d_in[15]; const float* Bk_b = (const float*)d_in[16];
    const float* Av_w = (const float*)d_in[17]; const float* Av_b = (const float*)d_in[18];
    const float* Bv_w = (const float*)d_in[19]; const float* Bv_b = (const float*)d_in[20];
    const float* Wo_w = (const float*)d_in[21]; const float* Wo_b = (const float*)d_in[22];
    float* out = (float*)d_out;

    cudaFuncSetAttribute(gemm_mma, cudaFuncAttributeMaxDynamicSharedMemorySize, GEMM_SMEM);
    cudaFuncSetAttribute(attn1_mma, cudaFuncAttributeMaxDynamicSharedMemorySize, A1_SMEM);
    cudaFuncSetAttribute(attn2_mma, cudaFuncAttributeMaxDynamicSharedMemorySize, F2_SMEM);

    void *pbeq, *pbek, *pbev, *pV, *pcs, *pKA;
    void *pqh, *pql, *pkh, *pkl, *pvh, *pvl, *paoh, *paol;
    void *pQph, *pQpl, *pKph, *pKpl;
    void *pwqh, *pwql, *pwkh, *pwkl, *pwvh, *pwvl, *pwoh, *pwol;
    cudaGetSymbolAddress(&pbeq, g_beq); cudaGetSymbolAddress(&pbek, g_bek);
    cudaGetSymbolAddress(&pbev, g_bev); cudaGetSymbolAddress(&pV, g_V);
    cudaGetSymbolAddress(&pcs, g_colsum); cudaGetSymbolAddress(&pKA, g_KA);
    cudaGetSymbolAddress(&pqh, g_qh); cudaGetSymbolAddress(&pql, g_ql);
    cudaGetSymbolAddress(&pkh, g_kh); cudaGetSymbolAddress(&pkl, g_kl);
    cudaGetSymbolAddress(&pvh, g_vh); cudaGetSymbolAddress(&pvl, g_vl);
    cudaGetSymbolAddress(&paoh, g_aoh); cudaGetSymbolAddress(&paol, g_aol);
    cudaGetSymbolAddress(&pQph, g_Qph); cudaGetSymbolAddress(&pQpl, g_Qpl);
    cudaGetSymbolAddress(&pKph, g_Kph); cudaGetSymbolAddress(&pKpl, g_Kpl);
    cudaGetSymbolAddress(&pwqh, g_wqh); cudaGetSymbolAddress(&pwql, g_wql);
    cudaGetSymbolAddress(&pwkh, g_wkh); cudaGetSymbolAddress(&pwkl, g_wkl);
    cudaGetSymbolAddress(&pwvh, g_wvh); cudaGetSymbolAddress(&pwvl, g_wvl);
    cudaGetSymbolAddress(&pwoh, g_woh); cudaGetSymbolAddress(&pwol, g_wol);

    ActArgs aa;
    aa.X[0] = queries; aa.X[1] = keys; aa.X[2] = values;
    aa.hi[0] = (__nv_bfloat16*)pqh; aa.hi[1] = (__nv_bfloat16*)pkh; aa.hi[2] = (__nv_bfloat16*)pvh;
    aa.lo[0] = (__nv_bfloat16*)pql; aa.lo[1] = (__nv_bfloat16*)pkl; aa.lo[2] = (__nv_bfloat16*)pvl;

    WprepArgs wa;
    wa.W[0] = Wq_w; wa.W[1] = Wk_w; wa.W[2] = Wv_w; wa.W[3] = Wo_w;
    wa.A[0] = Aq_w; wa.A[1] = Ak_w; wa.A[2] = nullptr; wa.A[3] = nullptr;
    wa.Bw[0] = Bq_w; wa.Bw[1] = Bk_w; wa.Bw[2] = nullptr; wa.Bw[3] = nullptr;
    wa.hi[0] = (__nv_bfloat16*)pwqh; wa.hi[1] = (__nv_bfloat16*)pwkh;
    wa.hi[2] = (__nv_bfloat16*)pwvh; wa.hi[3] = (__nv_bfloat16*)pwoh;
    wa.lo[0] = (__nv_bfloat16*)pwql; wa.lo[1] = (__nv_bfloat16*)pwkl;
    wa.lo[2] = (__nv_bfloat16*)pwvl; wa.lo[3] = (__nv_bfloat16*)pwol;

    BeffArgs ba;
    ba.Wb[0] = Wq_b; ba.Wb[1] = Wk_b; ba.Wb[2] = Wv_b;
    ba.Ab[0] = Aq_b; ba.Ab[1] = Ak_b; ba.Ab[2] = Av_b;
    ba.Bw[0] = Bq_w; ba.Bw[1] = Bk_w; ba.Bw[2] = Bv_w;
    ba.Bb[0] = Bq_b; ba.Bb[1] = Bk_b; ba.Bb[2] = Bv_b;
    ba.out[0] = (float*)pbeq; ba.out[1] = (float*)pbek; ba.out[2] = (float*)pbev;

    GemmArgs ga;
    ga.Ah[0] = (const __nv_bfloat16*)pqh;  ga.Al[0] = (const __nv_bfloat16*)pql;
    ga.Ah[1] = (const __nv_bfloat16*)pkh;  ga.Al[1] = (const __nv_bfloat16*)pkl;
    ga.Ah[2] = (const __nv_bfloat16*)pvh;  ga.Al[2] = (const __nv_bfloat16*)pvl;
    ga.Ah[3] = (const __nv_bfloat16*)paoh; ga.Al[3] = (const __nv_bfloat16*)paol;
    ga.Bh[0] = (const __nv_bfloat16*)pwqh; ga.Bl[0] = (const __nv_bfloat16*)pwql;
    ga.Bh[1] = (const __nv_bfloat16*)pwkh; ga.Bl[1] = (const __nv_bfloat16*)pwkl;
    ga.Bh[2] = (const __nv_bfloat16*)pwvh; ga.Bl[2] = (const __nv_bfloat16*)pwvl;
    ga.Bh[3] = (const __nv_bfloat16*)pwoh; ga.Bl[3] = (const __nv_bfloat16*)pwol;
    ga.bias[0] = (const float*)pbeq; ga.bias[1] = (const float*)pbek;
    ga.bias[2] = (const float*)pbev; ga.bias[3] = Wo_b;
    ga.outF[0] = nullptr; ga.outF[1] = nullptr; ga.outF[2] = (float*)pV; ga.outF[3] = out;
    ga.outH[0] = (__nv_bfloat16*)pQph; ga.outL[0] = (__nv_bfloat16*)pQpl;
    ga.outH[1] = (__nv_bfloat16*)pKph; ga.outL[1] = (__nv_bfloat16*)pKpl;
    ga.outH[2] = nullptr; ga.outL[2] = nullptr;
    ga.outH[3] = nullptr; ga.outL[3] = nullptr;
    ga.loraKA = (const float*)pKA; ga.loraB = Bv_w;

    actconv_kernel<<<dim3((TOK*DMODEL/4)/256, 1, 3), 256>>>(aa);          // 0
    wprep_kernel<<<dim3(DMODEL/32, HDIM/32, 4), 256>>>(wa);               // 1
    beff_kernel<<<dim3(HDIM/256, 1, 3), 256>>>(ba);                       // 2
    ka_kernel<<<TOK/8, 256>>>(keys, Av_w, (float*)pKA);                   // 3
    zero_kernel<<<(BB*NH*SS)/256, 256>>>((float*)pcs);                    // 4
    gemm_mma<<<dim3(HDIM/128, TOK/128, 3), 256, GEMM_SMEM>>>(ga, 0);      // 5: QKV fused
    attn1_mma<<<dim3(136, BB*NH), 256, A1_SMEM>>>();                      // 6
    vrt_kernel<<<dim3(SS/32, 2, BB*NH), 256>>>();                         // 7
    attn2_mma<<<dim3(16, BB*NH), 256, F2_SMEM>>>();                       // 8
    gemm_mma<<<dim3(HDIM/128, TOK/128, 1), 256, GEMM_SMEM>>>(ga, 3);      // 9: O
}

// round 17
// speedup vs baseline: 1.0800x; 1.0041x over previous
#include <cuda_runtime.h>
#include <cuda_bf16.h>
#include <cuda_fp16.h>
#include <math.h>
#include <stdint.h>

#define BB     4
#define SS     2048
#define DMODEL 1024
#define NH     16
#define HD     64
#define HDIM   1024
#define RK     8
#define TOK    (BB*SS)   // 8192

// ------------------- device scratch (static; allocation-free) -------------------
__device__ float g_beq[HDIM];
__device__ float g_bek[HDIM];
__device__ float g_bev[HDIM];
__device__ float g_V[(size_t)TOK*HDIM];
__device__ float g_colsum[(size_t)BB*NH*SS];
__device__ float g_KA[(size_t)TOK*RK];

// 16-bit buffers; z<2 hold bf16 hi/lo, z>=2 hold f16 hi/lo (reinterpreted)
__device__ __nv_bfloat16 g_qh[(size_t)TOK*DMODEL], g_ql[(size_t)TOK*DMODEL];
__device__ __nv_bfloat16 g_kh[(size_t)TOK*DMODEL], g_kl[(size_t)TOK*DMODEL];
__device__ __nv_bfloat16 g_vh[(size_t)TOK*DMODEL], g_vl[(size_t)TOK*DMODEL];   // f16
__device__ __nv_bfloat16 g_Qph[(size_t)TOK*HDIM], g_Qpl[(size_t)TOK*HDIM];
__device__ __nv_bfloat16 g_Kph[(size_t)TOK*HDIM], g_Kpl[(size_t)TOK*HDIM];
__device__ __nv_bfloat16 g_aoh[(size_t)TOK*HDIM], g_aol[(size_t)TOK*HDIM];     // f16
__device__ __nv_bfloat16 g_Vrth[(size_t)BB*NH*64*SS];
__device__ __nv_bfloat16 g_Vrtl[(size_t)BB*NH*64*SS];
__device__ __nv_bfloat16 g_wqh[DMODEL*HDIM], g_wql[DMODEL*HDIM];
__device__ __nv_bfloat16 g_wkh[DMODEL*HDIM], g_wkl[DMODEL*HDIM];
__device__ __nv_bfloat16 g_wvh[DMODEL*HDIM], g_wvl[DMODEL*HDIM];               // f16
__device__ __nv_bfloat16 g_woh[DMODEL*HDIM], g_wol[DMODEL*HDIM];               // f16

// ------------------- helpers ------------------------------------------------------
__device__ __forceinline__ uint32_t smem_u32(const void* p) {
    uint32_t a;
    asm("{ .reg .u64 t; cvta.to.shared.u64 t, %1; cvt.u32.u64 %0, t; }" : "=r"(a) : "l"(p));
    return a;
}
__device__ __forceinline__ void cpa16(uint32_t dst, const void* src) {
    asm volatile("cp.async.cg.shared.global [%0], [%1], 16;"
                 :: "r"(dst), "l"(__cvta_generic_to_global(src)));
}
#define CPA_COMMIT() asm volatile("cp.async.commit_group;")
#define CPA_WAIT2()  asm volatile("cp.async.wait_group 2;")
#define CPA_WAIT1()  asm volatile("cp.async.wait_group 1;")
#define CPA_WAIT0()  asm volatile("cp.async.wait_group 0;")

#define LDSM4(r, a) \
    asm volatile("ldmatrix.sync.aligned.m8n8.x4.shared.b16 {%0,%1,%2,%3}, [%4];" \
        : "=r"((r)[0]), "=r"((r)[1]), "=r"((r)[2]), "=r"((r)[3]) : "r"(a))

#define MMA16816(c, a, b0, b1) \
    asm volatile("mma.sync.aligned.m16n8k16.row.col.f32.bf16.bf16.f32 " \
        "{%0,%1,%2,%3}, {%4,%5,%6,%7}, {%8,%9}, {%0,%1,%2,%3};" \
        : "+f"((c)[0]), "+f"((c)[1]), "+f"((c)[2]), "+f"((c)[3]) \
        : "r"((a)[0]), "r"((a)[1]), "r"((a)[2]), "r"((a)[3]), "r"(b0), "r"(b1))

#define MMAF16(c, a, b0, b1) \
    asm volatile("mma.sync.aligned.m16n8k16.row.col.f32.f16.f16.f32 " \
        "{%0,%1,%2,%3}, {%4,%5,%6,%7}, {%8,%9}, {%0,%1,%2,%3};" \
        : "+f"((c)[0]), "+f"((c)[1]), "+f"((c)[2]), "+f"((c)[3]) \
        : "r"((a)[0]), "r"((a)[1]), "r"((a)[2]), "r"((a)[3]), "r"(b0), "r"(b1))

__device__ __forceinline__ uint32_t cvt_bf2(float lo, float hi) {
    uint32_t r;
    asm("cvt.rn.bf16x2.f32 %0, %1, %2;" : "=r"(r) : "f"(hi), "f"(lo));
    return r;
}

#define SWZ128(x) ((x) ^ (((x) >> 3) & 0x70))
__device__ __forceinline__ uint32_t swz_off(int row, int chunk) {
    uint32_t o = (uint32_t)((row >> 1) * 128 + (row & 1) * 64 + chunk * 16);
    return SWZ128(o);
}

// ------------------- fused prep kernels -------------------------------------------
struct ActArgs { const float* X[3]; __nv_bfloat16 *hi[3], *lo[3]; };
__global__ void actconv_kernel(ActArgs aa)
{
    int z = blockIdx.z;
    const float* X = aa.X[z];
    size_t i = ((size_t)blockIdx.x * 256 + threadIdx.x) * 4;
    float4 v = *(const float4*)&X[i];
    if (z < 2) {
        __nv_bfloat16* hi = aa.hi[z];
        __nv_bfloat16* lo = aa.lo[z];
        __nv_bfloat16 h0 = __float2bfloat16(v.x), h1 = __float2bfloat16(v.y);
        __nv_bfloat16 h2 = __float2bfloat16(v.z), h3 = __float2bfloat16(v.w);
        __nv_bfloat162 ph0 = {h0, h1}, ph1 = {h2, h3};
        __nv_bfloat162 pl0 = {__float2bfloat16(v.x - __bfloat162float(h0)),
                              __float2bfloat16(v.y - __bfloat162float(h1))};
        __nv_bfloat162 pl1 = {__float2bfloat16(v.z - __bfloat162float(h2)),
                              __float2bfloat16(v.w - __bfloat162float(h3))};
        *(__nv_bfloat162*)&hi[i]   = ph0;  *(__nv_bfloat162*)&hi[i+2] = ph1;
        *(__nv_bfloat162*)&lo[i]   = pl0;  *(__nv_bfloat162*)&lo[i+2] = pl1;
    } else {
        __half* hi = (__half*)aa.hi[z];
        __half* lo = (__half*)aa.lo[z];
        __half h0 = __float2half_rn(v.x), h1 = __float2half_rn(v.y);
        __half h2 = __float2half_rn(v.z), h3 = __float2half_rn(v.w);
        __half2 ph0 = {h0, h1}, ph1 = {h2, h3};
        __half2 pl0 = {__float2half_rn(v.x - __half2float(h0)),
                       __float2half_rn(v.y - __half2float(h1))};
        __half2 pl1 = {__float2half_rn(v.z - __half2float(h2)),
                       __float2half_rn(v.w - __half2float(h3))};
        *(__half2*)&hi[i]   = ph0;  *(__half2*)&hi[i+2] = ph1;
        *(__half2*)&lo[i]   = pl0;  *(__half2*)&lo[i+2] = pl1;
    }
}

struct WprepArgs { const float *W[4], *A[4], *Bw[4]; __nv_bfloat16 *hi[4], *lo[4]; };
__global__ __launch_bounds__(256) void wprep_kernel(WprepArgs wa)
{
    __shared__ float t[32][33];
    int z = blockIdx.z;
    const float* W = wa.W[z];
    const float* A = wa.A[z];
    const float* Bw = wa.Bw[z];
    int kb = blockIdx.x * 32, nb = blockIdx.y * 32;
    int x = threadIdx.x & 31, y = threadIdx.x >> 5;
#pragma unroll
    for (int i = y; i < 32; i += 8) {
        int k = kb + i, n = nb + x;
        float v = W[(size_t)k*HDIM + n];
        if (A) {
#pragma unroll
            for (int r = 0; r < RK; r++) v += A[k*RK + r] * Bw[r*HDIM + n];
        }
        t[i][x] = v;
    }
    __syncthreads();
    if (z < 2) {
        __nv_bfloat16* hi = wa.hi[z];
        __nv_bfloat16* lo = wa.lo[z];
#pragma unroll
        for (int i = y; i < 32; i += 8) {
            int n = nb + i, k = kb + x;
            float v = t[x][i];
            __nv_bfloat16 h = __float2bfloat16(v);
            hi[(size_t)n*DMODEL + k] = h;
            lo[(size_t)n*DMODEL + k] = __float2bfloat16(v - __bfloat162float(h));
        }
    } else {
        __half* hi = (__half*)wa.hi[z];
        __half* lo = (__half*)wa.lo[z];
#pragma unroll
        for (int i = y; i < 32; i += 8) {
            int n = nb + i, k = kb + x;
            float v = t[x][i];
            __half h = __float2half_rn(v);
            hi[(size_t)n*DMODEL + k] = h;
            lo[(size_t)n*DMODEL + k] = __float2half_rn(v - __half2float(h));
        }
    }
}

struct BeffArgs { const float *Wb[3], *Ab[3], *Bw[3], *Bb[3]; float* out[3]; };
__global__ void beff_kernel(BeffArgs ba)
{
    int z = blockIdx.z;
    int j = blockIdx.x * 256 + threadIdx.x;
    float acc = ba.Wb[z][j] + ba.Bb[z][j];
    const float* Ab = ba.Ab[z];
    const float* Bw = ba.Bw[z];
#pragma unroll
    for (int r = 0; r < RK; r++) acc += Ab[r] * Bw[r*HDIM + j];
    ba.out[z][j] = acc;
}

// ka + colsum-zero fused: each block zeros its 128-float colsum slice.
__global__ __launch_bounds__(256) void ka_kernel(const float* __restrict__ keys,
                                                 const float* __restrict__ Av,
                                                 float* __restrict__ KA,
                                                 float* __restrict__ colsum)
{
    __shared__ float avT[RK][DMODEL];
    int tid = threadIdx.x;
    // zero colsum slice (BB*NH*SS = 131072 floats / 1024 blocks = 128 per block)
    if (tid < 128)
        colsum[(size_t)blockIdx.x * 128 + tid] = 0.f;
#pragma unroll
    for (int f = tid; f < DMODEL*RK/4; f += 256) {
        int k = f >> 1, j = (f & 1) * 4;
        float4 v = ((const float4*)Av)[f];
        avT[j+0][k] = v.x; avT[j+1][k] = v.y;
        avT[j+2][k] = v.z; avT[j+3][k] = v.w;
    }
    __syncthreads();

    int warp = tid >> 5, lane = tid & 31;
    int row = blockIdx.x * 8 + warp;
    const float4* kr = (const float4*)(keys + (size_t)row * DMODEL);
    float acc[RK];
#pragma unroll
    for (int r = 0; r < RK; r++) acc[r] = 0.f;
#pragma unroll
    for (int i = 0; i < 8; i++) {
        int k4 = lane + i * 32;
        float4 kv = kr[k4];
        int k = 4 * k4;
#pragma unroll
        for (int r = 0; r < RK; r++) {
            float4 av = *(const float4*)&avT[r][k];
            acc[r] += kv.x*av.x + kv.y*av.y + kv.z*av.z + kv.w*av.w;
        }
    }
#pragma unroll
    for (int r = 0; r < RK; r++) {
#pragma unroll
        for (int off = 16; off > 0; off >>= 1)
            acc[r] += __shfl_down_sync(0xffffffffu, acc[r], off);
    }
    if (lane == 0) {
#pragma unroll
        for (int r = 0; r < RK; r++) KA[(size_t)row*RK + r] = acc[r];
    }
}

// ------------------- fused mma.sync GEMM: bf16 3-prod (z<2, 3-stage) /
//                     f16 2-prod (z>=2, 4-stage: stage = 3 tiles only) ------------
static constexpr int G_TILE  = 8192;
static constexpr int GEMM_SMEM = 98304;   // bf16: 3 x 32KB; f16: 4 x 24KB

struct GemmArgs {
    const __nv_bfloat16 *Ah[4], *Al[4], *Bh[4], *Bl[4];
    const float* bias[4];
    float* outF[4];
    __nv_bfloat16 *outH[4], *outL[4];
    const float *loraKA, *loraB;
};

__global__ __launch_bounds__(256, 2)
void gemm_mma(GemmArgs ga, int op)
{
    extern __shared__ char smem[];
    const uint32_t sb = smem_u32(smem);
    const int z = (op == 0) ? blockIdx.z : op;
    const bool F16 = (z >= 2);
    const uint32_t STG = F16 ? (uint32_t)(3*G_TILE) : (uint32_t)(4*G_TILE);
    const __nv_bfloat16* Ah = ga.Ah[z];
    const __nv_bfloat16* Al = ga.Al[z];
    const __nv_bfloat16* Bh = ga.Bh[z];
    const __nv_bfloat16* Bl = ga.Bl[z];
    const float* bias = ga.bias[z];
    float* outF = ga.outF[z];
    __nv_bfloat16* outH = ga.outH[z];
    __nv_bfloat16* outL = ga.outL[z];
    const float* loraKA = (z == 2) ? ga.loraKA : nullptr;
    const float* loraB  = ga.loraB;

    const int tid  = threadIdx.x;
    const int lane = tid & 31;
    const int warp = tid >> 5;
    const int wm = warp >> 2, wn = warp & 3;
    const int m0 = blockIdx.y * 128, n0 = blockIdx.x * 128;

    float acc[4][4][4];
#pragma unroll
    for (int i = 0; i < 4; i++)
#pragma unroll
        for (int j = 0; j < 4; j++)
#pragma unroll
            for (int k = 0; k < 4; k++) acc[i][j][k] = 0.f;

    auto load_stage = [&](int st, int chunk) {
        int k0 = chunk * 32;
        const __nv_bfloat16* tp[4] = {Ah, Al, Bh, Bl};
        uint32_t sbase = sb + st * STG;
#pragma unroll
        for (int i = 0; i < 8; i++) {
            const int t = i >> 1;
            if (F16 && t == 3) continue;
            int j = (i & 1) ? tid + 256 : tid;
            int row = j >> 2, sg = j & 3;
            int r0 = (t < 2) ? m0 : n0;
            cpa16(sbase + t * G_TILE + swz_off(row, sg),
                  tp[t] + (size_t)(r0 + row) * 1024 + k0 + sg * 8);
        }
    };

    auto compute_stage = [&](int st) {
        uint32_t ab = sb + st * STG;
#pragma unroll
        for (int kk = 0; kk < 2; kk++) {
            uint32_t ahr[4][4], alr[4][4], bh2[4][2], bl2[4][2];
            int arow = wm*64 + (lane & 15);
            int ac   = kk*2 + (lane >> 4);
            uint32_t abase = ab + swz_off(arow, ac);
#pragma unroll
            for (int mt = 0; mt < 4; mt++) {
                LDSM4(ahr[mt], abase + mt * 1024);
                LDSM4(alr[mt], abase + G_TILE + mt * 1024);
            }
            int brow = wn*32 + (lane & 7) + ((lane >> 4) << 3);
            int bc   = kk*2 + ((lane >> 3) & 1);
            uint32_t bbase = ab + 2*G_TILE + swz_off(brow, bc);
            {
                uint32_t t0[4], t1[4];
                LDSM4(t0, bbase);
                LDSM4(t1, bbase + 1024);
                bh2[0][0]=t0[0]; bh2[0][1]=t0[1]; bh2[1][0]=t0[2]; bh2[1][1]=t0[3];
                bh2[2][0]=t1[0]; bh2[2][1]=t1[1]; bh2[3][0]=t1[2]; bh2[3][1]=t1[3];
                if (!F16) {
                    LDSM4(t0, bbase + G_TILE);
                    LDSM4(t1, bbase + G_TILE + 1024);
                    bl2[0][0]=t0[0]; bl2[0][1]=t0[1]; bl2[1][0]=t0[2]; bl2[1][1]=t0[3];
                    bl2[2][0]=t1[0]; bl2[2][1]=t1[1]; bl2[3][0]=t1[2]; bl2[3][1]=t1[3];
                }
            }
            if (!F16) {
#pragma unroll
                for (int mt = 0; mt < 4; mt++)
#pragma unroll
                    for (int nt = 0; nt < 4; nt++) {
                        MMA16816(acc[mt][nt], ahr[mt], bh2[nt][0], bh2[nt][1]);
                        MMA16816(acc[mt][nt], ahr[mt], bl2[nt][0], bl2[nt][1]);
                        MMA16816(acc[mt][nt], alr[mt], bh2[nt][0], bh2[nt][1]);
                    }
            } else {
#pragma unroll
                for (int mt = 0; mt < 4; mt++)
#pragma unroll
                    for (int nt = 0; nt < 4; nt++) {
                        MMAF16(acc[mt][nt], ahr[mt], bh2[nt][0], bh2[nt][1]);
                        MMAF16(acc[mt][nt], alr[mt], bh2[nt][0], bh2[nt][1]);
                    }
            }
        }
    };

    if (!F16) {
        load_stage(0, 0); CPA_COMMIT();
        load_stage(1, 1); CPA_COMMIT();
#pragma unroll 1
        for (int c = 0; c < 32; c++) {
            CPA_WAIT1();
            __syncthreads();
            if (c + 2 < 32) load_stage((c + 2) % 3, c + 2);
            CPA_COMMIT();
            compute_stage(c % 3);
        }
    } else {
        load_stage(0, 0); CPA_COMMIT();
        load_stage(1, 1); CPA_COMMIT();
        load_stage(2, 2); CPA_COMMIT();
#pragma unroll 1
        for (int c = 0; c < 32; c++) {
            CPA_WAIT2();
            __syncthreads();
            if (c + 3 < 32) load_stage((c + 3) & 3, c + 3);
            CPA_COMMIT();
            compute_stage(c & 3);
        }
    }

    int r_ = lane >> 2, c_ = (lane & 3) * 2;
#pragma unroll
    for (int mt = 0; mt < 4; mt++) {
        int row = m0 + wm*64 + mt*16 + r_;
        float ka0[RK], ka1[RK];
        if (loraKA) {
#pragma unroll
            for (int r = 0; r < RK; r++) {
                ka0[r] = loraKA[(size_t)row*RK + r];
                ka1[r] = loraKA[(size_t)(row+8)*RK + r];
            }
        }
#pragma unroll
        for (int nt = 0; nt < 4; nt++) {
            int col = n0 + wn*32 + nt*8 + c_;
            float b0 = bias[col], b1 = bias[col + 1];
            float v00 = acc[mt][nt][0] + b0, v01 = acc[mt][nt][1] + b1;
            float v10 = acc[mt][nt][2] + b0, v11 = acc[mt][nt][3] + b1;
            if (loraKA) {
#pragma unroll
                for (int r = 0; r < RK; r++) {
                    float w0 = loraB[r*HDIM + col], w1 = loraB[r*HDIM + col + 1];
                    v00 += ka0[r] * w0;  v01 += ka0[r] * w1;
                    v10 += ka1[r] * w0;  v11 += ka1[r] * w1;
                }
            }
            if (outF) {
                *(float2*)&outF[(size_t)row * 1024 + col] = {v00, v01};
                *(float2*)&outF[(size_t)(row + 8) * 1024 + col] = {v10, v11};
            } else {
                __nv_bfloat16 h00 = __float2bfloat16(v00), h01 = __float2bfloat16(v01);
                __nv_bfloat16 h10 = __float2bfloat16(v10), h11 = __float2bfloat16(v11);
                __nv_bfloat162 hp0 = {h00, h01}, hp1 = {h10, h11};
                __nv_bfloat162 lp0 = {__float2bfloat16(v00 - __bfloat162float(h00)),
                                      __float2bfloat16(v01 - __bfloat162float(h01))};
                __nv_bfloat162 lp1 = {__float2bfloat16(v10 - __bfloat162float(h10)),
                                      __float2bfloat16(v11 - __bfloat162float(h11))};
                *(__nv_bfloat162*)&outH[(size_t)row * 1024 + col] = hp0;
                *(__nv_bfloat162*)&outH[(size_t)(row + 8) * 1024 + col] = hp1;
                *(__nv_bfloat162*)&outL[(size_t)row * 1024 + col] = lp0;
                *(__nv_bfloat162*)&outL[(size_t)(row + 8) * 1024 + col] = lp1;
            }
        }
    }
}

// ------------------- pass 1 (slim): column sums of exp(QK^T) masked --------------
static constexpr int A1_PITCH = 144;
static constexpr int A1_TILE  = 128 * A1_PITCH;
static constexpr int A1_SMEM  = 4 * A1_TILE;

__global__ __launch_bounds__(256, 2) void attn1_mma()
{
    extern __shared__ char smem[];
    int idx = blockIdx.x;
    int qt = (int)((sqrtf(8.f*idx + 1.f) - 1.f) * 0.5f);
    if ((qt+1)*(qt+2)/2 <= idx) qt++;
    if (qt*(qt+1)/2 > idx) qt--;
    int kt = idx - qt*(qt+1)/2;
    int bh = blockIdx.y;
    const uint32_t sb = smem_u32(smem);
    int b = bh >> 4, h = bh & 15;
    int q0 = qt * 128, k0 = kt * 128;
    int tid = threadIdx.x, lane = tid & 31, warp = tid >> 5;
    int wm = warp >> 2, wn = warp & 3;

    {
        const __nv_bfloat16* tp[4] = {g_Qph, g_Qpl, g_Kph, g_Kpl};
#pragma unroll
        for (int tt = 0; tt < 2; tt++) {
            int t = tt * 2;
            int r0 = (t < 2) ? q0 : k0;
#pragma unroll
            for (int i = 0; i < 4; i++) {
                int ix = tid + i * 256;
                int row = ix >> 3, sg = ix & 7;
                cpa16(sb + t * A1_TILE + row * A1_PITCH + sg * 16,
                      tp[t] + (size_t)(b*SS + r0 + row) * 1024 + h*64 + sg * 8);
            }
        }
        CPA_COMMIT();
#pragma unroll
        for (int tt = 0; tt < 2; tt++) {
            int t = tt * 2 + 1;
            int r0 = (t < 2) ? q0 : k0;
#pragma unroll
            for (int i = 0; i < 4; i++) {
                int ix = tid + i * 256;
                int row = ix >> 3, sg = ix & 7;
                cpa16(sb + t * A1_TILE + row * A1_PITCH + sg * 16,
                      tp[t] + (size_t)(b*SS + r0 + row) * 1024 + h*64 + sg * 8);
            }
        }
        CPA_COMMIT();
    }

    float acc[4][4][4];
#pragma unroll
    for (int i = 0; i < 4; i++)
#pragma unroll
        for (int j = 0; j < 4; j++)
#pragma unroll
            for (int k = 0; k < 4; k++) acc[i][j][k] = 0.f;

    // phase A: hi x hi while lo tiles stream
    CPA_WAIT1();
    __syncthreads();
#pragma unroll
    for (int kk = 0; kk < 4; kk++) {
        uint32_t ahr[4][4], bhf[4][2];
        uint32_t aoff = (uint32_t)(wm*64 + (lane & 15)) * A1_PITCH
                      + (uint32_t)(kk*16 + (lane >> 4) * 8) * 2;
#pragma unroll
        for (int mt = 0; mt < 4; mt++)
            LDSM4(ahr[mt], sb + aoff + mt * (16*A1_PITCH));
        uint32_t boff = (uint32_t)(wn*32 + (lane & 7) + ((lane >> 4) << 3)) * A1_PITCH
                      + (uint32_t)(kk*16 + ((lane >> 3) & 1) * 8) * 2;
        {
            uint32_t t0[4], t1[4];
            LDSM4(t0, sb + 2*A1_TILE + boff);
            LDSM4(t1, sb + 2*A1_TILE + boff + 16*A1_PITCH);
            bhf[0][0]=t0[0]; bhf[0][1]=t0[1]; bhf[1][0]=t0[2]; bhf[1][1]=t0[3];
            bhf[2][0]=t1[0]; bhf[2][1]=t1[1]; bhf[3][0]=t1[2]; bhf[3][1]=t1[3];
        }
#pragma unroll
        for (int mt = 0; mt < 4; mt++)
#pragma unroll
            for (int nt = 0; nt < 4; nt++)
                MMA16816(acc[mt][nt], ahr[mt], bhf[nt][0], bhf[nt][1]);
    }

    // phase B: cross products
    CPA_WAIT0();
    __syncthreads();
#pragma unroll
    for (int kk = 0; kk < 4; kk++) {
        uint32_t ahr[4][4], alr[4][4], bhf[4][2], blf[4][2];
        uint32_t aoff = (uint32_t)(wm*64 + (lane & 15)) * A1_PITCH
                      + (uint32_t)(kk*16 + (lane >> 4) * 8) * 2;
#pragma unroll
        for (int mt = 0; mt < 4; mt++) {
            LDSM4(ahr[mt], sb + aoff + mt * (16*A1_PITCH));
            LDSM4(alr[mt], sb + A1_TILE + aoff + mt * (16*A1_PITCH));
        }
        uint32_t boff = (uint32_t)(wn*32 + (lane & 7) + ((lane >> 4) << 3)) * A1_PITCH
                      + (uint32_t)(kk*16 + ((lane >> 3) & 1) * 8) * 2;
        {
            uint32_t t0[4], t1[4];
            LDSM4(t0, sb + 2*A1_TILE + boff);
            LDSM4(t1, sb + 2*A1_TILE + boff + 16*A1_PITCH);
            bhf[0][0]=t0[0]; bhf[0][1]=t0[1]; bhf[1][0]=t0[2]; bhf[1][1]=t0[3];
            bhf[2][0]=t1[0]; bhf[2][1]=t1[1]; bhf[3][0]=t1[2]; bhf[3][1]=t1[3];
            LDSM4(t0, sb + 3*A1_TILE + boff);
            LDSM4(t1, sb + 3*A1_TILE + boff + 16*A1_PITCH);
            blf[0][0]=t0[0]; blf[0][1]=t0[1]; blf[1][0]=t0[2]; blf[1][1]=t0[3];
            blf[2][0]=t1[0]; blf[2][1]=t1[1]; blf[3][0]=t1[2]; blf[3][1]=t1[3];
        }
#pragma unroll
        for (int mt = 0; mt < 4; mt++)
#pragma unroll
            for (int nt = 0; nt < 4; nt++) {
                MMA16816(acc[mt][nt], ahr[mt], blf[nt][0], blf[nt][1]);
                MMA16816(acc[mt][nt], alr[mt], bhf[nt][0], bhf[nt][1]);
            }
    }

    __syncthreads();
    float* cs = (float*)smem;
    if (tid < 128) cs[tid] = 0.f;
    __syncthreads();

    const bool diag = (qt == kt);
    int r_ = lane >> 2, c_ = (lane & 3) * 2;
    float cs0[4] = {0,0,0,0}, cs1[4] = {0,0,0,0};
#pragma unroll
    for (int mt = 0; mt < 4; mt++) {
        int qb = q0 + wm*64 + mt*16;
#pragma unroll
        for (int nt = 0; nt < 4; nt++) {
            int k = k0 + wn*32 + nt*8 + c_;
            float e00 = __expf(acc[mt][nt][0]);
            float e01 = __expf(acc[mt][nt][1]);
            float e10 = __expf(acc[mt][nt][2]);
            float e11 = __expf(acc[mt][nt][3]);
            int qr0 = qb + r_, qr1 = qb + r_ + 8;
            if (diag) {
                if (qr0 < k)     e00 = 0.f;
                if (qr0 < k + 1) e01 = 0.f;
                if (qr1 < k)     e10 = 0.f;
                if (qr1 < k + 1) e11 = 0.f;
            }
            cs0[nt] += e00 + e10;
            cs1[nt] += e01 + e11;
        }
    }
#pragma unroll
    for (int nt = 0; nt < 4; nt++) {
        atomicAdd(&cs[wn*32 + nt*8 + c_],     cs0[nt]);
        atomicAdd(&cs[wn*32 + nt*8 + c_ + 1], cs1[nt]);
    }
    __syncthreads();
    if (tid < 128)
        atomicAdd(&g_colsum[(size_t)bh*SS + k0 + tid], cs[tid]);
}

// ------------------- Vrt prep: bf16 hi/lo ----------------------------------------
__global__ __launch_bounds__(256) void vrt_kernel()
{
    __shared__ float t[32][33];
    int kt = blockIdx.x, dt = blockIdx.y, bh = blockIdx.z;
    int b = bh >> 4, h = bh & 15;
    int k0 = kt * 32, d0 = dt * 32;
    int x = threadIdx.x & 31, y = threadIdx.x >> 5;
#pragma unroll
    for (int i = y; i < 32; i += 8) {
        int k = k0 + i;
        float r = 1.0f / (g_colsum[(size_t)bh*SS + k] * 8.0f);
        t[i][x] = g_V[(size_t)(b*SS + k) * HDIM + h*64 + d0 + x] * r;
    }
    __syncthreads();
#pragma unroll
    for (int i = y; i < 32; i += 8) {
        int d = d0 + i, k = k0 + x;
        float v = t[x][i];
        __nv_bfloat16 hh = __float2bfloat16(v);
        size_t idx = ((size_t)bh*64 + d) * SS + k;
        g_Vrth[idx] = hh;
        g_Vrtl[idx] = __float2bfloat16(v - __bfloat162float(hh));
    }
}

// ------------------- pass 2 (flash): recompute P = exp(QK^T), out = P @ Vrt^T ----
static constexpr int F2_QTILE = 16384;
static constexpr int F2_KTILE = 4096;
static constexpr int F2_VTILE = 4096;
static constexpr int F2_STAGE = 2*F2_KTILE + 2*F2_VTILE;
static constexpr int F2_SMEM  = 2*F2_QTILE + 4*F2_STAGE;      // 98304

__global__ __launch_bounds__(256, 2) void attn2_mma()
{
    extern __shared__ char smem[];
    const uint32_t sb = smem_u32(smem);
    int qt = (int)gridDim.x - 1 - (int)blockIdx.x;
    int bh = blockIdx.y;
    int b = bh >> 4, h = bh & 15;
    int q0 = qt * 128;
    int tid = threadIdx.x, lane = tid & 31, warp = tid >> 5;
    int nch = (qt + 1) * 4;

    const uint32_t qbh = sb;
    const uint32_t qbl = sb + F2_QTILE;
    const uint32_t stb = sb + 2*F2_QTILE;

#pragma unroll
    for (int i = 0; i < 4; i++) {
        int ix = tid + i * 256;
        int row = ix >> 3, sg = ix & 7;
        size_t gi = (size_t)(b*SS + q0 + row) * 1024 + h*64 + sg * 8;
        uint32_t off = SWZ128((uint32_t)(row * 128 + sg * 16));
        cpa16(qbh + off, &g_Qph[gi]);
        cpa16(qbl + off, &g_Qpl[gi]);
    }

    auto load_stage = [&](int st, int c) {
        int k0 = c * 32;
        uint32_t s = stb + st * F2_STAGE;
        {
            int row = tid >> 3, sg = tid & 7;
            size_t gi = (size_t)(b*SS + k0 + row) * 1024 + h*64 + sg * 8;
            uint32_t off = SWZ128((uint32_t)(row * 128 + sg * 16));
            cpa16(s + off, &g_Kph[gi]);
            cpa16(s + F2_KTILE + off, &g_Kpl[gi]);
        }
        {
            int row = tid >> 2, sg = tid & 3;
            size_t gi = ((size_t)bh*64 + row) * SS + k0 + sg * 8;
            uint32_t off = swz_off(row, sg);
            cpa16(s + 2*F2_KTILE + off, &g_Vrth[gi]);
            cpa16(s + 2*F2_KTILE + F2_VTILE + off, &g_Vrtl[gi]);
        }
    };

    load_stage(0, 0); CPA_COMMIT();
    load_stage(1, 1); CPA_COMMIT();
    load_stage(2, 2); CPA_COMMIT();

    float oacc[8][4];
#pragma unroll
    for (int i = 0; i < 8; i++)
#pragma unroll
        for (int j = 0; j < 4; j++) oacc[i][j] = 0.f;

    const int r_ = lane >> 2, t2 = (lane & 3) * 2;
    const int qrow = q0 + warp*16 + r_;

    // Q fragments hoisted: peel the group-0 wait before the loop
    uint32_t qfh[4][4], qfl[4][4];
    CPA_WAIT2();
    __syncthreads();
#pragma unroll
    for (int kk = 0; kk < 4; kk++) {
        uint32_t arow = (uint32_t)(warp*16 + (lane & 15));
        uint32_t aoff = SWZ128(arow * 128 + (uint32_t)(kk*32 + (lane >> 4) * 16));
        LDSM4(qfh[kk], qbh + aoff);
        LDSM4(qfl[kk], qbl + aoff);
    }

#pragma unroll 1
    for (int c = 0; c < nch; c++) {
        CPA_WAIT2();
        __syncthreads();
        if (c + 3 < nch) load_stage((c + 3) & 3, c + 3);
        CPA_COMMIT();
        uint32_t s = stb + (c & 3) * F2_STAGE;
        int k0 = c * 32;

        float sacc[4][4];
#pragma unroll
        for (int i = 0; i < 4; i++)
#pragma unroll
            for (int j = 0; j < 4; j++) sacc[i][j] = 0.f;

#pragma unroll
        for (int kk = 0; kk < 4; kk++) {
            uint32_t bh2[4][2], bl2[4][2];
            uint32_t brow = (uint32_t)((lane & 7) + ((lane >> 4) << 3));
            uint32_t bcol = (uint32_t)(kk*32 + ((lane >> 3) & 1) * 16);
            {
                uint32_t t0[4], t1[4];
                LDSM4(t0, s + SWZ128(brow * 128 + bcol));
                LDSM4(t1, s + SWZ128((brow + 16) * 128 + bcol));
                bh2[0][0]=t0[0]; bh2[0][1]=t0[1]; bh2[1][0]=t0[2]; bh2[1][1]=t0[3];
                bh2[2][0]=t1[0]; bh2[2][1]=t1[1]; bh2[3][0]=t1[2]; bh2[3][1]=t1[3];
                LDSM4(t0, s + F2_KTILE + SWZ128(brow * 128 + bcol));
                LDSM4(t1, s + F2_KTILE + SWZ128((brow + 16) * 128 + bcol));
                bl2[0][0]=t0[0]; bl2[0][1]=t0[1]; bl2[1][0]=t0[2]; bl2[1][1]=t0[3];
                bl2[2][0]=t1[0]; bl2[2][1]=t1[1]; bl2[3][0]=t1[2]; bl2[3][1]=t1[3];
            }
#pragma unroll
            for (int nt = 0; nt < 4; nt++) {
                MMA16816(sacc[nt], qfh[kk], bh2[nt][0], bh2[nt][1]);
                MMA16816(sacc[nt], qfh[kk], bl2[nt][0], bl2[nt][1]);
                MMA16816(sacc[nt], qfl[kk], bh2[nt][0], bh2[nt][1]);
            }
        }

        uint32_t pah[2][4], pal[2][4];
        const bool needmask = (k0 + 32 > q0 + warp*16);
#pragma unroll
        for (int nf = 0; nf < 4; nf++) {
            int kc = k0 + nf*8 + t2;
            float e0 = __expf(sacc[nf][0]);
            float e1 = __expf(sacc[nf][1]);
            float e2 = __expf(sacc[nf][2]);
            float e3 = __expf(sacc[nf][3]);
            if (needmask) {
                if (kc     > qrow)     e0 = 0.f;
                if (kc + 1 > qrow)     e1 = 0.f;
                if (kc     > qrow + 8) e2 = 0.f;
                if (kc + 1 > qrow + 8) e3 = 0.f;
            }
            uint32_t p0 = cvt_bf2(e0, e1);
            uint32_t p1 = cvt_bf2(e2, e3);
            float h0 = __uint_as_float(p0 << 16);
            float h1 = __uint_as_float(p0 & 0xFFFF0000u);
            float h2 = __uint_as_float(p1 << 16);
            float h3 = __uint_as_float(p1 & 0xFFFF0000u);
            int kk2 = nf >> 1;
            int ro  = (nf & 1) * 2;
            pah[kk2][ro+0] = p0;
            pah[kk2][ro+1] = p1;
            pal[kk2][ro+0] = cvt_bf2(e0 - h0, e1 - h1);
            pal[kk2][ro+1] = cvt_bf2(e2 - h2, e3 - h3);
        }

#pragma unroll
        for (int kk2 = 0; kk2 < 2; kk2++) {
            int brow = (lane & 7) + ((lane >> 4) << 3);
            int bc = kk2*2 + ((lane >> 3) & 1);
#pragma unroll
            for (int g = 0; g < 4; g++) {
                uint32_t th[4], tl[4];
                LDSM4(th, s + 2*F2_KTILE + swz_off(brow + g*16, bc));
                LDSM4(tl, s + 2*F2_KTILE + F2_VTILE + swz_off(brow + g*16, bc));
                MMA16816(oacc[2*g],   pah[kk2], th[0], th[1]);
                MMA16816(oacc[2*g],   pah[kk2], tl[0], tl[1]);
                MMA16816(oacc[2*g],   pal[kk2], th[0], th[1]);
                MMA16816(oacc[2*g+1], pah[kk2], th[2], th[3]);
                MMA16816(oacc[2*g+1], pah[kk2], tl[2], tl[3]);
                MMA16816(oacc[2*g+1], pal[kk2], th[2], th[3]);
            }
        }
    }

#pragma unroll
    for (int nt = 0; nt < 8; nt++) {
        int d = nt*8 + t2;
        float v00 = oacc[nt][0], v01 = oacc[nt][1];
        float v10 = oacc[nt][2], v11 = oacc[nt][3];
        size_t i0 = (size_t)(b*SS + qrow) * HDIM + h*64 + d;
        size_t i1 = (size_t)(b*SS + qrow + 8) * HDIM + h*64 + d;
        __half h00 = __float2half_rn(v00), h01 = __float2half_rn(v01);
        __half h10 = __float2half_rn(v10), h11 = __float2half_rn(v11);
        __half2 hp0 = {h00, h01}, hp1 = {h10, h11};
        __half2 lp0 = {__float2half_rn(v00 - __half2float(h00)),
                       __float2half_rn(v01 - __half2float(h01))};
        __half2 lp1 = {__float2half_rn(v10 - __half2float(h10)),
                       __float2half_rn(v11 - __half2float(h11))};
        *(__half2*)&g_aoh[i0] = hp0;  *(__half2*)&g_aol[i0] = lp0;
        *(__half2*)&g_aoh[i1] = hp1;  *(__half2*)&g_aol[i1] = lp1;
    }
}

// ------------------- launch ------------------------------------------------------
extern "C" void kernel_launch(void* const* d_in, const int* in_sizes, int n_in,
                              void* d_out, int out_size)
{
    const float* queries = (const float*)d_in[0];
    const float* keys    = (const float*)d_in[1];
    const float* values  = (const float*)d_in[2];
    const float* Wq_w = (const float*)d_in[3];  const float* Wq_b = (const float*)d_in[4];
    const float* Wk_w = (const float*)d_in[5];  const float* Wk_b = (const float*)d_in[6];
    const float* Wv_w = (const float*)d_in[7];  const float* Wv_b = (const float*)d_in[8];
    const float* Aq_w = (const float*)d_in[9];  const float* Aq_b = (const float*)d_in[10];
    const float* Bq_w = (const float*)d_in[11]; const float* Bq_b = (const float*)d_in[12];
    const float* Ak_w = (const float*)d_in[13]; const float* Ak_b = (const float*)d_in[14];
    const float* Bk_w = (const float*)d_in[15]; const float* Bk_b = (const float*)d_in[16];
    const float* Av_w = (const float*)d_in[17]; const float* Av_b = (const float*)d_in[18];
    const float* Bv_w = (const float*)d_in[19]; const float* Bv_b = (const float*)d_in[20];
    const float* Wo_w = (const float*)d_in[21]; const float* Wo_b = (const float*)d_in[22];
    float* out = (float*)d_out;

    cudaFuncSetAttribute(gemm_mma, cudaFuncAttributeMaxDynamicSharedMemorySize, GEMM_SMEM);
    cudaFuncSetAttribute(attn1_mma, cudaFuncAttributeMaxDynamicSharedMemorySize, A1_SMEM);
    cudaFuncSetAttribute(attn2_mma, cudaFuncAttributeMaxDynamicSharedMemorySize, F2_SMEM);

    void *pbeq, *pbek, *pbev, *pV, *pcs, *pKA;
    void *pqh, *pql, *pkh, *pkl, *pvh, *pvl, *paoh, *paol;
    void *pQph, *pQpl, *pKph, *pKpl;
    void *pwqh, *pwql, *pwkh, *pwkl, *pwvh, *pwvl, *pwoh, *pwol;
    cudaGetSymbolAddress(&pbeq, g_beq); cudaGetSymbolAddress(&pbek, g_bek);
    cudaGetSymbolAddress(&pbev, g_bev); cudaGetSymbolAddress(&pV, g_V);
    cudaGetSymbolAddress(&pcs, g_colsum); cudaGetSymbolAddress(&pKA, g_KA);
    cudaGetSymbolAddress(&pqh, g_qh); cudaGetSymbolAddress(&pql, g_ql);
    cudaGetSymbolAddress(&pkh, g_kh); cudaGetSymbolAddress(&pkl, g_kl);
    cudaGetSymbolAddress(&pvh, g_vh); cudaGetSymbolAddress(&pvl, g_vl);
    cudaGetSymbolAddress(&paoh, g_aoh); cudaGetSymbolAddress(&paol, g_aol);
    cudaGetSymbolAddress(&pQph, g_Qph); cudaGetSymbolAddress(&pQpl, g_Qpl);
    cudaGetSymbolAddress(&pKph, g_Kph); cudaGetSymbolAddress(&pKpl, g_Kpl);
    cudaGetSymbolAddress(&pwqh, g_wqh); cudaGetSymbolAddress(&pwql, g_wql);
    cudaGetSymbolAddress(&pwkh, g_wkh); cudaGetSymbolAddress(&pwkl, g_wkl);
    cudaGetSymbolAddress(&pwvh, g_wvh); cudaGetSymbolAddress(&pwvl, g_wvl);
    cudaGetSymbolAddress(&pwoh, g_woh); cudaGetSymbolAddress(&pwol, g_wol);

    ActArgs aa;
    aa.X[0] = queries; aa.X[1] = keys; aa.X[2] = values;
    aa.hi[0] = (__nv_bfloat16*)pqh; aa.hi[1] = (__nv_bfloat16*)pkh; aa.hi[2] = (__nv_bfloat16*)pvh;
    aa.lo[0] = (__nv_bfloat16*)pql; aa.lo[1] = (__nv_bfloat16*)pkl; aa.lo[2] = (__nv_bfloat16*)pvl;

    WprepArgs wa;
    wa.W[0] = Wq_w; wa.W[1] = Wk_w; wa.W[2] = Wv_w; wa.W[3] = Wo_w;
    wa.A[0] = Aq_w; wa.A[1] = Ak_w; wa.A[2] = nullptr; wa.A[3] = nullptr;
    wa.Bw[0] = Bq_w; wa.Bw[1] = Bk_w; wa.Bw[2] = nullptr; wa.Bw[3] = nullptr;
    wa.hi[0] = (__nv_bfloat16*)pwqh; wa.hi[1] = (__nv_bfloat16*)pwkh;
    wa.hi[2] = (__nv_bfloat16*)pwvh; wa.hi[3] = (__nv_bfloat16*)pwoh;
    wa.lo[0] = (__nv_bfloat16*)pwql; wa.lo[1] = (__nv_bfloat16*)pwkl;
    wa.lo[2] = (__nv_bfloat16*)pwvl; wa.lo[3] = (__nv_bfloat16*)pwol;

    BeffArgs ba;
    ba.Wb[0] = Wq_b; ba.Wb[1] = Wk_b; ba.Wb[2] = Wv_b;
    ba.Ab[0] = Aq_b; ba.Ab[1] = Ak_b; ba.Ab[2] = Av_b;
    ba.Bw[0] = Bq_w; ba.Bw[1] = Bk_w; ba.Bw[2] = Bv_w;
    ba.Bb[0] = Bq_b; ba.Bb[1] = Bk_b; ba.Bb[2] = Bv_b;
    ba.out[0] = (float*)pbeq; ba.out[1] = (float*)pbek; ba.out[2] = (float*)pbev;

    GemmArgs ga;
    ga.Ah[0] = (const __nv_bfloat16*)pqh;  ga.Al[0] = (const __nv_bfloat16*)pql;
    ga.Ah[1] = (const __nv_bfloat16*)pkh;  ga.Al[1] = (const __nv_bfloat16*)pkl;
    ga.Ah[2] = (const __nv_bfloat16*)pvh;  ga.Al[2] = (const __nv_bfloat16*)pvl;
    ga.Ah[3] = (const __nv_bfloat16*)paoh; ga.Al[3] = (const __nv_bfloat16*)paol;
    ga.Bh[0] = (const __nv_bfloat16*)pwqh; ga.Bl[0] = (const __nv_bfloat16*)pwql;
    ga.Bh[1] = (const __nv_bfloat16*)pwkh; ga.Bl[1] = (const __nv_bfloat16*)pwkl;
    ga.Bh[2] = (const __nv_bfloat16*)pwvh; ga.Bl[2] = (const __nv_bfloat16*)pwvl;
    ga.Bh[3] = (const __nv_bfloat16*)pwoh; ga.Bl[3] = (const __nv_bfloat16*)pwol;
    ga.bias[0] = (const float*)pbeq; ga.bias[1] = (const float*)pbek;
    ga.bias[2] = (const float*)pbev; ga.bias[3] = Wo_b;
    ga.outF[0] = nullptr; ga.outF[1] = nullptr; ga.outF[2] = (float*)pV; ga.outF[3] = out;
    ga.outH[0] = (__nv_bfloat16*)pQph; ga.outL[0] = (__nv_bfloat16*)pQpl;
    ga.outH[1] = (__nv_bfloat16*)pKph; ga.outL[1] = (__nv_bfloat16*)pKpl;
    ga.outH[2] = nullptr; ga.outL[2] = nullptr;
    ga.outH[3] = nullptr; ga.outL[3] = nullptr;
    ga.loraKA = (const float*)pKA; ga.loraB = Bv_w;

    actconv_kernel<<<dim3((TOK*DMODEL/4)/256, 1, 3), 256>>>(aa);          // 0
    wprep_kernel<<<dim3(DMODEL/32, HDIM/32, 4), 256>>>(wa);               // 1
    beff_kernel<<<dim3(HDIM/256, 1, 3), 256>>>(ba);                       // 2
    ka_kernel<<<TOK/8, 256>>>(keys, Av_w, (float*)pKA, (float*)pcs);      // 3 (zeros colsum)
    gemm_mma<<<dim3(HDIM/128, TOK/128, 3), 256, GEMM_SMEM>>>(ga, 0);      // 4: QKV fused
    attn1_mma<<<dim3(136, BB*NH), 256, A1_SMEM>>>();                      // 5
    vrt_kernel<<<dim3(SS/32, 2, BB*NH), 256>>>();                         // 6
    attn2_mma<<<dim3(16, BB*NH), 256, F2_SMEM>>>();                       // 7
    gemm_mma<<<dim3(HDIM/128, TOK/128, 1), 256, GEMM_SMEM>>>(ga, 3);      // 8: O
}